// round 1
// baseline (speedup 1.0000x reference)
#include <cuda_runtime.h>
#include <math.h>

// Problem constants (fixed by reference)
constexpr int CB  = 32;    // batch
constexpr int CN  = 512;   // regions
constexpr int CD  = 1024;  // hidden
constexpr int CH  = 8;     // heads
constexpr int CHD = 128;   // head dim
constexpr int C3D = 3 * CD;
constexpr int CM  = CB * CN;  // 16384 rows for the big GEMMs

// ---------------- scratch (device globals; no allocation at runtime) ---------
__device__ float g_vtran[(size_t)CB * CN * C3D];   // 192 MiB
__device__ float g_qtran[(size_t)CB * CN * C3D];   // 192 MiB
__device__ float g_s1[(size_t)CB * CH * CN * CN];  // 256 MiB  (q2v scores)
__device__ float g_s2[(size_t)CB * CH * CN * CN];  // 256 MiB  (v2q scores)
__device__ float g_vupd[(size_t)CB * CN * CD];     // 64 MiB
__device__ float g_qupd[(size_t)CB * CN * CD];     // 64 MiB

// =============================================================================
// Kernel 1/5: C = relu(A @ B + bias)
// A: M x K row-major, possibly split column-wise into A0 (cols [0,K0)) and
// A1 (cols [K0,K)) — used to virtualize concat([x, x_update]).
// B: K x N row-major. 128x128 block tile, 8x8 per thread, BK=8, 256 threads.
// All dims assumed multiples of tile sizes (true here).
// =============================================================================
__global__ __launch_bounds__(256)
void sgemm_bias_relu(const float* __restrict__ A0, const float* __restrict__ A1,
                     int K0, const float* __restrict__ B,
                     const float* __restrict__ bias, float* __restrict__ C,
                     int M, int N, int K)
{
    constexpr int BM = 128, BN = 128, BK = 8, TM = 8, TN = 8;
    __shared__ float As[BK][BM];
    __shared__ float Bs[BK][BN];

    const int tid = threadIdx.x;
    const int block_row = blockIdx.y * BM;
    const int block_col = blockIdx.x * BN;

    const int tr = (tid / 16) * TM;   // 0..120
    const int tc = (tid % 16) * TN;   // 0..120

    // A tile loader: 128 rows x 8 cols -> one float4 per thread
    const int a_row = tid / 2;
    const int a_col = (tid % 2) * 4;
    // B tile loader: 8 rows x 128 cols -> one float4 per thread
    const int b_row = tid / 32;
    const int b_col = (tid % 32) * 4;

    const int K1len = K - K0;

    float acc[TM][TN];
    #pragma unroll
    for (int i = 0; i < TM; i++)
        #pragma unroll
        for (int j = 0; j < TN; j++) acc[i][j] = 0.f;

    for (int k0 = 0; k0 < K; k0 += BK) {
        // ---- load A (two-part aware; K0 % 4 == 0 so no straddle) ----
        const int gk = k0 + a_col;
        const int grow = block_row + a_row;
        float4 av;
        if (gk < K0) {
            av = *reinterpret_cast<const float4*>(&A0[(size_t)grow * K0 + gk]);
        } else {
            av = *reinterpret_cast<const float4*>(&A1[(size_t)grow * K1len + (gk - K0)]);
        }
        As[a_col + 0][a_row] = av.x;
        As[a_col + 1][a_row] = av.y;
        As[a_col + 2][a_row] = av.z;
        As[a_col + 3][a_row] = av.w;

        // ---- load B ----
        const float4 bv4 = *reinterpret_cast<const float4*>(
            &B[(size_t)(k0 + b_row) * N + block_col + b_col]);
        *reinterpret_cast<float4*>(&Bs[b_row][b_col]) = bv4;

        __syncthreads();

        #pragma unroll
        for (int k = 0; k < BK; ++k) {
            float a[TM], b[TN];
            #pragma unroll
            for (int i = 0; i < TM; i++) a[i] = As[k][tr + i];
            #pragma unroll
            for (int j = 0; j < TN; j++) b[j] = Bs[k][tc + j];
            #pragma unroll
            for (int i = 0; i < TM; i++)
                #pragma unroll
                for (int j = 0; j < TN; j++)
                    acc[i][j] = fmaf(a[i], b[j], acc[i][j]);
        }
        __syncthreads();
    }

    #pragma unroll
    for (int i = 0; i < TM; i++) {
        const size_t row = (size_t)(block_row + tr + i);
        #pragma unroll
        for (int j = 0; j < TN; j += 4) {
            float4 o;
            o.x = fmaxf(acc[i][j + 0] + bias[block_col + tc + j + 0], 0.f);
            o.y = fmaxf(acc[i][j + 1] + bias[block_col + tc + j + 1], 0.f);
            o.z = fmaxf(acc[i][j + 2] + bias[block_col + tc + j + 2], 0.f);
            o.w = fmaxf(acc[i][j + 3] + bias[block_col + tc + j + 3], 0.f);
            *reinterpret_cast<float4*>(&C[row * N + block_col + tc + j]) = o;
        }
    }
}

// =============================================================================
// Kernel 2/5: attention scores (batched NT GEMM)
// S[bz, n, m] = scale * sum_d Xa[b, n, offA + h*HD + d] * Xb[b, m, offB + h*HD + d]
// bz = b*H + h. 64x64 tile, 4x4 per thread, BK=16, 256 threads.
// =============================================================================
__global__ __launch_bounds__(256)
void attn_scores(const float* __restrict__ Xa, int offA,
                 const float* __restrict__ Xb, int offB,
                 float* __restrict__ S, float scale)
{
    constexpr int BT = 64, BKk = 16;
    __shared__ float As[BKk][BT];
    __shared__ float Bs[BKk][BT];

    const int tid = threadIdx.x;
    const int bz = blockIdx.z;
    const int b = bz / CH, h = bz % CH;
    const float* Abase = Xa + (size_t)b * CN * C3D + offA + h * CHD;
    const float* Bbase = Xb + (size_t)b * CN * C3D + offB + h * CHD;
    const int n0 = blockIdx.y * BT;
    const int m0 = blockIdx.x * BT;

    const int lr = tid / 4;          // 0..63 (row within tile)
    const int lk = (tid % 4) * 4;    // 0,4,8,12 (k within BK)

    const int tr = (tid / 16) * 4;
    const int tc = (tid % 16) * 4;

    float acc[4][4];
    #pragma unroll
    for (int i = 0; i < 4; i++)
        #pragma unroll
        for (int j = 0; j < 4; j++) acc[i][j] = 0.f;

    for (int k0 = 0; k0 < CHD; k0 += BKk) {
        const float4 a4 = *reinterpret_cast<const float4*>(
            &Abase[(size_t)(n0 + lr) * C3D + k0 + lk]);
        const float4 b4 = *reinterpret_cast<const float4*>(
            &Bbase[(size_t)(m0 + lr) * C3D + k0 + lk]);
        As[lk + 0][lr] = a4.x; As[lk + 1][lr] = a4.y;
        As[lk + 2][lr] = a4.z; As[lk + 3][lr] = a4.w;
        Bs[lk + 0][lr] = b4.x; Bs[lk + 1][lr] = b4.y;
        Bs[lk + 2][lr] = b4.z; Bs[lk + 3][lr] = b4.w;
        __syncthreads();

        #pragma unroll
        for (int k = 0; k < BKk; ++k) {
            float a[4], bb[4];
            #pragma unroll
            for (int i = 0; i < 4; i++) a[i] = As[k][tr + i];
            #pragma unroll
            for (int j = 0; j < 4; j++) bb[j] = Bs[k][tc + j];
            #pragma unroll
            for (int i = 0; i < 4; i++)
                #pragma unroll
                for (int j = 0; j < 4; j++)
                    acc[i][j] = fmaf(a[i], bb[j], acc[i][j]);
        }
        __syncthreads();
    }

    float* Sb = S + (size_t)bz * CN * CN;
    #pragma unroll
    for (int i = 0; i < 4; i++) {
        float4 o;
        o.x = acc[i][0] * scale; o.y = acc[i][1] * scale;
        o.z = acc[i][2] * scale; o.w = acc[i][3] * scale;
        *reinterpret_cast<float4*>(&Sb[(size_t)(n0 + tr + i) * CN + m0 + tc]) = o;
    }
}

// =============================================================================
// Kernel 3/5: row softmax over 512 columns, in place. 1 block/row, 256 threads.
// =============================================================================
__global__ __launch_bounds__(256)
void softmax_rows(float* __restrict__ S)
{
    float* p = S + (size_t)blockIdx.x * CN;
    const int t = threadIdx.x;
    const float v0 = p[t], v1 = p[t + 256];

    __shared__ float red[256];
    red[t] = fmaxf(v0, v1);
    __syncthreads();
    #pragma unroll
    for (int s = 128; s > 0; s >>= 1) {
        if (t < s) red[t] = fmaxf(red[t], red[t + s]);
        __syncthreads();
    }
    const float mx = red[0];
    __syncthreads();

    const float e0 = __expf(v0 - mx), e1 = __expf(v1 - mx);
    red[t] = e0 + e1;
    __syncthreads();
    #pragma unroll
    for (int s = 128; s > 0; s >>= 1) {
        if (t < s) red[t] += red[t + s];
        __syncthreads();
    }
    const float inv = 1.f / red[0];
    p[t] = e0 * inv;
    p[t + 256] = e1 * inv;
}

// =============================================================================
// Kernel 4/5: U[b, n, h*HD + d] = sum_m S[bz, n, m] * Xv[b, m, offV + h*HD + d]
// batched NN GEMM, 64x64 tile, 4x4 per thread, BK=16.
// grid: x = d-tile (HD/64 = 2), y = n-tile (8), z = b*H + h
// =============================================================================
__global__ __launch_bounds__(256)
void attn_av(const float* __restrict__ S,
             const float* __restrict__ Xv, int offV,
             float* __restrict__ U)
{
    constexpr int BT = 64, BKk = 16;
    __shared__ float As[BKk][BT];   // scores, transposed: As[k][n]
    __shared__ float Vs[BKk][BT];   // values: Vs[k][d]

    const int tid = threadIdx.x;
    const int bz = blockIdx.z;
    const int b = bz / CH, h = bz % CH;
    const float* Sb = S + (size_t)bz * CN * CN;
    const float* Vb = Xv + (size_t)b * CN * C3D + offV + h * CHD;
    const int n0 = blockIdx.y * BT;
    const int d0 = blockIdx.x * BT;

    const int lr = tid / 4;          // S: row within n-tile
    const int lk = (tid % 4) * 4;    // S: k within BK
    const int vr = tid / 16;         // V: k row (0..15)
    const int vc = (tid % 16) * 4;   // V: d col

    const int tr = (tid / 16) * 4;
    const int tc = (tid % 16) * 4;

    float acc[4][4];
    #pragma unroll
    for (int i = 0; i < 4; i++)
        #pragma unroll
        for (int j = 0; j < 4; j++) acc[i][j] = 0.f;

    for (int k0 = 0; k0 < CN; k0 += BKk) {
        const float4 a4 = *reinterpret_cast<const float4*>(
            &Sb[(size_t)(n0 + lr) * CN + k0 + lk]);
        As[lk + 0][lr] = a4.x; As[lk + 1][lr] = a4.y;
        As[lk + 2][lr] = a4.z; As[lk + 3][lr] = a4.w;

        const float4 v4 = *reinterpret_cast<const float4*>(
            &Vb[(size_t)(k0 + vr) * C3D + d0 + vc]);
        *reinterpret_cast<float4*>(&Vs[vr][vc]) = v4;
        __syncthreads();

        #pragma unroll
        for (int k = 0; k < BKk; ++k) {
            float a[4], vv[4];
            #pragma unroll
            for (int i = 0; i < 4; i++) a[i] = As[k][tr + i];
            #pragma unroll
            for (int j = 0; j < 4; j++) vv[j] = Vs[k][tc + j];
            #pragma unroll
            for (int i = 0; i < 4; i++)
                #pragma unroll
                for (int j = 0; j < 4; j++)
                    acc[i][j] = fmaf(a[i], vv[j], acc[i][j]);
        }
        __syncthreads();
    }

    #pragma unroll
    for (int i = 0; i < 4; i++) {
        float4 o;
        o.x = acc[i][0]; o.y = acc[i][1]; o.z = acc[i][2]; o.w = acc[i][3];
        *reinterpret_cast<float4*>(
            &U[((size_t)b * CN + n0 + tr + i) * CD + h * CHD + d0 + tc]) = o;
    }
}

// =============================================================================
// launch
// =============================================================================
extern "C" void kernel_launch(void* const* d_in, const int* in_sizes, int n_in,
                              void* d_out, int out_size)
{
    const float* v   = (const float*)d_in[0];
    const float* q   = (const float*)d_in[1];
    const float* Wv  = (const float*)d_in[2];
    const float* bv  = (const float*)d_in[3];
    const float* Wq  = (const float*)d_in[4];
    const float* bq  = (const float*)d_in[5];
    const float* Wvo = (const float*)d_in[6];
    const float* bvo = (const float*)d_in[7];
    const float* Wqo = (const float*)d_in[8];
    const float* bqo = (const float*)d_in[9];
    float* out = (float*)d_out;

    float *vtran, *qtran, *s1, *s2, *vupd, *qupd;
    cudaGetSymbolAddress((void**)&vtran, g_vtran);
    cudaGetSymbolAddress((void**)&qtran, g_qtran);
    cudaGetSymbolAddress((void**)&s1, g_s1);
    cudaGetSymbolAddress((void**)&s2, g_s2);
    cudaGetSymbolAddress((void**)&vupd, g_vupd);
    cudaGetSymbolAddress((void**)&qupd, g_qupd);

    const dim3 t256(256);
    const float scale = 0.08838834764831845f;  // 1/sqrt(128)

    // 1) input transforms: T = relu(X @ W + b), [16384,1024]@[1024,3072]
    sgemm_bias_relu<<<dim3(C3D / 128, CM / 128), t256>>>(v, v, CD, Wv, bv, vtran, CM, C3D, CD);
    sgemm_bias_relu<<<dim3(C3D / 128, CM / 128), t256>>>(q, q, CD, Wq, bq, qtran, CM, C3D, CD);

    // 2) scores: q2v = vq . qk^T ; v2q = qq . vk^T   (offsets: key=0, query=D, val=2D)
    attn_scores<<<dim3(8, 8, CB * CH), t256>>>(vtran, CD, qtran, 0, s1, scale);
    attn_scores<<<dim3(8, 8, CB * CH), t256>>>(qtran, CD, vtran, 0, s2, scale);

    // 3) softmax over last dim
    softmax_rows<<<CB * CH * CN, 256>>>(s1);
    softmax_rows<<<CB * CH * CN, 256>>>(s2);

    // 4) updates: v_update = A_q2v @ qv ; q_update = A_v2q @ vv
    attn_av<<<dim3(2, 8, CB * CH), t256>>>(s1, qtran, 2 * CD, vupd);
    attn_av<<<dim3(2, 8, CB * CH), t256>>>(s2, vtran, 2 * CD, qupd);

    // 5) output: relu(concat([x, x_update]) @ Wxo + bxo)
    const size_t half = (size_t)CM * CD;
    sgemm_bias_relu<<<dim3(CD / 128, CM / 128), t256>>>(v, vupd, CD, Wvo, bvo, out, CM, CD, 2 * CD);
    sgemm_bias_relu<<<dim3(CD / 128, CM / 128), t256>>>(q, qupd, CD, Wqo, bqo, out + half, CM, CD, 2 * CD);
}

// round 3
// speedup vs baseline: 1.8374x; 1.8374x over previous
#include <cuda_runtime.h>
#include <cuda_bf16.h>
#include <cstdint>
#include <math.h>

// Problem constants
constexpr int CB  = 32;
constexpr int CN  = 512;
constexpr int CD  = 1024;
constexpr int CH  = 8;
constexpr int CHD = 128;
constexpr int C3D = 3 * CD;
constexpr int CM  = CB * CN;   // 16384

// ---------------- scratch (device globals) ----------------------------------
__device__ float g_vtran[(size_t)CM * C3D];
__device__ float g_qtran[(size_t)CM * C3D];
__device__ float g_s1[(size_t)CB * CH * CN * CN];
__device__ float g_s2[(size_t)CB * CH * CN * CN];
__device__ float g_vupd[(size_t)CM * CD];
__device__ float g_qupd[(size_t)CM * CD];

__device__ __nv_bfloat16 g_vhi[(size_t)CM * CD],  g_vlo[(size_t)CM * CD];
__device__ __nv_bfloat16 g_qhi[(size_t)CM * CD],  g_qlo[(size_t)CM * CD];
__device__ __nv_bfloat16 g_vuhi[(size_t)CM * CD], g_vulo[(size_t)CM * CD];
__device__ __nv_bfloat16 g_quhi[(size_t)CM * CD], g_qulo[(size_t)CM * CD];
__device__ __nv_bfloat16 g_Wvt_hi[(size_t)C3D * CD],     g_Wvt_lo[(size_t)C3D * CD];
__device__ __nv_bfloat16 g_Wqt_hi[(size_t)C3D * CD],     g_Wqt_lo[(size_t)C3D * CD];
__device__ __nv_bfloat16 g_Wvot_hi[(size_t)CD * 2 * CD], g_Wvot_lo[(size_t)CD * 2 * CD];
__device__ __nv_bfloat16 g_Wqot_hi[(size_t)CD * 2 * CD], g_Wqot_lo[(size_t)CD * 2 * CD];

// ---------------- base-ISA PTX helpers (no 'a' features) ---------------------
__device__ __forceinline__ uint32_t smem_u32(const void* p) {
    uint32_t a;
    asm("{ .reg .u64 t; cvta.to.shared.u64 t, %1; cvt.u32.u64 %0, t; }" : "=r"(a) : "l"(p));
    return a;
}
__device__ __forceinline__ void cp_async16(uint32_t dst, const void* src) {
    asm volatile("cp.async.cg.shared.global [%0], [%1], 16;" :: "r"(dst), "l"(src) : "memory");
}
__device__ __forceinline__ void cp_commit() { asm volatile("cp.async.commit_group;" ::: "memory"); }
template <int N>
__device__ __forceinline__ void cp_wait() { asm volatile("cp.async.wait_group %0;" :: "n"(N) : "memory"); }

__device__ __forceinline__ void ldm_x4(uint32_t* r, uint32_t addr) {
    asm volatile("ldmatrix.sync.aligned.m8n8.x4.shared.b16 {%0,%1,%2,%3}, [%4];"
        : "=r"(r[0]), "=r"(r[1]), "=r"(r[2]), "=r"(r[3]) : "r"(addr));
}
__device__ __forceinline__ void ldm_x2(uint32_t* r, uint32_t addr) {
    asm volatile("ldmatrix.sync.aligned.m8n8.x2.shared.b16 {%0,%1}, [%2];"
        : "=r"(r[0]), "=r"(r[1]) : "r"(addr));
}
__device__ __forceinline__ void mma_bf16(float* c, const uint32_t* a, const uint32_t* b) {
    asm volatile("mma.sync.aligned.m16n8k16.row.col.f32.bf16.bf16.f32 "
        "{%0,%1,%2,%3}, {%4,%5,%6,%7}, {%8,%9}, {%0,%1,%2,%3};"
        : "+f"(c[0]), "+f"(c[1]), "+f"(c[2]), "+f"(c[3])
        : "r"(a[0]), "r"(a[1]), "r"(a[2]), "r"(a[3]), "r"(b[0]), "r"(b[1]));
}

// =============================================================================
// split-bf16 warp-MMA GEMM: C = relu(A @ W + bias)
// A: [M,K] as hi/lo bf16, two column-parts (A0: [0,K0), A1: [K0,K)).
// Bt: [N,K] hi/lo bf16 (pre-transposed W). CTA tile 128x128, BK=32,
// 8 warps (4Mx2N, warp tile 32x64), cp.async double buffer.
// SMEM tile stride 40 halves (80B) -> ldmatrix conflict-free.
// =============================================================================
constexpr int TSTR   = 40;                 // halves per smem row
constexpr int TILE_H = 128 * TSTR;         // halves per 128x32 tile
constexpr int STAGE_H = 4 * TILE_H;        // Ahi, Alo, Bhi, Blo
constexpr int MMA_SMEM_BYTES = 2 * STAGE_H * 2;   // 81920

__global__ __launch_bounds__(256)
void mma_gemm_bias_relu(const __nv_bfloat16* __restrict__ A0hi, const __nv_bfloat16* __restrict__ A0lo,
                        const __nv_bfloat16* __restrict__ A1hi, const __nv_bfloat16* __restrict__ A1lo,
                        int K0,
                        const __nv_bfloat16* __restrict__ Bthi, const __nv_bfloat16* __restrict__ Btlo,
                        const float* __restrict__ bias, float* __restrict__ C,
                        int M, int N, int K)
{
    extern __shared__ __nv_bfloat16 sm[];
    const uint32_t smb = smem_u32(sm);
    const int tid  = threadIdx.x;
    const int wid  = tid >> 5;
    const int lane = tid & 31;
    const int bm0 = blockIdx.y * 128;
    const int bn0 = blockIdx.x * 128;
    const int nk  = K / 32;
    const int K1  = K - K0;

    const int mw = (wid & 3) * 32;    // warp M offset in tile
    const int nw = (wid >> 2) * 64;   // warp N offset in tile

    // ---- async tile copy: global [128 x 32] -> smem (stride TSTR) ----
    auto load_stage = [&](int kc, int buf) {
        const int kk = kc * 32;
        const __nv_bfloat16 *ah, *al;
        int ldA, ka;
        if (kk < K0) { ah = A0hi; al = A0lo; ldA = K0; ka = kk; }
        else         { ah = A1hi; al = A1lo; ldA = K1; ka = kk - K0; }
        ah += (size_t)bm0 * ldA + ka;
        al += (size_t)bm0 * ldA + ka;
        const __nv_bfloat16* bh = Bthi + (size_t)bn0 * K + kk;
        const __nv_bfloat16* bl = Btlo + (size_t)bn0 * K + kk;
        const uint32_t base = smb + (uint32_t)buf * STAGE_H * 2;

        #pragma unroll
        for (int i = 0; i < 2; ++i) {
            const int idx = tid + i * 256;    // 0..511
            const int r = idx >> 2;
            const int c = (idx & 3) * 8;      // halves
            const uint32_t doff = (uint32_t)(r * TSTR + c) * 2;
            cp_async16(base + 0 * TILE_H * 2 + doff, ah + (size_t)r * ldA + c);
            cp_async16(base + 1 * TILE_H * 2 + doff, al + (size_t)r * ldA + c);
            cp_async16(base + 2 * TILE_H * 2 + doff, bh + (size_t)r * K + c);
            cp_async16(base + 3 * TILE_H * 2 + doff, bl + (size_t)r * K + c);
        }
        cp_commit();
    };

    float acc[2][8][4];
    #pragma unroll
    for (int mi = 0; mi < 2; ++mi)
        #pragma unroll
        for (int ni = 0; ni < 8; ++ni)
            #pragma unroll
            for (int r = 0; r < 4; ++r) acc[mi][ni][r] = 0.f;

    // ldmatrix address components
    const int arow = lane & 15;              // A: row within 16
    const int acol = (lane >> 4) * 8;        // A: col half-block
    const int brow = lane & 7;               // B: row within 8
    const int bcol = ((lane >> 3) & 1) * 8;  // B: col half-block

    load_stage(0, 0);

    for (int kc = 0; kc < nk; ++kc) {
        const int buf = kc & 1;
        if (kc + 1 < nk) { load_stage(kc + 1, buf ^ 1); cp_wait<1>(); }
        else             { cp_wait<0>(); }
        __syncthreads();

        const uint32_t base = smb + (uint32_t)buf * STAGE_H * 2;
        #pragma unroll
        for (int ks = 0; ks < 2; ++ks) {
            const int k0 = ks * 16;
            uint32_t ah[2][4], al[2][4];
            #pragma unroll
            for (int mi = 0; mi < 2; ++mi) {
                const uint32_t aoff = (uint32_t)((mw + mi * 16 + arow) * TSTR + k0 + acol) * 2;
                ldm_x4(ah[mi], base + 0 * TILE_H * 2 + aoff);
                ldm_x4(al[mi], base + 1 * TILE_H * 2 + aoff);
            }
            #pragma unroll
            for (int ni = 0; ni < 8; ++ni) {
                const uint32_t boff = (uint32_t)((nw + ni * 8 + brow) * TSTR + k0 + bcol) * 2;
                uint32_t bh[2], bl[2];
                ldm_x2(bh, base + 2 * TILE_H * 2 + boff);
                ldm_x2(bl, base + 3 * TILE_H * 2 + boff);
                #pragma unroll
                for (int mi = 0; mi < 2; ++mi) {
                    mma_bf16(acc[mi][ni], ah[mi], bh);
                    mma_bf16(acc[mi][ni], ah[mi], bl);
                    mma_bf16(acc[mi][ni], al[mi], bh);
                }
            }
        }
        __syncthreads();
    }

    // ---- epilogue: bias + relu, direct global stores ----
    const int g  = lane >> 2;
    const int tq = lane & 3;
    #pragma unroll
    for (int mi = 0; mi < 2; ++mi) {
        const int row0 = bm0 + mw + mi * 16 + g;
        #pragma unroll
        for (int ni = 0; ni < 8; ++ni) {
            const int col = bn0 + nw + ni * 8 + tq * 2;
            const float b0 = __ldg(&bias[col]), b1 = __ldg(&bias[col + 1]);
            float2 o0, o1;
            o0.x = fmaxf(acc[mi][ni][0] + b0, 0.f);
            o0.y = fmaxf(acc[mi][ni][1] + b1, 0.f);
            o1.x = fmaxf(acc[mi][ni][2] + b0, 0.f);
            o1.y = fmaxf(acc[mi][ni][3] + b1, 0.f);
            *reinterpret_cast<float2*>(&C[(size_t)row0 * N + col]) = o0;
            *reinterpret_cast<float2*>(&C[(size_t)(row0 + 8) * N + col]) = o1;
        }
    }
}

// =============================================================================
// fp32 -> (hi, lo) bf16 split
// =============================================================================
__global__ __launch_bounds__(256)
void split_bf16(const float* __restrict__ x, __nv_bfloat16* __restrict__ hi,
                __nv_bfloat16* __restrict__ lo, size_t n)
{
    const size_t stride = (size_t)gridDim.x * blockDim.x * 4;
    for (size_t i = ((size_t)blockIdx.x * blockDim.x + threadIdx.x) * 4; i < n; i += stride) {
        float4 v = *reinterpret_cast<const float4*>(x + i);
        __nv_bfloat16 h0 = __float2bfloat16(v.x), h1 = __float2bfloat16(v.y);
        __nv_bfloat16 h2 = __float2bfloat16(v.z), h3 = __float2bfloat16(v.w);
        __nv_bfloat16 l0 = __float2bfloat16(v.x - __bfloat162float(h0));
        __nv_bfloat16 l1 = __float2bfloat16(v.y - __bfloat162float(h1));
        __nv_bfloat16 l2 = __float2bfloat16(v.z - __bfloat162float(h2));
        __nv_bfloat16 l3 = __float2bfloat16(v.w - __bfloat162float(h3));
        *reinterpret_cast<__nv_bfloat162*>(hi + i)     = __nv_bfloat162(h0, h1);
        *reinterpret_cast<__nv_bfloat162*>(hi + i + 2) = __nv_bfloat162(h2, h3);
        *reinterpret_cast<__nv_bfloat162*>(lo + i)     = __nv_bfloat162(l0, l1);
        *reinterpret_cast<__nv_bfloat162*>(lo + i + 2) = __nv_bfloat162(l2, l3);
    }
}

// =============================================================================
// W [K,N] fp32 -> Wt [N,K] bf16 hi/lo
// =============================================================================
__global__ __launch_bounds__(256)
void transpose_split(const float* __restrict__ W, __nv_bfloat16* __restrict__ thi,
                     __nv_bfloat16* __restrict__ tlo, int K, int N)
{
    __shared__ float t[32][33];
    const int k0 = blockIdx.y * 32, n0 = blockIdx.x * 32;
    const int tx = threadIdx.x, ty = threadIdx.y;
    for (int i = ty; i < 32; i += 8)
        t[i][tx] = W[(size_t)(k0 + i) * N + n0 + tx];
    __syncthreads();
    for (int i = ty; i < 32; i += 8) {
        const float x = t[tx][i];
        const __nv_bfloat16 h = __float2bfloat16(x);
        thi[(size_t)(n0 + i) * K + k0 + tx] = h;
        tlo[(size_t)(n0 + i) * K + k0 + tx] = __float2bfloat16(x - __bfloat162float(h));
    }
}

// =============================================================================
// attention scores (batched NT GEMM, scalar fp32)
// =============================================================================
__global__ __launch_bounds__(256)
void attn_scores(const float* __restrict__ Xa, int offA,
                 const float* __restrict__ Xb, int offB,
                 float* __restrict__ S, float scale)
{
    constexpr int BT = 64, BKk = 16;
    __shared__ float As[BKk][BT];
    __shared__ float Bs[BKk][BT];

    const int tid = threadIdx.x;
    const int bz = blockIdx.z;
    const int b = bz / CH, h = bz % CH;
    const float* Abase = Xa + (size_t)b * CN * C3D + offA + h * CHD;
    const float* Bbase = Xb + (size_t)b * CN * C3D + offB + h * CHD;
    const int n0 = blockIdx.y * BT;
    const int m0 = blockIdx.x * BT;

    const int lr = tid / 4;
    const int lk = (tid % 4) * 4;
    const int tr = (tid / 16) * 4;
    const int tc = (tid % 16) * 4;

    float acc[4][4];
    #pragma unroll
    for (int i = 0; i < 4; i++)
        #pragma unroll
        for (int j = 0; j < 4; j++) acc[i][j] = 0.f;

    for (int k0 = 0; k0 < CHD; k0 += BKk) {
        const float4 a4 = *reinterpret_cast<const float4*>(&Abase[(size_t)(n0 + lr) * C3D + k0 + lk]);
        const float4 b4 = *reinterpret_cast<const float4*>(&Bbase[(size_t)(m0 + lr) * C3D + k0 + lk]);
        As[lk + 0][lr] = a4.x; As[lk + 1][lr] = a4.y;
        As[lk + 2][lr] = a4.z; As[lk + 3][lr] = a4.w;
        Bs[lk + 0][lr] = b4.x; Bs[lk + 1][lr] = b4.y;
        Bs[lk + 2][lr] = b4.z; Bs[lk + 3][lr] = b4.w;
        __syncthreads();
        #pragma unroll
        for (int k = 0; k < BKk; ++k) {
            float a[4], bb[4];
            #pragma unroll
            for (int i = 0; i < 4; i++) a[i] = As[k][tr + i];
            #pragma unroll
            for (int j = 0; j < 4; j++) bb[j] = Bs[k][tc + j];
            #pragma unroll
            for (int i = 0; i < 4; i++)
                #pragma unroll
                for (int j = 0; j < 4; j++)
                    acc[i][j] = fmaf(a[i], bb[j], acc[i][j]);
        }
        __syncthreads();
    }

    float* Sb = S + (size_t)bz * CN * CN;
    #pragma unroll
    for (int i = 0; i < 4; i++) {
        float4 o;
        o.x = acc[i][0] * scale; o.y = acc[i][1] * scale;
        o.z = acc[i][2] * scale; o.w = acc[i][3] * scale;
        *reinterpret_cast<float4*>(&Sb[(size_t)(n0 + tr + i) * CN + m0 + tc]) = o;
    }
}

// =============================================================================
// row softmax (512 cols, in place)
// =============================================================================
__global__ __launch_bounds__(256)
void softmax_rows(float* __restrict__ S)
{
    float* p = S + (size_t)blockIdx.x * CN;
    const int t = threadIdx.x;
    const float v0 = p[t], v1 = p[t + 256];

    __shared__ float red[256];
    red[t] = fmaxf(v0, v1);
    __syncthreads();
    #pragma unroll
    for (int s = 128; s > 0; s >>= 1) {
        if (t < s) red[t] = fmaxf(red[t], red[t + s]);
        __syncthreads();
    }
    const float mx = red[0];
    __syncthreads();

    const float e0 = __expf(v0 - mx), e1 = __expf(v1 - mx);
    red[t] = e0 + e1;
    __syncthreads();
    #pragma unroll
    for (int s = 128; s > 0; s >>= 1) {
        if (t < s) red[t] += red[t + s];
        __syncthreads();
    }
    const float inv = 1.f / red[0];
    p[t] = e0 * inv;
    p[t + 256] = e1 * inv;
}

// =============================================================================
// attn AV (batched NN GEMM, scalar fp32)
// =============================================================================
__global__ __launch_bounds__(256)
void attn_av(const float* __restrict__ S,
             const float* __restrict__ Xv, int offV,
             float* __restrict__ U)
{
    constexpr int BT = 64, BKk = 16;
    __shared__ float As[BKk][BT];
    __shared__ float Vs[BKk][BT];

    const int tid = threadIdx.x;
    const int bz = blockIdx.z;
    const int b = bz / CH, h = bz % CH;
    const float* Sb = S + (size_t)bz * CN * CN;
    const float* Vb = Xv + (size_t)b * CN * C3D + offV + h * CHD;
    const int n0 = blockIdx.y * BT;
    const int d0 = blockIdx.x * BT;

    const int lr = tid / 4;
    const int lk = (tid % 4) * 4;
    const int vr = tid / 16;
    const int vc = (tid % 16) * 4;
    const int tr = (tid / 16) * 4;
    const int tc = (tid % 16) * 4;

    float acc[4][4];
    #pragma unroll
    for (int i = 0; i < 4; i++)
        #pragma unroll
        for (int j = 0; j < 4; j++) acc[i][j] = 0.f;

    for (int k0 = 0; k0 < CN; k0 += BKk) {
        const float4 a4 = *reinterpret_cast<const float4*>(&Sb[(size_t)(n0 + lr) * CN + k0 + lk]);
        As[lk + 0][lr] = a4.x; As[lk + 1][lr] = a4.y;
        As[lk + 2][lr] = a4.z; As[lk + 3][lr] = a4.w;
        const float4 v4 = *reinterpret_cast<const float4*>(&Vb[(size_t)(k0 + vr) * C3D + d0 + vc]);
        *reinterpret_cast<float4*>(&Vs[vr][vc]) = v4;
        __syncthreads();
        #pragma unroll
        for (int k = 0; k < BKk; ++k) {
            float a[4], vv[4];
            #pragma unroll
            for (int i = 0; i < 4; i++) a[i] = As[k][tr + i];
            #pragma unroll
            for (int j = 0; j < 4; j++) vv[j] = Vs[k][tc + j];
            #pragma unroll
            for (int i = 0; i < 4; i++)
                #pragma unroll
                for (int j = 0; j < 4; j++)
                    acc[i][j] = fmaf(a[i], vv[j], acc[i][j]);
        }
        __syncthreads();
    }

    #pragma unroll
    for (int i = 0; i < 4; i++) {
        float4 o;
        o.x = acc[i][0]; o.y = acc[i][1]; o.z = acc[i][2]; o.w = acc[i][3];
        *reinterpret_cast<float4*>(&U[((size_t)b * CN + n0 + tr + i) * CD + h * CHD + d0 + tc]) = o;
    }
}

// =============================================================================
// launch
// =============================================================================
extern "C" void kernel_launch(void* const* d_in, const int* in_sizes, int n_in,
                              void* d_out, int out_size)
{
    const float* v   = (const float*)d_in[0];
    const float* q   = (const float*)d_in[1];
    const float* Wv  = (const float*)d_in[2];
    const float* bv  = (const float*)d_in[3];
    const float* Wq  = (const float*)d_in[4];
    const float* bq  = (const float*)d_in[5];
    const float* Wvo = (const float*)d_in[6];
    const float* bvo = (const float*)d_in[7];
    const float* Wqo = (const float*)d_in[8];
    const float* bqo = (const float*)d_in[9];
    float* out = (float*)d_out;

    float *vtran, *qtran, *s1, *s2, *vupd, *qupd;
    cudaGetSymbolAddress((void**)&vtran, g_vtran);
    cudaGetSymbolAddress((void**)&qtran, g_qtran);
    cudaGetSymbolAddress((void**)&s1, g_s1);
    cudaGetSymbolAddress((void**)&s2, g_s2);
    cudaGetSymbolAddress((void**)&vupd, g_vupd);
    cudaGetSymbolAddress((void**)&qupd, g_qupd);

    __nv_bfloat16 *vhi, *vlo, *qhi, *qlo, *vuhi, *vulo, *quhi, *qulo;
    __nv_bfloat16 *Wvth, *Wvtl, *Wqth, *Wqtl, *Wvoth, *Wvotl, *Wqoth, *Wqotl;
    cudaGetSymbolAddress((void**)&vhi, g_vhi);   cudaGetSymbolAddress((void**)&vlo, g_vlo);
    cudaGetSymbolAddress((void**)&qhi, g_qhi);   cudaGetSymbolAddress((void**)&qlo, g_qlo);
    cudaGetSymbolAddress((void**)&vuhi, g_vuhi); cudaGetSymbolAddress((void**)&vulo, g_vulo);
    cudaGetSymbolAddress((void**)&quhi, g_quhi); cudaGetSymbolAddress((void**)&qulo, g_qulo);
    cudaGetSymbolAddress((void**)&Wvth, g_Wvt_hi);   cudaGetSymbolAddress((void**)&Wvtl, g_Wvt_lo);
    cudaGetSymbolAddress((void**)&Wqth, g_Wqt_hi);   cudaGetSymbolAddress((void**)&Wqtl, g_Wqt_lo);
    cudaGetSymbolAddress((void**)&Wvoth, g_Wvot_hi); cudaGetSymbolAddress((void**)&Wvotl, g_Wvot_lo);
    cudaGetSymbolAddress((void**)&Wqoth, g_Wqot_hi); cudaGetSymbolAddress((void**)&Wqotl, g_Wqot_lo);

    cudaFuncSetAttribute(mma_gemm_bias_relu,
                         cudaFuncAttributeMaxDynamicSharedMemorySize, MMA_SMEM_BYTES);

    const dim3 t256(256);
    const float scale = 0.08838834764831845f;   // 1/sqrt(128)
    const size_t nVD = (size_t)CM * CD;

    // 0) bf16 splits of activations; transpose+split weights
    split_bf16<<<4096, t256>>>(v, vhi, vlo, nVD);
    split_bf16<<<4096, t256>>>(q, qhi, qlo, nVD);
    transpose_split<<<dim3(C3D / 32, CD / 32), dim3(32, 8)>>>(Wv, Wvth, Wvtl, CD, C3D);
    transpose_split<<<dim3(C3D / 32, CD / 32), dim3(32, 8)>>>(Wq, Wqth, Wqtl, CD, C3D);
    transpose_split<<<dim3(CD / 32, 2 * CD / 32), dim3(32, 8)>>>(Wvo, Wvoth, Wvotl, 2 * CD, CD);
    transpose_split<<<dim3(CD / 32, 2 * CD / 32), dim3(32, 8)>>>(Wqo, Wqoth, Wqotl, 2 * CD, CD);

    // 1) input transforms (tensor cores): T = relu(X @ W + b)
    mma_gemm_bias_relu<<<dim3(C3D / 128, CM / 128), t256, MMA_SMEM_BYTES>>>(
        vhi, vlo, vhi, vlo, CD, Wvth, Wvtl, bv, vtran, CM, C3D, CD);
    mma_gemm_bias_relu<<<dim3(C3D / 128, CM / 128), t256, MMA_SMEM_BYTES>>>(
        qhi, qlo, qhi, qlo, CD, Wqth, Wqtl, bq, qtran, CM, C3D, CD);

    // 2) scores
    attn_scores<<<dim3(8, 8, CB * CH), t256>>>(vtran, CD, qtran, 0, s1, scale);
    attn_scores<<<dim3(8, 8, CB * CH), t256>>>(qtran, CD, vtran, 0, s2, scale);

    // 3) softmax
    softmax_rows<<<CB * CH * CN, 256>>>(s1);
    softmax_rows<<<CB * CH * CN, 256>>>(s2);

    // 4) updates
    attn_av<<<dim3(2, 8, CB * CH), t256>>>(s1, qtran, 2 * CD, vupd);
    attn_av<<<dim3(2, 8, CB * CH), t256>>>(s2, vtran, 2 * CD, qupd);

    // 5) split updates, then output transforms with virtual concat
    split_bf16<<<4096, t256>>>(vupd, vuhi, vulo, nVD);
    split_bf16<<<4096, t256>>>(qupd, quhi, qulo, nVD);

    const size_t half = (size_t)CM * CD;
    mma_gemm_bias_relu<<<dim3(CD / 128, CM / 128), t256, MMA_SMEM_BYTES>>>(
        vhi, vlo, vuhi, vulo, CD, Wvoth, Wvotl, bvo, out, CM, CD, 2 * CD);
    mma_gemm_bias_relu<<<dim3(CD / 128, CM / 128), t256, MMA_SMEM_BYTES>>>(
        qhi, qlo, quhi, qulo, CD, Wqoth, Wqotl, bqo, out + half, CM, CD, 2 * CD);
}

// round 4
// speedup vs baseline: 2.5745x; 1.4012x over previous
#include <cuda_runtime.h>
#include <cuda_bf16.h>
#include <cstdint>
#include <math.h>

// Problem constants
constexpr int CB  = 32;
constexpr int CN  = 512;
constexpr int CD  = 1024;
constexpr int CH  = 8;
constexpr int CHD = 128;
constexpr int C3D = 3 * CD;
constexpr int CM  = CB * CN;   // 16384

// ---------------- scratch (device globals) ----------------------------------
__device__ float g_s1[(size_t)CB * CH * CN * CN];   // q2v scores fp32
__device__ float g_s2[(size_t)CB * CH * CN * CN];   // v2q scores fp32

__device__ __nv_bfloat16 g_vthi[(size_t)CM * C3D], g_vtlo[(size_t)CM * C3D];
__device__ __nv_bfloat16 g_qthi[(size_t)CM * C3D], g_qtlo[(size_t)CM * C3D];
__device__ __nv_bfloat16 g_p1hi[(size_t)CB * CH * CN * CN], g_p1lo[(size_t)CB * CH * CN * CN];
__device__ __nv_bfloat16 g_p2hi[(size_t)CB * CH * CN * CN], g_p2lo[(size_t)CB * CH * CN * CN];

__device__ __nv_bfloat16 g_vhi[(size_t)CM * CD],  g_vlo[(size_t)CM * CD];
__device__ __nv_bfloat16 g_qhi[(size_t)CM * CD],  g_qlo[(size_t)CM * CD];
__device__ __nv_bfloat16 g_vuhi[(size_t)CM * CD], g_vulo[(size_t)CM * CD];
__device__ __nv_bfloat16 g_quhi[(size_t)CM * CD], g_qulo[(size_t)CM * CD];
__device__ __nv_bfloat16 g_Wvt_hi[(size_t)C3D * CD],     g_Wvt_lo[(size_t)C3D * CD];
__device__ __nv_bfloat16 g_Wqt_hi[(size_t)C3D * CD],     g_Wqt_lo[(size_t)C3D * CD];
__device__ __nv_bfloat16 g_Wvot_hi[(size_t)CD * 2 * CD], g_Wvot_lo[(size_t)CD * 2 * CD];
__device__ __nv_bfloat16 g_Wqot_hi[(size_t)CD * 2 * CD], g_Wqot_lo[(size_t)CD * 2 * CD];

// ---------------- base-ISA PTX helpers ---------------------------------------
__device__ __forceinline__ uint32_t smem_u32(const void* p) {
    uint32_t a;
    asm("{ .reg .u64 t; cvta.to.shared.u64 t, %1; cvt.u32.u64 %0, t; }" : "=r"(a) : "l"(p));
    return a;
}
__device__ __forceinline__ void cp_async16(uint32_t dst, const void* src) {
    asm volatile("cp.async.cg.shared.global [%0], [%1], 16;" :: "r"(dst), "l"(src) : "memory");
}
__device__ __forceinline__ void cp_commit() { asm volatile("cp.async.commit_group;" ::: "memory"); }
template <int N>
__device__ __forceinline__ void cp_wait() { asm volatile("cp.async.wait_group %0;" :: "n"(N) : "memory"); }

__device__ __forceinline__ void ldm_x4(uint32_t* r, uint32_t addr) {
    asm volatile("ldmatrix.sync.aligned.m8n8.x4.shared.b16 {%0,%1,%2,%3}, [%4];"
        : "=r"(r[0]), "=r"(r[1]), "=r"(r[2]), "=r"(r[3]) : "r"(addr));
}
__device__ __forceinline__ void ldm_x2(uint32_t* r, uint32_t addr) {
    asm volatile("ldmatrix.sync.aligned.m8n8.x2.shared.b16 {%0,%1}, [%2];"
        : "=r"(r[0]), "=r"(r[1]) : "r"(addr));
}
__device__ __forceinline__ void ldm_x2_trans(uint32_t* r, uint32_t addr) {
    asm volatile("ldmatrix.sync.aligned.m8n8.x2.trans.shared.b16 {%0,%1}, [%2];"
        : "=r"(r[0]), "=r"(r[1]) : "r"(addr));
}
__device__ __forceinline__ void mma_bf16(float* c, const uint32_t* a, const uint32_t* b) {
    asm volatile("mma.sync.aligned.m16n8k16.row.col.f32.bf16.bf16.f32 "
        "{%0,%1,%2,%3}, {%4,%5,%6,%7}, {%8,%9}, {%0,%1,%2,%3};"
        : "+f"(c[0]), "+f"(c[1]), "+f"(c[2]), "+f"(c[3])
        : "r"(a[0]), "r"(a[1]), "r"(a[2]), "r"(a[3]), "r"(b[0]), "r"(b[1]));
}
__device__ __forceinline__ __nv_bfloat162 split_pair(float x, float y,
                                                     __nv_bfloat162& lo) {
    __nv_bfloat16 hx = __float2bfloat16(x), hy = __float2bfloat16(y);
    lo = __nv_bfloat162(__float2bfloat16(x - __bfloat162float(hx)),
                        __float2bfloat16(y - __bfloat162float(hy)));
    return __nv_bfloat162(hx, hy);
}

// Common tiling constants (128x128 CTA, BK=32, 8 warps 4Mx2N)
constexpr int TSTR    = 40;
constexpr int TILE_H  = 128 * TSTR;
constexpr int STAGE_H = 4 * TILE_H;
constexpr int GEMM_SMEM = 2 * STAGE_H * 2;          // 81920 B

// =============================================================================
// GEMM core macro-parts shared by the three MMA kernels (written out per kernel
// for clarity). All use: warp tile 32x64, 3-term split accumulate.
// =============================================================================

// ---------- stage-1 GEMM: Chi/Clo = split(relu(A @ W + bias)) ----------------
__global__ __launch_bounds__(256)
void gemm_in(const __nv_bfloat16* __restrict__ Ahi, const __nv_bfloat16* __restrict__ Alo,
             const __nv_bfloat16* __restrict__ Bthi, const __nv_bfloat16* __restrict__ Btlo,
             const float* __restrict__ bias,
             __nv_bfloat16* __restrict__ Chi, __nv_bfloat16* __restrict__ Clo,
             int M, int N, int K)
{
    extern __shared__ __nv_bfloat16 sm[];
    const uint32_t smb = smem_u32(sm);
    const int tid = threadIdx.x, wid = tid >> 5, lane = tid & 31;
    const int bm0 = blockIdx.y * 128, bn0 = blockIdx.x * 128;
    const int nk = K / 32;
    const int mw = (wid & 3) * 32, nw = (wid >> 2) * 64;

    auto load_stage = [&](int kc, int buf) {
        const int kk = kc * 32;
        const __nv_bfloat16* ah = Ahi + (size_t)bm0 * K + kk;
        const __nv_bfloat16* al = Alo + (size_t)bm0 * K + kk;
        const __nv_bfloat16* bh = Bthi + (size_t)bn0 * K + kk;
        const __nv_bfloat16* bl = Btlo + (size_t)bn0 * K + kk;
        const uint32_t base = smb + (uint32_t)buf * STAGE_H * 2;
        #pragma unroll
        for (int i = 0; i < 2; ++i) {
            const int idx = tid + i * 256;
            const int r = idx >> 2, c = (idx & 3) * 8;
            const uint32_t doff = (uint32_t)(r * TSTR + c) * 2;
            cp_async16(base + 0 * TILE_H * 2 + doff, ah + (size_t)r * K + c);
            cp_async16(base + 1 * TILE_H * 2 + doff, al + (size_t)r * K + c);
            cp_async16(base + 2 * TILE_H * 2 + doff, bh + (size_t)r * K + c);
            cp_async16(base + 3 * TILE_H * 2 + doff, bl + (size_t)r * K + c);
        }
        cp_commit();
    };

    float acc[2][8][4] = {};
    const int arow = lane & 15, acol = (lane >> 4) * 8;
    const int brow = lane & 7,  bcol = ((lane >> 3) & 1) * 8;

    load_stage(0, 0);
    for (int kc = 0; kc < nk; ++kc) {
        const int buf = kc & 1;
        if (kc + 1 < nk) { load_stage(kc + 1, buf ^ 1); cp_wait<1>(); }
        else             { cp_wait<0>(); }
        __syncthreads();
        const uint32_t base = smb + (uint32_t)buf * STAGE_H * 2;
        #pragma unroll
        for (int ks = 0; ks < 2; ++ks) {
            const int k0 = ks * 16;
            uint32_t ah[2][4], al[2][4];
            #pragma unroll
            for (int mi = 0; mi < 2; ++mi) {
                const uint32_t aoff = (uint32_t)((mw + mi * 16 + arow) * TSTR + k0 + acol) * 2;
                ldm_x4(ah[mi], base + 0 * TILE_H * 2 + aoff);
                ldm_x4(al[mi], base + 1 * TILE_H * 2 + aoff);
            }
            #pragma unroll
            for (int ni = 0; ni < 8; ++ni) {
                const uint32_t boff = (uint32_t)((nw + ni * 8 + brow) * TSTR + k0 + bcol) * 2;
                uint32_t bh[2], bl[2];
                ldm_x2(bh, base + 2 * TILE_H * 2 + boff);
                ldm_x2(bl, base + 3 * TILE_H * 2 + boff);
                #pragma unroll
                for (int mi = 0; mi < 2; ++mi) {
                    mma_bf16(acc[mi][ni], ah[mi], bh);
                    mma_bf16(acc[mi][ni], ah[mi], bl);
                    mma_bf16(acc[mi][ni], al[mi], bh);
                }
            }
        }
        __syncthreads();
    }

    const int g = lane >> 2, tq = lane & 3;
    #pragma unroll
    for (int mi = 0; mi < 2; ++mi) {
        const int row0 = bm0 + mw + mi * 16 + g;
        #pragma unroll
        for (int ni = 0; ni < 8; ++ni) {
            const int col = bn0 + nw + ni * 8 + tq * 2;
            const float b0 = __ldg(&bias[col]), b1 = __ldg(&bias[col + 1]);
            const float x0 = fmaxf(acc[mi][ni][0] + b0, 0.f);
            const float x1 = fmaxf(acc[mi][ni][1] + b1, 0.f);
            const float x2 = fmaxf(acc[mi][ni][2] + b0, 0.f);
            const float x3 = fmaxf(acc[mi][ni][3] + b1, 0.f);
            __nv_bfloat162 lo01, lo23;
            const __nv_bfloat162 hi01 = split_pair(x0, x1, lo01);
            const __nv_bfloat162 hi23 = split_pair(x2, x3, lo23);
            *reinterpret_cast<__nv_bfloat162*>(&Chi[(size_t)row0 * N + col]) = hi01;
            *reinterpret_cast<__nv_bfloat162*>(&Clo[(size_t)row0 * N + col]) = lo01;
            *reinterpret_cast<__nv_bfloat162*>(&Chi[(size_t)(row0 + 8) * N + col]) = hi23;
            *reinterpret_cast<__nv_bfloat162*>(&Clo[(size_t)(row0 + 8) * N + col]) = lo23;
        }
    }
}

// ---------- stage-5 GEMM: C = relu(concat(A0,A1) @ W + bias), fp32 out -------
__global__ __launch_bounds__(256)
void gemm_out(const __nv_bfloat16* __restrict__ A0hi, const __nv_bfloat16* __restrict__ A0lo,
              const __nv_bfloat16* __restrict__ A1hi, const __nv_bfloat16* __restrict__ A1lo,
              int K0,
              const __nv_bfloat16* __restrict__ Bthi, const __nv_bfloat16* __restrict__ Btlo,
              const float* __restrict__ bias, float* __restrict__ C,
              int M, int N, int K)
{
    extern __shared__ __nv_bfloat16 sm[];
    const uint32_t smb = smem_u32(sm);
    const int tid = threadIdx.x, wid = tid >> 5, lane = tid & 31;
    const int bm0 = blockIdx.y * 128, bn0 = blockIdx.x * 128;
    const int nk = K / 32, K1 = K - K0;
    const int mw = (wid & 3) * 32, nw = (wid >> 2) * 64;

    auto load_stage = [&](int kc, int buf) {
        const int kk = kc * 32;
        const __nv_bfloat16 *ah, *al; int ldA, ka;
        if (kk < K0) { ah = A0hi; al = A0lo; ldA = K0; ka = kk; }
        else         { ah = A1hi; al = A1lo; ldA = K1; ka = kk - K0; }
        ah += (size_t)bm0 * ldA + ka;
        al += (size_t)bm0 * ldA + ka;
        const __nv_bfloat16* bh = Bthi + (size_t)bn0 * K + kk;
        const __nv_bfloat16* bl = Btlo + (size_t)bn0 * K + kk;
        const uint32_t base = smb + (uint32_t)buf * STAGE_H * 2;
        #pragma unroll
        for (int i = 0; i < 2; ++i) {
            const int idx = tid + i * 256;
            const int r = idx >> 2, c = (idx & 3) * 8;
            const uint32_t doff = (uint32_t)(r * TSTR + c) * 2;
            cp_async16(base + 0 * TILE_H * 2 + doff, ah + (size_t)r * ldA + c);
            cp_async16(base + 1 * TILE_H * 2 + doff, al + (size_t)r * ldA + c);
            cp_async16(base + 2 * TILE_H * 2 + doff, bh + (size_t)r * K + c);
            cp_async16(base + 3 * TILE_H * 2 + doff, bl + (size_t)r * K + c);
        }
        cp_commit();
    };

    float acc[2][8][4] = {};
    const int arow = lane & 15, acol = (lane >> 4) * 8;
    const int brow = lane & 7,  bcol = ((lane >> 3) & 1) * 8;

    load_stage(0, 0);
    for (int kc = 0; kc < nk; ++kc) {
        const int buf = kc & 1;
        if (kc + 1 < nk) { load_stage(kc + 1, buf ^ 1); cp_wait<1>(); }
        else             { cp_wait<0>(); }
        __syncthreads();
        const uint32_t base = smb + (uint32_t)buf * STAGE_H * 2;
        #pragma unroll
        for (int ks = 0; ks < 2; ++ks) {
            const int k0 = ks * 16;
            uint32_t ah[2][4], al[2][4];
            #pragma unroll
            for (int mi = 0; mi < 2; ++mi) {
                const uint32_t aoff = (uint32_t)((mw + mi * 16 + arow) * TSTR + k0 + acol) * 2;
                ldm_x4(ah[mi], base + 0 * TILE_H * 2 + aoff);
                ldm_x4(al[mi], base + 1 * TILE_H * 2 + aoff);
            }
            #pragma unroll
            for (int ni = 0; ni < 8; ++ni) {
                const uint32_t boff = (uint32_t)((nw + ni * 8 + brow) * TSTR + k0 + bcol) * 2;
                uint32_t bh[2], bl[2];
                ldm_x2(bh, base + 2 * TILE_H * 2 + boff);
                ldm_x2(bl, base + 3 * TILE_H * 2 + boff);
                #pragma unroll
                for (int mi = 0; mi < 2; ++mi) {
                    mma_bf16(acc[mi][ni], ah[mi], bh);
                    mma_bf16(acc[mi][ni], ah[mi], bl);
                    mma_bf16(acc[mi][ni], al[mi], bh);
                }
            }
        }
        __syncthreads();
    }

    const int g = lane >> 2, tq = lane & 3;
    #pragma unroll
    for (int mi = 0; mi < 2; ++mi) {
        const int row0 = bm0 + mw + mi * 16 + g;
        #pragma unroll
        for (int ni = 0; ni < 8; ++ni) {
            const int col = bn0 + nw + ni * 8 + tq * 2;
            const float b0 = __ldg(&bias[col]), b1 = __ldg(&bias[col + 1]);
            float2 o0, o1;
            o0.x = fmaxf(acc[mi][ni][0] + b0, 0.f);
            o0.y = fmaxf(acc[mi][ni][1] + b1, 0.f);
            o1.x = fmaxf(acc[mi][ni][2] + b0, 0.f);
            o1.y = fmaxf(acc[mi][ni][3] + b1, 0.f);
            *reinterpret_cast<float2*>(&C[(size_t)row0 * N + col]) = o0;
            *reinterpret_cast<float2*>(&C[(size_t)(row0 + 8) * N + col]) = o1;
        }
    }
}

// ---------- scores: S[bz,n,m] = scale * sum_k A[n,k] B[m,k] (NT) -------------
// A = T_a rows (query slice, col offset offA+h*HD), B = T_b rows (key slice).
__global__ __launch_bounds__(256)
void attn_scores_mma(const __nv_bfloat16* __restrict__ Tahi, const __nv_bfloat16* __restrict__ Talo,
                     int offA,
                     const __nv_bfloat16* __restrict__ Tbhi, const __nv_bfloat16* __restrict__ Tblo,
                     int offB, float* __restrict__ S, float scale)
{
    extern __shared__ __nv_bfloat16 sm[];
    const uint32_t smb = smem_u32(sm);
    const int tid = threadIdx.x, wid = tid >> 5, lane = tid & 31;
    const int bz = blockIdx.z, b = bz / CH, h = bz % CH;
    const int bm0 = blockIdx.y * 128;   // n
    const int bn0 = blockIdx.x * 128;   // m
    const int mw = (wid & 3) * 32, nw = (wid >> 2) * 64;

    const size_t arow_base = (size_t)(b * CN + bm0) * C3D + offA + h * CHD;
    const size_t brow_base = (size_t)(b * CN + bn0) * C3D + offB + h * CHD;

    auto load_stage = [&](int kc, int buf) {
        const int kk = kc * 32;
        const __nv_bfloat16* ah = Tahi + arow_base + kk;
        const __nv_bfloat16* al = Talo + arow_base + kk;
        const __nv_bfloat16* bh = Tbhi + brow_base + kk;
        const __nv_bfloat16* bl = Tblo + brow_base + kk;
        const uint32_t base = smb + (uint32_t)buf * STAGE_H * 2;
        #pragma unroll
        for (int i = 0; i < 2; ++i) {
            const int idx = tid + i * 256;
            const int r = idx >> 2, c = (idx & 3) * 8;
            const uint32_t doff = (uint32_t)(r * TSTR + c) * 2;
            cp_async16(base + 0 * TILE_H * 2 + doff, ah + (size_t)r * C3D + c);
            cp_async16(base + 1 * TILE_H * 2 + doff, al + (size_t)r * C3D + c);
            cp_async16(base + 2 * TILE_H * 2 + doff, bh + (size_t)r * C3D + c);
            cp_async16(base + 3 * TILE_H * 2 + doff, bl + (size_t)r * C3D + c);
        }
        cp_commit();
    };

    float acc[2][8][4] = {};
    const int arow = lane & 15, acol = (lane >> 4) * 8;
    const int brow = lane & 7,  bcol = ((lane >> 3) & 1) * 8;

    load_stage(0, 0);
    #pragma unroll
    for (int kc = 0; kc < CHD / 32; ++kc) {
        const int buf = kc & 1;
        if (kc + 1 < CHD / 32) { load_stage(kc + 1, buf ^ 1); cp_wait<1>(); }
        else                   { cp_wait<0>(); }
        __syncthreads();
        const uint32_t base = smb + (uint32_t)buf * STAGE_H * 2;
        #pragma unroll
        for (int ks = 0; ks < 2; ++ks) {
            const int k0 = ks * 16;
            uint32_t ah[2][4], al[2][4];
            #pragma unroll
            for (int mi = 0; mi < 2; ++mi) {
                const uint32_t aoff = (uint32_t)((mw + mi * 16 + arow) * TSTR + k0 + acol) * 2;
                ldm_x4(ah[mi], base + 0 * TILE_H * 2 + aoff);
                ldm_x4(al[mi], base + 1 * TILE_H * 2 + aoff);
            }
            #pragma unroll
            for (int ni = 0; ni < 8; ++ni) {
                const uint32_t boff = (uint32_t)((nw + ni * 8 + brow) * TSTR + k0 + bcol) * 2;
                uint32_t bh[2], bl[2];
                ldm_x2(bh, base + 2 * TILE_H * 2 + boff);
                ldm_x2(bl, base + 3 * TILE_H * 2 + boff);
                #pragma unroll
                for (int mi = 0; mi < 2; ++mi) {
                    mma_bf16(acc[mi][ni], ah[mi], bh);
                    mma_bf16(acc[mi][ni], ah[mi], bl);
                    mma_bf16(acc[mi][ni], al[mi], bh);
                }
            }
        }
        __syncthreads();
    }

    float* Sb = S + (size_t)bz * CN * CN;
    const int g = lane >> 2, tq = lane & 3;
    #pragma unroll
    for (int mi = 0; mi < 2; ++mi) {
        const int row0 = bm0 + mw + mi * 16 + g;
        #pragma unroll
        for (int ni = 0; ni < 8; ++ni) {
            const int col = bn0 + nw + ni * 8 + tq * 2;
            float2 o0, o1;
            o0.x = acc[mi][ni][0] * scale; o0.y = acc[mi][ni][1] * scale;
            o1.x = acc[mi][ni][2] * scale; o1.y = acc[mi][ni][3] * scale;
            *reinterpret_cast<float2*>(&Sb[(size_t)row0 * CN + col]) = o0;
            *reinterpret_cast<float2*>(&Sb[(size_t)(row0 + 8) * CN + col]) = o1;
        }
    }
}

// ---------- softmax over 512 cols + bf16 hi/lo split -------------------------
__global__ __launch_bounds__(256)
void softmax_split(const float* __restrict__ S,
                   __nv_bfloat16* __restrict__ Phi, __nv_bfloat16* __restrict__ Plo)
{
    const size_t roff = (size_t)blockIdx.x * CN;
    const float* p = S + roff;
    const int t = threadIdx.x;
    const float v0 = p[t], v1 = p[t + 256];

    __shared__ float red[256];
    red[t] = fmaxf(v0, v1);
    __syncthreads();
    #pragma unroll
    for (int s = 128; s > 0; s >>= 1) {
        if (t < s) red[t] = fmaxf(red[t], red[t + s]);
        __syncthreads();
    }
    const float mx = red[0];
    __syncthreads();

    const float e0 = __expf(v0 - mx), e1 = __expf(v1 - mx);
    red[t] = e0 + e1;
    __syncthreads();
    #pragma unroll
    for (int s = 128; s > 0; s >>= 1) {
        if (t < s) red[t] += red[t + s];
        __syncthreads();
    }
    const float inv = 1.f / red[0];
    const float p0 = e0 * inv, p1 = e1 * inv;
    const __nv_bfloat16 h0 = __float2bfloat16(p0), h1 = __float2bfloat16(p1);
    Phi[roff + t]       = h0;
    Phi[roff + t + 256] = h1;
    Plo[roff + t]       = __float2bfloat16(p0 - __bfloat162float(h0));
    Plo[roff + t + 256] = __float2bfloat16(p1 - __bfloat162float(h1));
}

// ---------- AV: U[n,d] = sum_m P[n,m] V[m,d]; out split bf16 -----------------
// P: [bz][n][m] bf16 hi/lo (row-major, m contiguous). V: value slice of T
// (rows m, cols offV+h*HD+d, stride 3D). Output Uhi/Ulo [b*N+n][D] at h*HD+d.
constexpr int PSTR  = 40;                  // P tile stride (halves)
constexpr int VSTR  = 136;                 // V tile stride (halves)
constexpr int PT_H  = 128 * PSTR;          // 5120 halves
constexpr int VT_H  = 32 * VSTR;           // 4352 halves
constexpr int AV_STAGE_H = 2 * PT_H + 2 * VT_H;        // 18944
constexpr int AV_SMEM = 2 * AV_STAGE_H * 2;            // 75776 B

__global__ __launch_bounds__(256)
void attn_av_mma(const __nv_bfloat16* __restrict__ Phi, const __nv_bfloat16* __restrict__ Plo,
                 const __nv_bfloat16* __restrict__ Thi, const __nv_bfloat16* __restrict__ Tlo,
                 int offV,
                 __nv_bfloat16* __restrict__ Uhi, __nv_bfloat16* __restrict__ Ulo)
{
    extern __shared__ __nv_bfloat16 sm[];
    const uint32_t smb = smem_u32(sm);
    const int tid = threadIdx.x, wid = tid >> 5, lane = tid & 31;
    const int bz = blockIdx.z, b = bz / CH, h = bz % CH;
    const int n0 = blockIdx.y * 128;
    const int mw = (wid & 3) * 32, nw = (wid >> 2) * 64;   // n-offset, d-offset

    const size_t prow_base = ((size_t)bz * CN + n0) * CN;
    const size_t vcol_base = offV + h * CHD;

    auto load_stage = [&](int kc, int buf) {
        const int m0 = kc * 32;
        const uint32_t base = smb + (uint32_t)buf * AV_STAGE_H * 2;
        const __nv_bfloat16* ph = Phi + prow_base + m0;
        const __nv_bfloat16* pl = Plo + prow_base + m0;
        const __nv_bfloat16* vh = Thi + (size_t)(b * CN + m0) * C3D + vcol_base;
        const __nv_bfloat16* vl = Tlo + (size_t)(b * CN + m0) * C3D + vcol_base;
        // P tiles: 128 rows x 32 halves
        #pragma unroll
        for (int i = 0; i < 2; ++i) {
            const int idx = tid + i * 256;
            const int r = idx >> 2, c = (idx & 3) * 8;
            const uint32_t doff = (uint32_t)(r * PSTR + c) * 2;
            cp_async16(base + doff,              ph + (size_t)r * CN + c);
            cp_async16(base + PT_H * 2 + doff,   pl + (size_t)r * CN + c);
        }
        // V tiles: 32 rows x 128 halves
        #pragma unroll
        for (int i = 0; i < 2; ++i) {
            const int idx = tid + i * 256;
            const int r = idx >> 4, c = (idx & 15) * 8;
            const uint32_t doff = (uint32_t)(r * VSTR + c) * 2;
            cp_async16(base + 2 * PT_H * 2 + doff,            vh + (size_t)r * C3D + c);
            cp_async16(base + (2 * PT_H + VT_H) * 2 + doff,   vl + (size_t)r * C3D + c);
        }
        cp_commit();
    };

    float acc[2][8][4] = {};
    const int arow = lane & 15, acol = (lane >> 4) * 8;
    const int vrow = lane & 15;   // k-row for trans B load

    load_stage(0, 0);
    #pragma unroll 1
    for (int kc = 0; kc < CN / 32; ++kc) {
        const int buf = kc & 1;
        if (kc + 1 < CN / 32) { load_stage(kc + 1, buf ^ 1); cp_wait<1>(); }
        else                  { cp_wait<0>(); }
        __syncthreads();
        const uint32_t base = smb + (uint32_t)buf * AV_STAGE_H * 2;
        #pragma unroll
        for (int ks = 0; ks < 2; ++ks) {
            const int k0 = ks * 16;
            uint32_t ph[2][4], pl[2][4];
            #pragma unroll
            for (int mi = 0; mi < 2; ++mi) {
                const uint32_t aoff = (uint32_t)((mw + mi * 16 + arow) * PSTR + k0 + acol) * 2;
                ldm_x4(ph[mi], base + aoff);
                ldm_x4(pl[mi], base + PT_H * 2 + aoff);
            }
            #pragma unroll
            for (int ni = 0; ni < 8; ++ni) {
                // B (V) loaded transposed: addr = row (k0+vrow), col block d
                const uint32_t boff = (uint32_t)((k0 + vrow) * VSTR + nw + ni * 8) * 2;
                uint32_t vh[2], vl[2];
                ldm_x2_trans(vh, base + 2 * PT_H * 2 + boff);
                ldm_x2_trans(vl, base + (2 * PT_H + VT_H) * 2 + boff);
                #pragma unroll
                for (int mi = 0; mi < 2; ++mi) {
                    mma_bf16(acc[mi][ni], ph[mi], vh);
                    mma_bf16(acc[mi][ni], ph[mi], vl);
                    mma_bf16(acc[mi][ni], pl[mi], vh);
                }
            }
        }
        __syncthreads();
    }

    const int g = lane >> 2, tq = lane & 3;
    #pragma unroll
    for (int mi = 0; mi < 2; ++mi) {
        const int row0 = n0 + mw + mi * 16 + g;
        #pragma unroll
        for (int ni = 0; ni < 8; ++ni) {
            const int col = h * CHD + nw + ni * 8 + tq * 2;
            const size_t o0 = (size_t)(b * CN + row0) * CD + col;
            const size_t o1 = (size_t)(b * CN + row0 + 8) * CD + col;
            __nv_bfloat162 lo01, lo23;
            const __nv_bfloat162 hi01 = split_pair(acc[mi][ni][0], acc[mi][ni][1], lo01);
            const __nv_bfloat162 hi23 = split_pair(acc[mi][ni][2], acc[mi][ni][3], lo23);
            *reinterpret_cast<__nv_bfloat162*>(&Uhi[o0]) = hi01;
            *reinterpret_cast<__nv_bfloat162*>(&Ulo[o0]) = lo01;
            *reinterpret_cast<__nv_bfloat162*>(&Uhi[o1]) = hi23;
            *reinterpret_cast<__nv_bfloat162*>(&Ulo[o1]) = lo23;
        }
    }
}

// =============================================================================
// precompute kernels
// =============================================================================
__global__ __launch_bounds__(256)
void split_bf16(const float* __restrict__ x, __nv_bfloat16* __restrict__ hi,
                __nv_bfloat16* __restrict__ lo, size_t n)
{
    const size_t stride = (size_t)gridDim.x * blockDim.x * 4;
    for (size_t i = ((size_t)blockIdx.x * blockDim.x + threadIdx.x) * 4; i < n; i += stride) {
        float4 v = *reinterpret_cast<const float4*>(x + i);
        __nv_bfloat162 lo01, lo23;
        const __nv_bfloat162 hi01 = split_pair(v.x, v.y, lo01);
        const __nv_bfloat162 hi23 = split_pair(v.z, v.w, lo23);
        *reinterpret_cast<__nv_bfloat162*>(hi + i)     = hi01;
        *reinterpret_cast<__nv_bfloat162*>(hi + i + 2) = hi23;
        *reinterpret_cast<__nv_bfloat162*>(lo + i)     = lo01;
        *reinterpret_cast<__nv_bfloat162*>(lo + i + 2) = lo23;
    }
}

__global__ __launch_bounds__(256)
void transpose_split(const float* __restrict__ W, __nv_bfloat16* __restrict__ thi,
                     __nv_bfloat16* __restrict__ tlo, int K, int N)
{
    __shared__ float t[32][33];
    const int k0 = blockIdx.y * 32, n0 = blockIdx.x * 32;
    const int tx = threadIdx.x, ty = threadIdx.y;
    for (int i = ty; i < 32; i += 8)
        t[i][tx] = W[(size_t)(k0 + i) * N + n0 + tx];
    __syncthreads();
    for (int i = ty; i < 32; i += 8) {
        const float x = t[tx][i];
        const __nv_bfloat16 h = __float2bfloat16(x);
        thi[(size_t)(n0 + i) * K + k0 + tx] = h;
        tlo[(size_t)(n0 + i) * K + k0 + tx] = __float2bfloat16(x - __bfloat162float(h));
    }
}

// =============================================================================
// launch
// =============================================================================
extern "C" void kernel_launch(void* const* d_in, const int* in_sizes, int n_in,
                              void* d_out, int out_size)
{
    const float* v   = (const float*)d_in[0];
    const float* q   = (const float*)d_in[1];
    const float* Wv  = (const float*)d_in[2];
    const float* bv  = (const float*)d_in[3];
    const float* Wq  = (const float*)d_in[4];
    const float* bq  = (const float*)d_in[5];
    const float* Wvo = (const float*)d_in[6];
    const float* bvo = (const float*)d_in[7];
    const float* Wqo = (const float*)d_in[8];
    const float* bqo = (const float*)d_in[9];
    float* out = (float*)d_out;

    float *s1, *s2;
    cudaGetSymbolAddress((void**)&s1, g_s1);
    cudaGetSymbolAddress((void**)&s2, g_s2);
    __nv_bfloat16 *vthi, *vtlo, *qthi, *qtlo, *p1hi, *p1lo, *p2hi, *p2lo;
    cudaGetSymbolAddress((void**)&vthi, g_vthi); cudaGetSymbolAddress((void**)&vtlo, g_vtlo);
    cudaGetSymbolAddress((void**)&qthi, g_qthi); cudaGetSymbolAddress((void**)&qtlo, g_qtlo);
    cudaGetSymbolAddress((void**)&p1hi, g_p1hi); cudaGetSymbolAddress((void**)&p1lo, g_p1lo);
    cudaGetSymbolAddress((void**)&p2hi, g_p2hi); cudaGetSymbolAddress((void**)&p2lo, g_p2lo);
    __nv_bfloat16 *vhi, *vlo, *qhi, *qlo, *vuhi, *vulo, *quhi, *qulo;
    cudaGetSymbolAddress((void**)&vhi, g_vhi);   cudaGetSymbolAddress((void**)&vlo, g_vlo);
    cudaGetSymbolAddress((void**)&qhi, g_qhi);   cudaGetSymbolAddress((void**)&qlo, g_qlo);
    cudaGetSymbolAddress((void**)&vuhi, g_vuhi); cudaGetSymbolAddress((void**)&vulo, g_vulo);
    cudaGetSymbolAddress((void**)&quhi, g_quhi); cudaGetSymbolAddress((void**)&qulo, g_qulo);
    __nv_bfloat16 *Wvth, *Wvtl, *Wqth, *Wqtl, *Wvoth, *Wvotl, *Wqoth, *Wqotl;
    cudaGetSymbolAddress((void**)&Wvth, g_Wvt_hi);   cudaGetSymbolAddress((void**)&Wvtl, g_Wvt_lo);
    cudaGetSymbolAddress((void**)&Wqth, g_Wqt_hi);   cudaGetSymbolAddress((void**)&Wqtl, g_Wqt_lo);
    cudaGetSymbolAddress((void**)&Wvoth, g_Wvot_hi); cudaGetSymbolAddress((void**)&Wvotl, g_Wvot_lo);
    cudaGetSymbolAddress((void**)&Wqoth, g_Wqot_hi); cudaGetSymbolAddress((void**)&Wqotl, g_Wqot_lo);

    cudaFuncSetAttribute(gemm_in,  cudaFuncAttributeMaxDynamicSharedMemorySize, GEMM_SMEM);
    cudaFuncSetAttribute(gemm_out, cudaFuncAttributeMaxDynamicSharedMemorySize, GEMM_SMEM);
    cudaFuncSetAttribute(attn_scores_mma, cudaFuncAttributeMaxDynamicSharedMemorySize, GEMM_SMEM);
    cudaFuncSetAttribute(attn_av_mma, cudaFuncAttributeMaxDynamicSharedMemorySize, AV_SMEM);

    const dim3 t256(256);
    const float scale = 0.08838834764831845f;   // 1/sqrt(128)
    const size_t nVD = (size_t)CM * CD;

    // 0) splits of inputs; transpose+split weights
    split_bf16<<<4096, t256>>>(v, vhi, vlo, nVD);
    split_bf16<<<4096, t256>>>(q, qhi, qlo, nVD);
    transpose_split<<<dim3(C3D / 32, CD / 32), dim3(32, 8)>>>(Wv, Wvth, Wvtl, CD, C3D);
    transpose_split<<<dim3(C3D / 32, CD / 32), dim3(32, 8)>>>(Wq, Wqth, Wqtl, CD, C3D);
    transpose_split<<<dim3(CD / 32, 2 * CD / 32), dim3(32, 8)>>>(Wvo, Wvoth, Wvotl, 2 * CD, CD);
    transpose_split<<<dim3(CD / 32, 2 * CD / 32), dim3(32, 8)>>>(Wqo, Wqoth, Wqotl, 2 * CD, CD);

    // 1) input transforms -> bf16 hi/lo directly
    gemm_in<<<dim3(C3D / 128, CM / 128), t256, GEMM_SMEM>>>(
        vhi, vlo, Wvth, Wvtl, bv, vthi, vtlo, CM, C3D, CD);
    gemm_in<<<dim3(C3D / 128, CM / 128), t256, GEMM_SMEM>>>(
        qhi, qlo, Wqth, Wqtl, bq, qthi, qtlo, CM, C3D, CD);

    // 2) scores (tensor cores): q2v = vq . qk^T ; v2q = qq . vk^T
    attn_scores_mma<<<dim3(4, 4, CB * CH), t256, GEMM_SMEM>>>(
        vthi, vtlo, CD, qthi, qtlo, 0, s1, scale);
    attn_scores_mma<<<dim3(4, 4, CB * CH), t256, GEMM_SMEM>>>(
        qthi, qtlo, CD, vthi, vtlo, 0, s2, scale);

    // 3) softmax + split to bf16 hi/lo
    softmax_split<<<CB * CH * CN, 256>>>(s1, p1hi, p1lo);
    softmax_split<<<CB * CH * CN, 256>>>(s2, p2hi, p2lo);

    // 4) AV (tensor cores): v_update = A_q2v @ qv ; q_update = A_v2q @ vv
    attn_av_mma<<<dim3(1, 4, CB * CH), t256, AV_SMEM>>>(
        p1hi, p1lo, qthi, qtlo, 2 * CD, vuhi, vulo);
    attn_av_mma<<<dim3(1, 4, CB * CH), t256, AV_SMEM>>>(
        p2hi, p2lo, vthi, vtlo, 2 * CD, quhi, qulo);

    // 5) output transforms (virtual concat)
    const size_t half = (size_t)CM * CD;
    gemm_out<<<dim3(CD / 128, CM / 128), t256, GEMM_SMEM>>>(
        vhi, vlo, vuhi, vulo, CD, Wvoth, Wvotl, bvo, out, CM, CD, 2 * CD);
    gemm_out<<<dim3(CD / 128, CM / 128), t256, GEMM_SMEM>>>(
        qhi, qlo, quhi, qulo, CD, Wqoth, Wqotl, bqo, out + half, CM, CD, 2 * CD);
}

// round 5
// speedup vs baseline: 3.4813x; 1.3522x over previous
#include <cuda_runtime.h>
#include <cuda_fp16.h>
#include <cstdint>
#include <math.h>

// Problem constants
constexpr int CB  = 32;
constexpr int CN  = 512;
constexpr int CD  = 1024;
constexpr int CH  = 8;
constexpr int CHD = 128;
constexpr int C3D = 3 * CD;
constexpr int CM  = CB * CN;   // 16384

// ---------------- scratch (device globals) ----------------------------------
__device__ float g_s1[(size_t)CB * CH * CN * CN];
__device__ float g_s2[(size_t)CB * CH * CN * CN];

__device__ __half g_vthi[(size_t)CM * C3D], g_vtlo[(size_t)CM * C3D];
__device__ __half g_qthi[(size_t)CM * C3D], g_qtlo[(size_t)CM * C3D];
__device__ __half g_p1hi[(size_t)CB * CH * CN * CN];
__device__ __half g_p2hi[(size_t)CB * CH * CN * CN];

__device__ __half g_vhi[(size_t)CM * CD],  g_qhi[(size_t)CM * CD];
__device__ __half g_vuhi[(size_t)CM * CD], g_quhi[(size_t)CM * CD];
__device__ __half g_Wvt_hi[(size_t)C3D * CD],     g_Wvt_lo[(size_t)C3D * CD];
__device__ __half g_Wqt_hi[(size_t)C3D * CD],     g_Wqt_lo[(size_t)C3D * CD];
__device__ __half g_Wvot_hi[(size_t)CD * 2 * CD], g_Wvot_lo[(size_t)CD * 2 * CD];
__device__ __half g_Wqot_hi[(size_t)CD * 2 * CD], g_Wqot_lo[(size_t)CD * 2 * CD];

// ---------------- base-ISA PTX helpers ---------------------------------------
__device__ __forceinline__ uint32_t smem_u32(const void* p) {
    uint32_t a;
    asm("{ .reg .u64 t; cvta.to.shared.u64 t, %1; cvt.u32.u64 %0, t; }" : "=r"(a) : "l"(p));
    return a;
}
__device__ __forceinline__ void cp_async16(uint32_t dst, const void* src) {
    asm volatile("cp.async.cg.shared.global [%0], [%1], 16;" :: "r"(dst), "l"(src) : "memory");
}
__device__ __forceinline__ void cp_commit() { asm volatile("cp.async.commit_group;" ::: "memory"); }
template <int N>
__device__ __forceinline__ void cp_wait() { asm volatile("cp.async.wait_group %0;" :: "n"(N) : "memory"); }

__device__ __forceinline__ void ldm_x4(uint32_t* r, uint32_t addr) {
    asm volatile("ldmatrix.sync.aligned.m8n8.x4.shared.b16 {%0,%1,%2,%3}, [%4];"
        : "=r"(r[0]), "=r"(r[1]), "=r"(r[2]), "=r"(r[3]) : "r"(addr));
}
__device__ __forceinline__ void ldm_x2(uint32_t* r, uint32_t addr) {
    asm volatile("ldmatrix.sync.aligned.m8n8.x2.shared.b16 {%0,%1}, [%2];"
        : "=r"(r[0]), "=r"(r[1]) : "r"(addr));
}
__device__ __forceinline__ void ldm_x2_trans(uint32_t* r, uint32_t addr) {
    asm volatile("ldmatrix.sync.aligned.m8n8.x2.trans.shared.b16 {%0,%1}, [%2];"
        : "=r"(r[0]), "=r"(r[1]) : "r"(addr));
}
__device__ __forceinline__ void mma_f16(float* c, const uint32_t* a, const uint32_t* b) {
    asm volatile("mma.sync.aligned.m16n8k16.row.col.f32.f16.f16.f32 "
        "{%0,%1,%2,%3}, {%4,%5,%6,%7}, {%8,%9}, {%0,%1,%2,%3};"
        : "+f"(c[0]), "+f"(c[1]), "+f"(c[2]), "+f"(c[3])
        : "r"(a[0]), "r"(a[1]), "r"(a[2]), "r"(a[3]), "r"(b[0]), "r"(b[1]));
}
__device__ __forceinline__ __half2 split_pair_h(float x, float y, __half2& lo) {
    const __half hx = __float2half_rn(x), hy = __float2half_rn(y);
    lo = __halves2half2(__float2half_rn(x - __half2float(hx)),
                        __float2half_rn(y - __half2float(hy)));
    return __halves2half2(hx, hy);
}

// Tiling: CTA 128x128, BK=32, 8 warps as 2M x 4N (warp tile 64x32)
constexpr int TSTR    = 40;                 // halves per smem row
constexpr int TILE_H  = 128 * TSTR;         // one 128x32 tile (halves)
constexpr int STAGE_H = 3 * TILE_H;         // Ah, Bh, Bl
constexpr int GEMM_SMEM = 2 * STAGE_H * 2;  // 61440 B

// =============================================================================
// stage-1 GEMM: Thi/Tlo = split(relu(A @ W + bias));  A hi-only fp16
// =============================================================================
__global__ __launch_bounds__(256)
void gemm_in(const __half* __restrict__ Ah_g,
             const __half* __restrict__ Bthi, const __half* __restrict__ Btlo,
             const float* __restrict__ bias,
             __half* __restrict__ Chi, __half* __restrict__ Clo,
             int M, int N, int K)
{
    extern __shared__ __half sm[];
    const uint32_t smb = smem_u32(sm);
    const int tid = threadIdx.x, wid = tid >> 5, lane = tid & 31;
    const int bm0 = blockIdx.y * 128, bn0 = blockIdx.x * 128;
    const int nk = K / 32;
    const int mw = (wid & 1) * 64, nw = (wid >> 1) * 32;

    auto load_stage = [&](int kc, int buf) {
        const int kk = kc * 32;
        const __half* a  = Ah_g + (size_t)bm0 * K + kk;
        const __half* bh = Bthi + (size_t)bn0 * K + kk;
        const __half* bl = Btlo + (size_t)bn0 * K + kk;
        const uint32_t base = smb + (uint32_t)buf * STAGE_H * 2;
        #pragma unroll
        for (int i = 0; i < 2; ++i) {
            const int idx = tid + i * 256;
            const int r = idx >> 2, c = (idx & 3) * 8;
            const uint32_t doff = (uint32_t)(r * TSTR + c) * 2;
            cp_async16(base + 0 * TILE_H * 2 + doff, a  + (size_t)r * K + c);
            cp_async16(base + 1 * TILE_H * 2 + doff, bh + (size_t)r * K + c);
            cp_async16(base + 2 * TILE_H * 2 + doff, bl + (size_t)r * K + c);
        }
        cp_commit();
    };

    float acc[4][4][4] = {};
    const int arow = lane & 15, acol = (lane >> 4) * 8;
    const int brow = lane & 7,  bcol = ((lane >> 3) & 1) * 8;

    load_stage(0, 0);
    for (int kc = 0; kc < nk; ++kc) {
        const int buf = kc & 1;
        if (kc + 1 < nk) { load_stage(kc + 1, buf ^ 1); cp_wait<1>(); }
        else             { cp_wait<0>(); }
        __syncthreads();
        const uint32_t base = smb + (uint32_t)buf * STAGE_H * 2;
        #pragma unroll
        for (int ks = 0; ks < 2; ++ks) {
            const int k0 = ks * 16;
            uint32_t ah[4][4];
            #pragma unroll
            for (int mi = 0; mi < 4; ++mi) {
                const uint32_t aoff = (uint32_t)((mw + mi * 16 + arow) * TSTR + k0 + acol) * 2;
                ldm_x4(ah[mi], base + aoff);
            }
            #pragma unroll
            for (int ni = 0; ni < 4; ++ni) {
                const uint32_t boff = (uint32_t)((nw + ni * 8 + brow) * TSTR + k0 + bcol) * 2;
                uint32_t bh[2], bl[2];
                ldm_x2(bh, base + 1 * TILE_H * 2 + boff);
                ldm_x2(bl, base + 2 * TILE_H * 2 + boff);
                #pragma unroll
                for (int mi = 0; mi < 4; ++mi) {
                    mma_f16(acc[mi][ni], ah[mi], bh);
                    mma_f16(acc[mi][ni], ah[mi], bl);
                }
            }
        }
        __syncthreads();
    }

    const int g = lane >> 2, tq = lane & 3;
    #pragma unroll
    for (int mi = 0; mi < 4; ++mi) {
        const int row0 = bm0 + mw + mi * 16 + g;
        #pragma unroll
        for (int ni = 0; ni < 4; ++ni) {
            const int col = bn0 + nw + ni * 8 + tq * 2;
            const float b0 = __ldg(&bias[col]), b1 = __ldg(&bias[col + 1]);
            const float x0 = fmaxf(acc[mi][ni][0] + b0, 0.f);
            const float x1 = fmaxf(acc[mi][ni][1] + b1, 0.f);
            const float x2 = fmaxf(acc[mi][ni][2] + b0, 0.f);
            const float x3 = fmaxf(acc[mi][ni][3] + b1, 0.f);
            __half2 lo01, lo23;
            const __half2 hi01 = split_pair_h(x0, x1, lo01);
            const __half2 hi23 = split_pair_h(x2, x3, lo23);
            *reinterpret_cast<__half2*>(&Chi[(size_t)row0 * N + col]) = hi01;
            *reinterpret_cast<__half2*>(&Clo[(size_t)row0 * N + col]) = lo01;
            *reinterpret_cast<__half2*>(&Chi[(size_t)(row0 + 8) * N + col]) = hi23;
            *reinterpret_cast<__half2*>(&Clo[(size_t)(row0 + 8) * N + col]) = lo23;
        }
    }
}

// =============================================================================
// stage-5 GEMM: C = relu(concat(A0,A1) @ W + bias), fp32 out; A hi-only
// =============================================================================
__global__ __launch_bounds__(256)
void gemm_out(const __half* __restrict__ A0h, const __half* __restrict__ A1h, int K0,
              const __half* __restrict__ Bthi, const __half* __restrict__ Btlo,
              const float* __restrict__ bias, float* __restrict__ C,
              int M, int N, int K)
{
    extern __shared__ __half sm[];
    const uint32_t smb = smem_u32(sm);
    const int tid = threadIdx.x, wid = tid >> 5, lane = tid & 31;
    const int bm0 = blockIdx.y * 128, bn0 = blockIdx.x * 128;
    const int nk = K / 32, K1 = K - K0;
    const int mw = (wid & 1) * 64, nw = (wid >> 1) * 32;

    auto load_stage = [&](int kc, int buf) {
        const int kk = kc * 32;
        const __half* a; int ldA, ka;
        if (kk < K0) { a = A0h; ldA = K0; ka = kk; }
        else         { a = A1h; ldA = K1; ka = kk - K0; }
        a += (size_t)bm0 * ldA + ka;
        const __half* bh = Bthi + (size_t)bn0 * K + kk;
        const __half* bl = Btlo + (size_t)bn0 * K + kk;
        const uint32_t base = smb + (uint32_t)buf * STAGE_H * 2;
        #pragma unroll
        for (int i = 0; i < 2; ++i) {
            const int idx = tid + i * 256;
            const int r = idx >> 2, c = (idx & 3) * 8;
            const uint32_t doff = (uint32_t)(r * TSTR + c) * 2;
            cp_async16(base + 0 * TILE_H * 2 + doff, a  + (size_t)r * ldA + c);
            cp_async16(base + 1 * TILE_H * 2 + doff, bh + (size_t)r * K + c);
            cp_async16(base + 2 * TILE_H * 2 + doff, bl + (size_t)r * K + c);
        }
        cp_commit();
    };

    float acc[4][4][4] = {};
    const int arow = lane & 15, acol = (lane >> 4) * 8;
    const int brow = lane & 7,  bcol = ((lane >> 3) & 1) * 8;

    load_stage(0, 0);
    for (int kc = 0; kc < nk; ++kc) {
        const int buf = kc & 1;
        if (kc + 1 < nk) { load_stage(kc + 1, buf ^ 1); cp_wait<1>(); }
        else             { cp_wait<0>(); }
        __syncthreads();
        const uint32_t base = smb + (uint32_t)buf * STAGE_H * 2;
        #pragma unroll
        for (int ks = 0; ks < 2; ++ks) {
            const int k0 = ks * 16;
            uint32_t ah[4][4];
            #pragma unroll
            for (int mi = 0; mi < 4; ++mi) {
                const uint32_t aoff = (uint32_t)((mw + mi * 16 + arow) * TSTR + k0 + acol) * 2;
                ldm_x4(ah[mi], base + aoff);
            }
            #pragma unroll
            for (int ni = 0; ni < 4; ++ni) {
                const uint32_t boff = (uint32_t)((nw + ni * 8 + brow) * TSTR + k0 + bcol) * 2;
                uint32_t bh[2], bl[2];
                ldm_x2(bh, base + 1 * TILE_H * 2 + boff);
                ldm_x2(bl, base + 2 * TILE_H * 2 + boff);
                #pragma unroll
                for (int mi = 0; mi < 4; ++mi) {
                    mma_f16(acc[mi][ni], ah[mi], bh);
                    mma_f16(acc[mi][ni], ah[mi], bl);
                }
            }
        }
        __syncthreads();
    }

    const int g = lane >> 2, tq = lane & 3;
    #pragma unroll
    for (int mi = 0; mi < 4; ++mi) {
        const int row0 = bm0 + mw + mi * 16 + g;
        #pragma unroll
        for (int ni = 0; ni < 4; ++ni) {
            const int col = bn0 + nw + ni * 8 + tq * 2;
            const float b0 = __ldg(&bias[col]), b1 = __ldg(&bias[col + 1]);
            float2 o0, o1;
            o0.x = fmaxf(acc[mi][ni][0] + b0, 0.f);
            o0.y = fmaxf(acc[mi][ni][1] + b1, 0.f);
            o1.x = fmaxf(acc[mi][ni][2] + b0, 0.f);
            o1.y = fmaxf(acc[mi][ni][3] + b1, 0.f);
            *reinterpret_cast<float2*>(&C[(size_t)row0 * N + col]) = o0;
            *reinterpret_cast<float2*>(&C[(size_t)(row0 + 8) * N + col]) = o1;
        }
    }
}

// =============================================================================
// scores: S[bz,n,m] = scale * sum_k Ta[n,k] Tb[m,k]; A hi-only, B hi+lo
// =============================================================================
__global__ __launch_bounds__(256)
void attn_scores_mma(const __half* __restrict__ Tahi, int offA,
                     const __half* __restrict__ Tbhi, const __half* __restrict__ Tblo,
                     int offB, float* __restrict__ S, float scale)
{
    extern __shared__ __half sm[];
    const uint32_t smb = smem_u32(sm);
    const int tid = threadIdx.x, wid = tid >> 5, lane = tid & 31;
    const int bz = blockIdx.z, b = bz / CH, h = bz % CH;
    const int bm0 = blockIdx.y * 128;   // n
    const int bn0 = blockIdx.x * 128;   // m
    const int mw = (wid & 1) * 64, nw = (wid >> 1) * 32;

    const size_t arow_base = (size_t)(b * CN + bm0) * C3D + offA + h * CHD;
    const size_t brow_base = (size_t)(b * CN + bn0) * C3D + offB + h * CHD;

    auto load_stage = [&](int kc, int buf) {
        const int kk = kc * 32;
        const __half* a  = Tahi + arow_base + kk;
        const __half* bh = Tbhi + brow_base + kk;
        const __half* bl = Tblo + brow_base + kk;
        const uint32_t base = smb + (uint32_t)buf * STAGE_H * 2;
        #pragma unroll
        for (int i = 0; i < 2; ++i) {
            const int idx = tid + i * 256;
            const int r = idx >> 2, c = (idx & 3) * 8;
            const uint32_t doff = (uint32_t)(r * TSTR + c) * 2;
            cp_async16(base + 0 * TILE_H * 2 + doff, a  + (size_t)r * C3D + c);
            cp_async16(base + 1 * TILE_H * 2 + doff, bh + (size_t)r * C3D + c);
            cp_async16(base + 2 * TILE_H * 2 + doff, bl + (size_t)r * C3D + c);
        }
        cp_commit();
    };

    float acc[4][4][4] = {};
    const int arow = lane & 15, acol = (lane >> 4) * 8;
    const int brow = lane & 7,  bcol = ((lane >> 3) & 1) * 8;

    load_stage(0, 0);
    #pragma unroll
    for (int kc = 0; kc < CHD / 32; ++kc) {
        const int buf = kc & 1;
        if (kc + 1 < CHD / 32) { load_stage(kc + 1, buf ^ 1); cp_wait<1>(); }
        else                   { cp_wait<0>(); }
        __syncthreads();
        const uint32_t base = smb + (uint32_t)buf * STAGE_H * 2;
        #pragma unroll
        for (int ks = 0; ks < 2; ++ks) {
            const int k0 = ks * 16;
            uint32_t ah[4][4];
            #pragma unroll
            for (int mi = 0; mi < 4; ++mi) {
                const uint32_t aoff = (uint32_t)((mw + mi * 16 + arow) * TSTR + k0 + acol) * 2;
                ldm_x4(ah[mi], base + aoff);
            }
            #pragma unroll
            for (int ni = 0; ni < 4; ++ni) {
                const uint32_t boff = (uint32_t)((nw + ni * 8 + brow) * TSTR + k0 + bcol) * 2;
                uint32_t bh[2], bl[2];
                ldm_x2(bh, base + 1 * TILE_H * 2 + boff);
                ldm_x2(bl, base + 2 * TILE_H * 2 + boff);
                #pragma unroll
                for (int mi = 0; mi < 4; ++mi) {
                    mma_f16(acc[mi][ni], ah[mi], bh);
                    mma_f16(acc[mi][ni], ah[mi], bl);
                }
            }
        }
        __syncthreads();
    }

    float* Sb = S + (size_t)bz * CN * CN;
    const int g = lane >> 2, tq = lane & 3;
    #pragma unroll
    for (int mi = 0; mi < 4; ++mi) {
        const int row0 = bm0 + mw + mi * 16 + g;
        #pragma unroll
        for (int ni = 0; ni < 4; ++ni) {
            const int col = bn0 + nw + ni * 8 + tq * 2;
            float2 o0, o1;
            o0.x = acc[mi][ni][0] * scale; o0.y = acc[mi][ni][1] * scale;
            o1.x = acc[mi][ni][2] * scale; o1.y = acc[mi][ni][3] * scale;
            *reinterpret_cast<float2*>(&Sb[(size_t)row0 * CN + col]) = o0;
            *reinterpret_cast<float2*>(&Sb[(size_t)(row0 + 8) * CN + col]) = o1;
        }
    }
}

// =============================================================================
// softmax over 512 cols -> P hi (fp16)
// =============================================================================
__global__ __launch_bounds__(256)
void softmax_h(const float* __restrict__ S, __half* __restrict__ Phi)
{
    const size_t roff = (size_t)blockIdx.x * CN;
    const float* p = S + roff;
    const int t = threadIdx.x;
    const float v0 = p[t], v1 = p[t + 256];

    __shared__ float red[256];
    red[t] = fmaxf(v0, v1);
    __syncthreads();
    #pragma unroll
    for (int s = 128; s > 0; s >>= 1) {
        if (t < s) red[t] = fmaxf(red[t], red[t + s]);
        __syncthreads();
    }
    const float mx = red[0];
    __syncthreads();

    const float e0 = __expf(v0 - mx), e1 = __expf(v1 - mx);
    red[t] = e0 + e1;
    __syncthreads();
    #pragma unroll
    for (int s = 128; s > 0; s >>= 1) {
        if (t < s) red[t] += red[t + s];
        __syncthreads();
    }
    const float inv = 1.f / red[0];
    Phi[roff + t]       = __float2half_rn(e0 * inv);
    Phi[roff + t + 256] = __float2half_rn(e1 * inv);
}

// =============================================================================
// AV: U[n,d] = sum_m P[n,m] V[m,d];  P hi-only, V hi+lo;  out U hi fp16
// =============================================================================
constexpr int PSTR  = 40;
constexpr int VSTR  = 136;
constexpr int PT_H  = 128 * PSTR;               // 5120
constexpr int VT_H  = 32 * VSTR;                // 4352
constexpr int AV_STAGE_H = PT_H + 2 * VT_H;     // 13824
constexpr int AV_SMEM = 2 * AV_STAGE_H * 2;     // 55296 B

__global__ __launch_bounds__(256)
void attn_av_mma(const __half* __restrict__ Phi,
                 const __half* __restrict__ Thi, const __half* __restrict__ Tlo,
                 int offV, __half* __restrict__ Uhi)
{
    extern __shared__ __half sm[];
    const uint32_t smb = smem_u32(sm);
    const int tid = threadIdx.x, wid = tid >> 5, lane = tid & 31;
    const int bz = blockIdx.z, b = bz / CH, h = bz % CH;
    const int n0 = blockIdx.y * 128;
    const int mw = (wid & 1) * 64, nw = (wid >> 1) * 32;   // n-offset, d-offset

    const size_t prow_base = ((size_t)bz * CN + n0) * CN;
    const size_t vcol_base = offV + h * CHD;

    auto load_stage = [&](int kc, int buf) {
        const int m0 = kc * 32;
        const uint32_t base = smb + (uint32_t)buf * AV_STAGE_H * 2;
        const __half* ph = Phi + prow_base + m0;
        const __half* vh = Thi + (size_t)(b * CN + m0) * C3D + vcol_base;
        const __half* vl = Tlo + (size_t)(b * CN + m0) * C3D + vcol_base;
        #pragma unroll
        for (int i = 0; i < 2; ++i) {
            const int idx = tid + i * 256;
            const int r = idx >> 2, c = (idx & 3) * 8;
            const uint32_t doff = (uint32_t)(r * PSTR + c) * 2;
            cp_async16(base + doff, ph + (size_t)r * CN + c);
        }
        #pragma unroll
        for (int i = 0; i < 2; ++i) {
            const int idx = tid + i * 256;
            const int r = idx >> 4, c = (idx & 15) * 8;
            const uint32_t doff = (uint32_t)(r * VSTR + c) * 2;
            cp_async16(base + PT_H * 2 + doff,            vh + (size_t)r * C3D + c);
            cp_async16(base + (PT_H + VT_H) * 2 + doff,   vl + (size_t)r * C3D + c);
        }
        cp_commit();
    };

    float acc[4][4][4] = {};
    const int arow = lane & 15, acol = (lane >> 4) * 8;
    const int vrow = lane & 15;

    load_stage(0, 0);
    #pragma unroll 1
    for (int kc = 0; kc < CN / 32; ++kc) {
        const int buf = kc & 1;
        if (kc + 1 < CN / 32) { load_stage(kc + 1, buf ^ 1); cp_wait<1>(); }
        else                  { cp_wait<0>(); }
        __syncthreads();
        const uint32_t base = smb + (uint32_t)buf * AV_STAGE_H * 2;
        #pragma unroll
        for (int ks = 0; ks < 2; ++ks) {
            const int k0 = ks * 16;
            uint32_t ph[4][4];
            #pragma unroll
            for (int mi = 0; mi < 4; ++mi) {
                const uint32_t aoff = (uint32_t)((mw + mi * 16 + arow) * PSTR + k0 + acol) * 2;
                ldm_x4(ph[mi], base + aoff);
            }
            #pragma unroll
            for (int ni = 0; ni < 4; ++ni) {
                const uint32_t boff = (uint32_t)((k0 + vrow) * VSTR + nw + ni * 8) * 2;
                uint32_t vh[2], vl[2];
                ldm_x2_trans(vh, base + PT_H * 2 + boff);
                ldm_x2_trans(vl, base + (PT_H + VT_H) * 2 + boff);
                #pragma unroll
                for (int mi = 0; mi < 4; ++mi) {
                    mma_f16(acc[mi][ni], ph[mi], vh);
                    mma_f16(acc[mi][ni], ph[mi], vl);
                }
            }
        }
        __syncthreads();
    }

    const int g = lane >> 2, tq = lane & 3;
    #pragma unroll
    for (int mi = 0; mi < 4; ++mi) {
        const int row0 = n0 + mw + mi * 16 + g;
        #pragma unroll
        for (int ni = 0; ni < 4; ++ni) {
            const int col = h * CHD + nw + ni * 8 + tq * 2;
            const size_t o0 = (size_t)(b * CN + row0) * CD + col;
            const size_t o1 = (size_t)(b * CN + row0 + 8) * CD + col;
            *reinterpret_cast<__half2*>(&Uhi[o0]) =
                __halves2half2(__float2half_rn(acc[mi][ni][0]), __float2half_rn(acc[mi][ni][1]));
            *reinterpret_cast<__half2*>(&Uhi[o1]) =
                __halves2half2(__float2half_rn(acc[mi][ni][2]), __float2half_rn(acc[mi][ni][3]));
        }
    }
}

// =============================================================================
// precompute kernels
// =============================================================================
__global__ __launch_bounds__(256)
void to_half(const float* __restrict__ x, __half* __restrict__ hi, size_t n)
{
    const size_t stride = (size_t)gridDim.x * blockDim.x * 4;
    for (size_t i = ((size_t)blockIdx.x * blockDim.x + threadIdx.x) * 4; i < n; i += stride) {
        float4 v = *reinterpret_cast<const float4*>(x + i);
        *reinterpret_cast<__half2*>(hi + i) =
            __halves2half2(__float2half_rn(v.x), __float2half_rn(v.y));
        *reinterpret_cast<__half2*>(hi + i + 2) =
            __halves2half2(__float2half_rn(v.z), __float2half_rn(v.w));
    }
}

__global__ __launch_bounds__(256)
void transpose_split(const float* __restrict__ W, __half* __restrict__ thi,
                     __half* __restrict__ tlo, int K, int N)
{
    __shared__ float t[32][33];
    const int k0 = blockIdx.y * 32, n0 = blockIdx.x * 32;
    const int tx = threadIdx.x, ty = threadIdx.y;
    for (int i = ty; i < 32; i += 8)
        t[i][tx] = W[(size_t)(k0 + i) * N + n0 + tx];
    __syncthreads();
    for (int i = ty; i < 32; i += 8) {
        const float x = t[tx][i];
        const __half h = __float2half_rn(x);
        thi[(size_t)(n0 + i) * K + k0 + tx] = h;
        tlo[(size_t)(n0 + i) * K + k0 + tx] = __float2half_rn(x - __half2float(h));
    }
}

// =============================================================================
// launch
// =============================================================================
extern "C" void kernel_launch(void* const* d_in, const int* in_sizes, int n_in,
                              void* d_out, int out_size)
{
    const float* v   = (const float*)d_in[0];
    const float* q   = (const float*)d_in[1];
    const float* Wv  = (const float*)d_in[2];
    const float* bv  = (const float*)d_in[3];
    const float* Wq  = (const float*)d_in[4];
    const float* bq  = (const float*)d_in[5];
    const float* Wvo = (const float*)d_in[6];
    const float* bvo = (const float*)d_in[7];
    const float* Wqo = (const float*)d_in[8];
    const float* bqo = (const float*)d_in[9];
    float* out = (float*)d_out;

    float *s1, *s2;
    cudaGetSymbolAddress((void**)&s1, g_s1);
    cudaGetSymbolAddress((void**)&s2, g_s2);
    __half *vthi, *vtlo, *qthi, *qtlo, *p1hi, *p2hi;
    cudaGetSymbolAddress((void**)&vthi, g_vthi); cudaGetSymbolAddress((void**)&vtlo, g_vtlo);
    cudaGetSymbolAddress((void**)&qthi, g_qthi); cudaGetSymbolAddress((void**)&qtlo, g_qtlo);
    cudaGetSymbolAddress((void**)&p1hi, g_p1hi); cudaGetSymbolAddress((void**)&p2hi, g_p2hi);
    __half *vhi, *qhi, *vuhi, *quhi;
    cudaGetSymbolAddress((void**)&vhi, g_vhi);   cudaGetSymbolAddress((void**)&qhi, g_qhi);
    cudaGetSymbolAddress((void**)&vuhi, g_vuhi); cudaGetSymbolAddress((void**)&quhi, g_quhi);
    __half *Wvth, *Wvtl, *Wqth, *Wqtl, *Wvoth, *Wvotl, *Wqoth, *Wqotl;
    cudaGetSymbolAddress((void**)&Wvth, g_Wvt_hi);   cudaGetSymbolAddress((void**)&Wvtl, g_Wvt_lo);
    cudaGetSymbolAddress((void**)&Wqth, g_Wqt_hi);   cudaGetSymbolAddress((void**)&Wqtl, g_Wqt_lo);
    cudaGetSymbolAddress((void**)&Wvoth, g_Wvot_hi); cudaGetSymbolAddress((void**)&Wvotl, g_Wvot_lo);
    cudaGetSymbolAddress((void**)&Wqoth, g_Wqot_hi); cudaGetSymbolAddress((void**)&Wqotl, g_Wqot_lo);

    cudaFuncSetAttribute(gemm_in,  cudaFuncAttributeMaxDynamicSharedMemorySize, GEMM_SMEM);
    cudaFuncSetAttribute(gemm_out, cudaFuncAttributeMaxDynamicSharedMemorySize, GEMM_SMEM);
    cudaFuncSetAttribute(attn_scores_mma, cudaFuncAttributeMaxDynamicSharedMemorySize, GEMM_SMEM);
    cudaFuncSetAttribute(attn_av_mma, cudaFuncAttributeMaxDynamicSharedMemorySize, AV_SMEM);

    const dim3 t256(256);
    const float scale = 0.08838834764831845f;   // 1/sqrt(128)
    const size_t nVD = (size_t)CM * CD;

    // 0) fp16 copies of inputs; transpose+split weights
    to_half<<<2048, t256>>>(v, vhi, nVD);
    to_half<<<2048, t256>>>(q, qhi, nVD);
    transpose_split<<<dim3(C3D / 32, CD / 32), dim3(32, 8)>>>(Wv, Wvth, Wvtl, CD, C3D);
    transpose_split<<<dim3(C3D / 32, CD / 32), dim3(32, 8)>>>(Wq, Wqth, Wqtl, CD, C3D);
    transpose_split<<<dim3(CD / 32, 2 * CD / 32), dim3(32, 8)>>>(Wvo, Wvoth, Wvotl, 2 * CD, CD);
    transpose_split<<<dim3(CD / 32, 2 * CD / 32), dim3(32, 8)>>>(Wqo, Wqoth, Wqotl, 2 * CD, CD);

    // 1) input transforms -> fp16 hi/lo
    gemm_in<<<dim3(C3D / 128, CM / 128), t256, GEMM_SMEM>>>(
        vhi, Wvth, Wvtl, bv, vthi, vtlo, CM, C3D, CD);
    gemm_in<<<dim3(C3D / 128, CM / 128), t256, GEMM_SMEM>>>(
        qhi, Wqth, Wqtl, bq, qthi, qtlo, CM, C3D, CD);

    // 2) scores: q2v = vq . qk^T ; v2q = qq . vk^T
    attn_scores_mma<<<dim3(4, 4, CB * CH), t256, GEMM_SMEM>>>(
        vthi, CD, qthi, qtlo, 0, s1, scale);
    attn_scores_mma<<<dim3(4, 4, CB * CH), t256, GEMM_SMEM>>>(
        qthi, CD, vthi, vtlo, 0, s2, scale);

    // 3) softmax -> fp16 P
    softmax_h<<<CB * CH * CN, 256>>>(s1, p1hi);
    softmax_h<<<CB * CH * CN, 256>>>(s2, p2hi);

    // 4) AV: v_update = A_q2v @ qv ; q_update = A_v2q @ vv
    attn_av_mma<<<dim3(1, 4, CB * CH), t256, AV_SMEM>>>(
        p1hi, qthi, qtlo, 2 * CD, vuhi);
    attn_av_mma<<<dim3(1, 4, CB * CH), t256, AV_SMEM>>>(
        p2hi, vthi, vtlo, 2 * CD, quhi);

    // 5) output transforms (virtual concat)
    const size_t half = (size_t)CM * CD;
    gemm_out<<<dim3(CD / 128, CM / 128), t256, GEMM_SMEM>>>(
        vhi, vuhi, CD, Wvoth, Wvotl, bvo, out, CM, CD, 2 * CD);
    gemm_out<<<dim3(CD / 128, CM / 128), t256, GEMM_SMEM>>>(
        qhi, quhi, CD, Wqoth, Wqotl, bqo, out + half, CM, CD, 2 * CD);
}

// round 7
// speedup vs baseline: 4.3231x; 1.2418x over previous
#include <cuda_runtime.h>
#include <cuda_fp16.h>
#include <cstdint>
#include <math.h>

// Problem constants
constexpr int CB  = 32;
constexpr int CN  = 512;
constexpr int CD  = 1024;
constexpr int CH  = 8;
constexpr int CHD = 128;
constexpr int C3D = 3 * CD;
constexpr int CM  = CB * CN;   // 16384

// ---------------- scratch (device globals) ----------------------------------
__device__ __half g_vthi[(size_t)CM * C3D], g_vtlo[(size_t)CM * C3D];
__device__ __half g_qthi[(size_t)CM * C3D], g_qtlo[(size_t)CM * C3D];
__device__ __half g_vhi[(size_t)CM * CD],  g_qhi[(size_t)CM * CD];
__device__ __half g_vuhi[(size_t)CM * CD], g_quhi[(size_t)CM * CD];
__device__ __half g_Wvt_hi[(size_t)C3D * CD],     g_Wvt_lo[(size_t)C3D * CD];
__device__ __half g_Wqt_hi[(size_t)C3D * CD],     g_Wqt_lo[(size_t)C3D * CD];
__device__ __half g_Wvot_hi[(size_t)CD * 2 * CD], g_Wvot_lo[(size_t)CD * 2 * CD];
__device__ __half g_Wqot_hi[(size_t)CD * 2 * CD], g_Wqot_lo[(size_t)CD * 2 * CD];

// ---------------- base-ISA PTX helpers ---------------------------------------
__device__ __forceinline__ uint32_t smem_u32(const void* p) {
    uint32_t a;
    asm("{ .reg .u64 t; cvta.to.shared.u64 t, %1; cvt.u32.u64 %0, t; }" : "=r"(a) : "l"(p));
    return a;
}
__device__ __forceinline__ void cp_async16(uint32_t dst, const void* src) {
    asm volatile("cp.async.cg.shared.global [%0], [%1], 16;" :: "r"(dst), "l"(src) : "memory");
}
__device__ __forceinline__ void cp_commit() { asm volatile("cp.async.commit_group;" ::: "memory"); }
template <int N>
__device__ __forceinline__ void cp_wait() { asm volatile("cp.async.wait_group %0;" :: "n"(N) : "memory"); }

__device__ __forceinline__ void ldm_x4(uint32_t* r, uint32_t addr) {
    asm volatile("ldmatrix.sync.aligned.m8n8.x4.shared.b16 {%0,%1,%2,%3}, [%4];"
        : "=r"(r[0]), "=r"(r[1]), "=r"(r[2]), "=r"(r[3]) : "r"(addr));
}
__device__ __forceinline__ void ldm_x2(uint32_t* r, uint32_t addr) {
    asm volatile("ldmatrix.sync.aligned.m8n8.x2.shared.b16 {%0,%1}, [%2];"
        : "=r"(r[0]), "=r"(r[1]) : "r"(addr));
}
__device__ __forceinline__ void ldm_x2_trans(uint32_t* r, uint32_t addr) {
    asm volatile("ldmatrix.sync.aligned.m8n8.x2.trans.shared.b16 {%0,%1}, [%2];"
        : "=r"(r[0]), "=r"(r[1]) : "r"(addr));
}
__device__ __forceinline__ void mma_f16(float* c, const uint32_t* a, const uint32_t* b) {
    asm volatile("mma.sync.aligned.m16n8k16.row.col.f32.f16.f16.f32 "
        "{%0,%1,%2,%3}, {%4,%5,%6,%7}, {%8,%9}, {%0,%1,%2,%3};"
        : "+f"(c[0]), "+f"(c[1]), "+f"(c[2]), "+f"(c[3])
        : "r"(a[0]), "r"(a[1]), "r"(a[2]), "r"(a[3]), "r"(b[0]), "r"(b[1]));
}
__device__ __forceinline__ __half2 split_pair_h(float x, float y, __half2& lo) {
    const __half hx = __float2half_rn(x), hy = __float2half_rn(y);
    lo = __halves2half2(__float2half_rn(x - __half2float(hx)),
                        __float2half_rn(y - __half2float(hy)));
    return __halves2half2(hx, hy);
}

// Weight-GEMM tiling: CTA 128x128, BK=32, 8 warps 2Mx4N, 3-stage pipeline
constexpr int TSTR    = 40;
constexpr int TILE_H  = 128 * TSTR;
constexpr int STAGE_H = 3 * TILE_H;          // Ah, Bh, Bl
constexpr int GEMM_SMEM = 3 * STAGE_H * 2;   // 92160 B

// =============================================================================
// stage-1 GEMM: Thi/Tlo = split(relu(A @ W + bias));  A hi-only fp16
// =============================================================================
__global__ __launch_bounds__(256)
void gemm_in(const __half* __restrict__ Ah_g,
             const __half* __restrict__ Bthi, const __half* __restrict__ Btlo,
             const float* __restrict__ bias,
             __half* __restrict__ Chi, __half* __restrict__ Clo,
             int M, int N, int K)
{
    extern __shared__ __half sm[];
    const uint32_t smb = smem_u32(sm);
    const int tid = threadIdx.x, wid = tid >> 5, lane = tid & 31;
    const int bm0 = blockIdx.y * 128, bn0 = blockIdx.x * 128;
    const int nk = K / 32;
    const int mw = (wid & 1) * 64, nw = (wid >> 1) * 32;

    auto load_stage = [&](int kc, int buf) {
        const int kk = kc * 32;
        const __half* a  = Ah_g + (size_t)bm0 * K + kk;
        const __half* bh = Bthi + (size_t)bn0 * K + kk;
        const __half* bl = Btlo + (size_t)bn0 * K + kk;
        const uint32_t base = smb + (uint32_t)buf * STAGE_H * 2;
        #pragma unroll
        for (int i = 0; i < 2; ++i) {
            const int idx = tid + i * 256;
            const int r = idx >> 2, c = (idx & 3) * 8;
            const uint32_t doff = (uint32_t)(r * TSTR + c) * 2;
            cp_async16(base + 0 * TILE_H * 2 + doff, a  + (size_t)r * K + c);
            cp_async16(base + 1 * TILE_H * 2 + doff, bh + (size_t)r * K + c);
            cp_async16(base + 2 * TILE_H * 2 + doff, bl + (size_t)r * K + c);
        }
        cp_commit();
    };

    float acc[4][4][4] = {};
    const int arow = lane & 15, acol = (lane >> 4) * 8;
    const int brow = lane & 7,  bcol = ((lane >> 3) & 1) * 8;

    load_stage(0, 0);
    load_stage(1, 1);
    for (int kc = 0; kc < nk; ++kc) {
        const int buf = kc % 3;
        if (kc + 1 < nk) cp_wait<1>(); else cp_wait<0>();
        __syncthreads();
        if (kc + 2 < nk) load_stage(kc + 2, (kc + 2) % 3);
        const uint32_t base = smb + (uint32_t)buf * STAGE_H * 2;
        #pragma unroll
        for (int ks = 0; ks < 2; ++ks) {
            const int k0 = ks * 16;
            uint32_t ah[4][4];
            #pragma unroll
            for (int mi = 0; mi < 4; ++mi) {
                const uint32_t aoff = (uint32_t)((mw + mi * 16 + arow) * TSTR + k0 + acol) * 2;
                ldm_x4(ah[mi], base + aoff);
            }
            #pragma unroll
            for (int ni = 0; ni < 4; ++ni) {
                const uint32_t boff = (uint32_t)((nw + ni * 8 + brow) * TSTR + k0 + bcol) * 2;
                uint32_t bh[2], bl[2];
                ldm_x2(bh, base + 1 * TILE_H * 2 + boff);
                ldm_x2(bl, base + 2 * TILE_H * 2 + boff);
                #pragma unroll
                for (int mi = 0; mi < 4; ++mi) {
                    mma_f16(acc[mi][ni], ah[mi], bh);
                    mma_f16(acc[mi][ni], ah[mi], bl);
                }
            }
        }
    }

    const int g = lane >> 2, tq = lane & 3;
    #pragma unroll
    for (int mi = 0; mi < 4; ++mi) {
        const int row0 = bm0 + mw + mi * 16 + g;
        #pragma unroll
        for (int ni = 0; ni < 4; ++ni) {
            const int col = bn0 + nw + ni * 8 + tq * 2;
            const float b0 = __ldg(&bias[col]), b1 = __ldg(&bias[col + 1]);
            const float x0 = fmaxf(acc[mi][ni][0] + b0, 0.f);
            const float x1 = fmaxf(acc[mi][ni][1] + b1, 0.f);
            const float x2 = fmaxf(acc[mi][ni][2] + b0, 0.f);
            const float x3 = fmaxf(acc[mi][ni][3] + b1, 0.f);
            __half2 lo01, lo23;
            const __half2 hi01 = split_pair_h(x0, x1, lo01);
            const __half2 hi23 = split_pair_h(x2, x3, lo23);
            *reinterpret_cast<__half2*>(&Chi[(size_t)row0 * N + col]) = hi01;
            *reinterpret_cast<__half2*>(&Clo[(size_t)row0 * N + col]) = lo01;
            *reinterpret_cast<__half2*>(&Chi[(size_t)(row0 + 8) * N + col]) = hi23;
            *reinterpret_cast<__half2*>(&Clo[(size_t)(row0 + 8) * N + col]) = lo23;
        }
    }
}

// =============================================================================
// stage-5 GEMM: C = relu(concat(A0,A1) @ W + bias), fp32 out; A hi-only
// =============================================================================
__global__ __launch_bounds__(256)
void gemm_out(const __half* __restrict__ A0h, const __half* __restrict__ A1h, int K0,
              const __half* __restrict__ Bthi, const __half* __restrict__ Btlo,
              const float* __restrict__ bias, float* __restrict__ C,
              int M, int N, int K)
{
    extern __shared__ __half sm[];
    const uint32_t smb = smem_u32(sm);
    const int tid = threadIdx.x, wid = tid >> 5, lane = tid & 31;
    const int bm0 = blockIdx.y * 128, bn0 = blockIdx.x * 128;
    const int nk = K / 32, K1 = K - K0;
    const int mw = (wid & 1) * 64, nw = (wid >> 1) * 32;

    auto load_stage = [&](int kc, int buf) {
        const int kk = kc * 32;
        const __half* a; int ldA, ka;
        if (kk < K0) { a = A0h; ldA = K0; ka = kk; }
        else         { a = A1h; ldA = K1; ka = kk - K0; }
        a += (size_t)bm0 * ldA + ka;
        const __half* bh = Bthi + (size_t)bn0 * K + kk;
        const __half* bl = Btlo + (size_t)bn0 * K + kk;
        const uint32_t base = smb + (uint32_t)buf * STAGE_H * 2;
        #pragma unroll
        for (int i = 0; i < 2; ++i) {
            const int idx = tid + i * 256;
            const int r = idx >> 2, c = (idx & 3) * 8;
            const uint32_t doff = (uint32_t)(r * TSTR + c) * 2;
            cp_async16(base + 0 * TILE_H * 2 + doff, a  + (size_t)r * ldA + c);
            cp_async16(base + 1 * TILE_H * 2 + doff, bh + (size_t)r * K + c);
            cp_async16(base + 2 * TILE_H * 2 + doff, bl + (size_t)r * K + c);
        }
        cp_commit();
    };

    float acc[4][4][4] = {};
    const int arow = lane & 15, acol = (lane >> 4) * 8;
    const int brow = lane & 7,  bcol = ((lane >> 3) & 1) * 8;

    load_stage(0, 0);
    load_stage(1, 1);
    for (int kc = 0; kc < nk; ++kc) {
        const int buf = kc % 3;
        if (kc + 1 < nk) cp_wait<1>(); else cp_wait<0>();
        __syncthreads();
        if (kc + 2 < nk) load_stage(kc + 2, (kc + 2) % 3);
        const uint32_t base = smb + (uint32_t)buf * STAGE_H * 2;
        #pragma unroll
        for (int ks = 0; ks < 2; ++ks) {
            const int k0 = ks * 16;
            uint32_t ah[4][4];
            #pragma unroll
            for (int mi = 0; mi < 4; ++mi) {
                const uint32_t aoff = (uint32_t)((mw + mi * 16 + arow) * TSTR + k0 + acol) * 2;
                ldm_x4(ah[mi], base + aoff);
            }
            #pragma unroll
            for (int ni = 0; ni < 4; ++ni) {
                const uint32_t boff = (uint32_t)((nw + ni * 8 + brow) * TSTR + k0 + bcol) * 2;
                uint32_t bh[2], bl[2];
                ldm_x2(bh, base + 1 * TILE_H * 2 + boff);
                ldm_x2(bl, base + 2 * TILE_H * 2 + boff);
                #pragma unroll
                for (int mi = 0; mi < 4; ++mi) {
                    mma_f16(acc[mi][ni], ah[mi], bh);
                    mma_f16(acc[mi][ni], ah[mi], bl);
                }
            }
        }
    }

    const int g = lane >> 2, tq = lane & 3;
    #pragma unroll
    for (int mi = 0; mi < 4; ++mi) {
        const int row0 = bm0 + mw + mi * 16 + g;
        #pragma unroll
        for (int ni = 0; ni < 4; ++ni) {
            const int col = bn0 + nw + ni * 8 + tq * 2;
            const float b0 = __ldg(&bias[col]), b1 = __ldg(&bias[col + 1]);
            float2 o0, o1;
            o0.x = fmaxf(acc[mi][ni][0] + b0, 0.f);
            o0.y = fmaxf(acc[mi][ni][1] + b1, 0.f);
            o1.x = fmaxf(acc[mi][ni][2] + b0, 0.f);
            o1.y = fmaxf(acc[mi][ni][3] + b1, 0.f);
            *reinterpret_cast<float2*>(&C[(size_t)row0 * N + col]) = o0;
            *reinterpret_cast<float2*>(&C[(size_t)(row0 + 8) * N + col]) = o1;
        }
    }
}

// =============================================================================
// Fused flash attention: U = softmax(Q K^T * scale) V
// Q = Ta[:, CD + h*HD : +128] (hi only); K = Tb[:, h*HD] hi+lo;
// V = Tb[:, 2CD + h*HD] hi+lo. Output U fp16 at [b*CN+n][h*HD+d].
// CTA: 128 q-rows (8 warps x 16 rows), m-chunks of 64, double-buffered KV.
// =============================================================================
constexpr int QSTR = 136;
constexpr int KSTR = 136;
constexpr int Q_HLV = 128 * QSTR;          // 17408 halves
constexpr int KV_TILE = 64 * KSTR;         // 8704 halves
constexpr int KV_STAGE = 4 * KV_TILE;      // Khi,Klo,Vhi,Vlo
constexpr int ATT_SMEM = (Q_HLV + 2 * KV_STAGE) * 2;   // 174080 B

__global__ __launch_bounds__(256, 1)
void fused_attn(const __half* __restrict__ Tahi,
                const __half* __restrict__ Tbhi, const __half* __restrict__ Tblo,
                __half* __restrict__ U, float scale)
{
    extern __shared__ __half sm[];
    const uint32_t smb = smem_u32(sm);
    const int tid = threadIdx.x, wid = tid >> 5, lane = tid & 31;
    const int bz = blockIdx.y, b = bz >> 3, h = bz & 7;
    const int n0 = blockIdx.x * 128;
    const int wrow = wid * 16;

    const size_t qbase = (size_t)(b * CN + n0) * C3D + CD + h * CHD;
    const size_t kbase = (size_t)b * CN * C3D + h * CHD;           // + m*C3D
    const size_t vbase = (size_t)b * CN * C3D + 2 * CD + h * CHD;

    // Q tile: 128 rows x 128 halves = 2048 16B-chunks
    auto load_q = [&]() {
        #pragma unroll
        for (int i = 0; i < 8; ++i) {
            const int idx = tid + i * 256;
            const int r = idx >> 4, c = (idx & 15) * 8;
            cp_async16(smb + (uint32_t)(r * QSTR + c) * 2,
                       Tahi + qbase + (size_t)r * C3D + c);
        }
        cp_commit();
    };
    // K/V tiles: 4 tiles of 64 rows x 128 halves = 1024 chunks each
    auto load_kv = [&](int mc, int buf) {
        const int m0 = mc * 64;
        const uint32_t base = smb + (uint32_t)(Q_HLV + buf * KV_STAGE) * 2;
        const __half* kh = Tbhi + kbase + (size_t)m0 * C3D;
        const __half* kl = Tblo + kbase + (size_t)m0 * C3D;
        const __half* vh = Tbhi + vbase + (size_t)m0 * C3D;
        const __half* vl = Tblo + vbase + (size_t)m0 * C3D;
        #pragma unroll
        for (int i = 0; i < 4; ++i) {
            const int idx = tid + i * 256;
            const int r = idx >> 4, c = (idx & 15) * 8;
            const uint32_t doff = (uint32_t)(r * KSTR + c) * 2;
            cp_async16(base + 0 * KV_TILE * 2 + doff, kh + (size_t)r * C3D + c);
            cp_async16(base + 1 * KV_TILE * 2 + doff, kl + (size_t)r * C3D + c);
            cp_async16(base + 2 * KV_TILE * 2 + doff, vh + (size_t)r * C3D + c);
            cp_async16(base + 3 * KV_TILE * 2 + doff, vl + (size_t)r * C3D + c);
        }
        cp_commit();
    };

    load_q();
    load_kv(0, 0);
    cp_wait<1>();              // Q ready (kv0 may still be in flight)
    __syncthreads();

    // Q A-frags: 16 rows x 128 k, 8 k16-frags
    const int arow = lane & 15, acol = (lane >> 4) * 8;
    uint32_t qf[8][4];
    #pragma unroll
    for (int kf = 0; kf < 8; ++kf)
        ldm_x4(qf[kf], smb + (uint32_t)((wrow + arow) * QSTR + kf * 16 + acol) * 2);

    const int g = lane >> 2, tq = lane & 3;
    const int brow = lane & 7, bcol = ((lane >> 3) & 1) * 8;
    const int vrow = lane & 15;

    float m0s = -1e30f, m1s = -1e30f, l0s = 0.f, l1s = 0.f;
    float o[16][4] = {};

    for (int mc = 0; mc < 8; ++mc) {
        const int buf = mc & 1;
        if (mc + 1 < 8) { load_kv(mc + 1, buf ^ 1); cp_wait<1>(); }
        else            { cp_wait<0>(); }
        __syncthreads();

        const uint32_t base = smb + (uint32_t)(Q_HLV + buf * KV_STAGE) * 2;

        // ---- S = Q K^T (64 cols), 2-term on K ----
        float s[8][4] = {};
        #pragma unroll
        for (int kf = 0; kf < 8; ++kf) {
            #pragma unroll
            for (int nf = 0; nf < 8; ++nf) {
                const uint32_t boff = (uint32_t)((nf * 8 + brow) * KSTR + kf * 16 + bcol) * 2;
                uint32_t kh2[2], kl2[2];
                ldm_x2(kh2, base + 0 * KV_TILE * 2 + boff);
                ldm_x2(kl2, base + 1 * KV_TILE * 2 + boff);
                mma_f16(s[nf], qf[kf], kh2);
                mma_f16(s[nf], qf[kf], kl2);
            }
        }

        // ---- online softmax (rows g, g+8 of this warp) ----
        float mx0 = -1e30f, mx1 = -1e30f;
        #pragma unroll
        for (int nf = 0; nf < 8; ++nf) {
            mx0 = fmaxf(mx0, fmaxf(s[nf][0], s[nf][1]));
            mx1 = fmaxf(mx1, fmaxf(s[nf][2], s[nf][3]));
        }
        mx0 = fmaxf(mx0, __shfl_xor_sync(0xffffffffu, mx0, 1));
        mx0 = fmaxf(mx0, __shfl_xor_sync(0xffffffffu, mx0, 2));
        mx1 = fmaxf(mx1, __shfl_xor_sync(0xffffffffu, mx1, 1));
        mx1 = fmaxf(mx1, __shfl_xor_sync(0xffffffffu, mx1, 2));
        mx0 *= scale; mx1 *= scale;
        const float mn0 = fmaxf(m0s, mx0), mn1 = fmaxf(m1s, mx1);
        const float a0 = __expf(m0s - mn0), a1 = __expf(m1s - mn1);
        m0s = mn0; m1s = mn1;

        float rs0 = 0.f, rs1 = 0.f;
        __half2 pf[8][2];
        #pragma unroll
        for (int nf = 0; nf < 8; ++nf) {
            const float p0 = __expf(s[nf][0] * scale - mn0);
            const float p1 = __expf(s[nf][1] * scale - mn0);
            const float p2 = __expf(s[nf][2] * scale - mn1);
            const float p3 = __expf(s[nf][3] * scale - mn1);
            rs0 += p0 + p1; rs1 += p2 + p3;
            pf[nf][0] = __halves2half2(__float2half_rn(p0), __float2half_rn(p1));
            pf[nf][1] = __halves2half2(__float2half_rn(p2), __float2half_rn(p3));
        }
        rs0 += __shfl_xor_sync(0xffffffffu, rs0, 1);
        rs0 += __shfl_xor_sync(0xffffffffu, rs0, 2);
        rs1 += __shfl_xor_sync(0xffffffffu, rs1, 1);
        rs1 += __shfl_xor_sync(0xffffffffu, rs1, 2);
        l0s = l0s * a0 + rs0;
        l1s = l1s * a1 + rs1;

        #pragma unroll
        for (int nf2 = 0; nf2 < 16; ++nf2) {
            o[nf2][0] *= a0; o[nf2][1] *= a0;
            o[nf2][2] *= a1; o[nf2][3] *= a1;
        }

        // ---- O += P V (2-term on V), P as in-register A-frags ----
        #pragma unroll
        for (int kf2 = 0; kf2 < 4; ++kf2) {
            uint32_t pa[4];
            pa[0] = *reinterpret_cast<uint32_t*>(&pf[2 * kf2][0]);
            pa[1] = *reinterpret_cast<uint32_t*>(&pf[2 * kf2][1]);
            pa[2] = *reinterpret_cast<uint32_t*>(&pf[2 * kf2 + 1][0]);
            pa[3] = *reinterpret_cast<uint32_t*>(&pf[2 * kf2 + 1][1]);
            #pragma unroll
            for (int nf2 = 0; nf2 < 16; ++nf2) {
                const uint32_t boff = (uint32_t)((kf2 * 16 + vrow) * KSTR + nf2 * 8) * 2;
                uint32_t vh2[2], vl2[2];
                ldm_x2_trans(vh2, base + 2 * KV_TILE * 2 + boff);
                ldm_x2_trans(vl2, base + 3 * KV_TILE * 2 + boff);
                mma_f16(o[nf2], pa, vh2);
                mma_f16(o[nf2], pa, vl2);
            }
        }
        __syncthreads();
    }

    // ---- epilogue: O /= l, write fp16 ----
    const float inv0 = 1.f / l0s, inv1 = 1.f / l1s;
    const int row0 = n0 + wrow + g;
    #pragma unroll
    for (int nf2 = 0; nf2 < 16; ++nf2) {
        const int col = h * CHD + nf2 * 8 + tq * 2;
        const size_t off0 = (size_t)(b * CN + row0) * CD + col;
        const size_t off1 = (size_t)(b * CN + row0 + 8) * CD + col;
        *reinterpret_cast<__half2*>(&U[off0]) =
            __halves2half2(__float2half_rn(o[nf2][0] * inv0), __float2half_rn(o[nf2][1] * inv0));
        *reinterpret_cast<__half2*>(&U[off1]) =
            __halves2half2(__float2half_rn(o[nf2][2] * inv1), __float2half_rn(o[nf2][3] * inv1));
    }
}

// =============================================================================
// precompute kernels
// =============================================================================
__global__ __launch_bounds__(256)
void to_half(const float* __restrict__ x, __half* __restrict__ hi, size_t n)
{
    const size_t stride = (size_t)gridDim.x * blockDim.x * 4;
    for (size_t i = ((size_t)blockIdx.x * blockDim.x + threadIdx.x) * 4; i < n; i += stride) {
        float4 v = *reinterpret_cast<const float4*>(x + i);
        *reinterpret_cast<__half2*>(hi + i) =
            __halves2half2(__float2half_rn(v.x), __float2half_rn(v.y));
        *reinterpret_cast<__half2*>(hi + i + 2) =
            __halves2half2(__float2half_rn(v.z), __float2half_rn(v.w));
    }
}

__global__ __launch_bounds__(256)
void transpose_split(const float* __restrict__ W, __half* __restrict__ thi,
                     __half* __restrict__ tlo, int K, int N)
{
    __shared__ float t[32][33];
    const int k0 = blockIdx.y * 32, n0 = blockIdx.x * 32;
    const int tx = threadIdx.x, ty = threadIdx.y;
    for (int i = ty; i < 32; i += 8)
        t[i][tx] = W[(size_t)(k0 + i) * N + n0 + tx];
    __syncthreads();
    for (int i = ty; i < 32; i += 8) {
        const float x = t[tx][i];
        const __half h = __float2half_rn(x);
        thi[(size_t)(n0 + i) * K + k0 + tx] = h;
        tlo[(size_t)(n0 + i) * K + k0 + tx] = __float2half_rn(x - __half2float(h));
    }
}

// =============================================================================
// launch
// =============================================================================
extern "C" void kernel_launch(void* const* d_in, const int* in_sizes, int n_in,
                              void* d_out, int out_size)
{
    const float* v   = (const float*)d_in[0];
    const float* q   = (const float*)d_in[1];
    const float* Wv  = (const float*)d_in[2];
    const float* bv  = (const float*)d_in[3];
    const float* Wq  = (const float*)d_in[4];
    const float* bq  = (const float*)d_in[5];
    const float* Wvo = (const float*)d_in[6];
    const float* bvo = (const float*)d_in[7];
    const float* Wqo = (const float*)d_in[8];
    const float* bqo = (const float*)d_in[9];
    float* out = (float*)d_out;

    __half *vthi, *vtlo, *qthi, *qtlo;
    cudaGetSymbolAddress((void**)&vthi, g_vthi); cudaGetSymbolAddress((void**)&vtlo, g_vtlo);
    cudaGetSymbolAddress((void**)&qthi, g_qthi); cudaGetSymbolAddress((void**)&qtlo, g_qtlo);
    __half *vhi, *qhi, *vuhi, *quhi;
    cudaGetSymbolAddress((void**)&vhi, g_vhi);   cudaGetSymbolAddress((void**)&qhi, g_qhi);
    cudaGetSymbolAddress((void**)&vuhi, g_vuhi); cudaGetSymbolAddress((void**)&quhi, g_quhi);
    __half *Wvth, *Wvtl, *Wqth, *Wqtl, *Wvoth, *Wvotl, *Wqoth, *Wqotl;
    cudaGetSymbolAddress((void**)&Wvth, g_Wvt_hi);   cudaGetSymbolAddress((void**)&Wvtl, g_Wvt_lo);
    cudaGetSymbolAddress((void**)&Wqth, g_Wqt_hi);   cudaGetSymbolAddress((void**)&Wqtl, g_Wqt_lo);
    cudaGetSymbolAddress((void**)&Wvoth, g_Wvot_hi); cudaGetSymbolAddress((void**)&Wvotl, g_Wvot_lo);
    cudaGetSymbolAddress((void**)&Wqoth, g_Wqot_hi); cudaGetSymbolAddress((void**)&Wqotl, g_Wqot_lo);

    cudaFuncSetAttribute(gemm_in,  cudaFuncAttributeMaxDynamicSharedMemorySize, GEMM_SMEM);
    cudaFuncSetAttribute(gemm_out, cudaFuncAttributeMaxDynamicSharedMemorySize, GEMM_SMEM);
    cudaFuncSetAttribute(fused_attn, cudaFuncAttributeMaxDynamicSharedMemorySize, ATT_SMEM);

    const dim3 t256(256);
    const float scale = 0.08838834764831845f;   // 1/sqrt(128)
    const size_t nVD = (size_t)CM * CD;

    // 0) fp16 copies of inputs; transpose+split weights
    to_half<<<2048, t256>>>(v, vhi, nVD);
    to_half<<<2048, t256>>>(q, qhi, nVD);
    transpose_split<<<dim3(C3D / 32, CD / 32), dim3(32, 8)>>>(Wv, Wvth, Wvtl, CD, C3D);
    transpose_split<<<dim3(C3D / 32, CD / 32), dim3(32, 8)>>>(Wq, Wqth, Wqtl, CD, C3D);
    transpose_split<<<dim3(CD / 32, 2 * CD / 32), dim3(32, 8)>>>(Wvo, Wvoth, Wvotl, 2 * CD, CD);
    transpose_split<<<dim3(CD / 32, 2 * CD / 32), dim3(32, 8)>>>(Wqo, Wqoth, Wqotl, 2 * CD, CD);

    // 1) input transforms -> fp16 hi/lo
    gemm_in<<<dim3(C3D / 128, CM / 128), t256, GEMM_SMEM>>>(
        vhi, Wvth, Wvtl, bv, vthi, vtlo, CM, C3D, CD);
    gemm_in<<<dim3(C3D / 128, CM / 128), t256, GEMM_SMEM>>>(
        qhi, Wqth, Wqtl, bq, qthi, qtlo, CM, C3D, CD);

    // 2-4) fused attention (scores + softmax + AV), both directions
    fused_attn<<<dim3(CN / 128, CB * CH), t256, ATT_SMEM>>>(
        vthi, qthi, qtlo, vuhi, scale);
    fused_attn<<<dim3(CN / 128, CB * CH), t256, ATT_SMEM>>>(
        qthi, vthi, vtlo, quhi, scale);

    // 5) output transforms (virtual concat)
    const size_t half = (size_t)CM * CD;
    gemm_out<<<dim3(CD / 128, CM / 128), t256, GEMM_SMEM>>>(
        vhi, vuhi, CD, Wvoth, Wvotl, bvo, out, CM, CD, 2 * CD);
    gemm_out<<<dim3(CD / 128, CM / 128), t256, GEMM_SMEM>>>(
        qhi, quhi, CD, Wqoth, Wqotl, bqo, out + half, CM, CD, 2 * CD);
}

// round 8
// speedup vs baseline: 6.8195x; 1.5774x over previous
#include <cuda_runtime.h>
#include <cuda_fp16.h>
#include <cstdint>
#include <math.h>

// Problem constants
constexpr int CB  = 32;
constexpr int CN  = 512;
constexpr int CD  = 1024;
constexpr int CH  = 8;
constexpr int CHD = 128;
constexpr int C3D = 3 * CD;
constexpr int CM  = CB * CN;   // 16384

// ---------------- scratch (device globals) ----------------------------------
__device__ __half g_vt[(size_t)CM * C3D];          // relu(v@Wv+bv) fp16
__device__ __half g_qt[(size_t)CM * C3D];
__device__ __half g_vh[(size_t)CM * CD],  g_qh[(size_t)CM * CD];
__device__ __half g_vu[(size_t)CM * CD],  g_qu[(size_t)CM * CD];
__device__ __half g_Wvt[(size_t)C3D * CD],     g_Wqt[(size_t)C3D * CD];
__device__ __half g_Wvot[(size_t)CD * 2 * CD], g_Wqot[(size_t)CD * 2 * CD];

// ---------------- base-ISA PTX helpers ---------------------------------------
__device__ __forceinline__ uint32_t smem_u32(const void* p) {
    uint32_t a;
    asm("{ .reg .u64 t; cvta.to.shared.u64 t, %1; cvt.u32.u64 %0, t; }" : "=r"(a) : "l"(p));
    return a;
}
__device__ __forceinline__ void cp_async16(uint32_t dst, const void* src) {
    asm volatile("cp.async.cg.shared.global [%0], [%1], 16;" :: "r"(dst), "l"(src) : "memory");
}
__device__ __forceinline__ void cp_commit() { asm volatile("cp.async.commit_group;" ::: "memory"); }
template <int N>
__device__ __forceinline__ void cp_wait() { asm volatile("cp.async.wait_group %0;" :: "n"(N) : "memory"); }

__device__ __forceinline__ void ldm_x4(uint32_t* r, uint32_t addr) {
    asm volatile("ldmatrix.sync.aligned.m8n8.x4.shared.b16 {%0,%1,%2,%3}, [%4];"
        : "=r"(r[0]), "=r"(r[1]), "=r"(r[2]), "=r"(r[3]) : "r"(addr));
}
__device__ __forceinline__ void ldm_x2(uint32_t* r, uint32_t addr) {
    asm volatile("ldmatrix.sync.aligned.m8n8.x2.shared.b16 {%0,%1}, [%2];"
        : "=r"(r[0]), "=r"(r[1]) : "r"(addr));
}
__device__ __forceinline__ void ldm_x2_trans(uint32_t* r, uint32_t addr) {
    asm volatile("ldmatrix.sync.aligned.m8n8.x2.trans.shared.b16 {%0,%1}, [%2];"
        : "=r"(r[0]), "=r"(r[1]) : "r"(addr));
}
__device__ __forceinline__ void mma_f16(float* c, const uint32_t* a, const uint32_t* b) {
    asm volatile("mma.sync.aligned.m16n8k16.row.col.f32.f16.f16.f32 "
        "{%0,%1,%2,%3}, {%4,%5,%6,%7}, {%8,%9}, {%0,%1,%2,%3};"
        : "+f"(c[0]), "+f"(c[1]), "+f"(c[2]), "+f"(c[3])
        : "r"(a[0]), "r"(a[1]), "r"(a[2]), "r"(a[3]), "r"(b[0]), "r"(b[1]));
}

// Weight-GEMM tiling: CTA 128x128, BK=32, 8 warps 2Mx4N, 3-stage pipeline
constexpr int TSTR    = 40;
constexpr int TILE_H  = 128 * TSTR;          // 5120 halves per 128x32 tile
constexpr int STAGE_H = 2 * TILE_H;          // A, B
constexpr int GEMM_SMEM = 3 * STAGE_H * 2;   // 61440 B

// =============================================================================
// stage-1 GEMM (merged v/q by blockIdx.z): C = fp16(relu(A @ W + bias))
// =============================================================================
__global__ __launch_bounds__(256)
void gemm_in(const __half* __restrict__ A0g, const __half* __restrict__ A1g,
             const __half* __restrict__ B0g, const __half* __restrict__ B1g,
             const float* __restrict__ bias0, const float* __restrict__ bias1,
             __half* __restrict__ C0g, __half* __restrict__ C1g,
             int M, int N, int K)
{
    extern __shared__ __half sm[];
    const uint32_t smb = smem_u32(sm);
    const int tid = threadIdx.x, wid = tid >> 5, lane = tid & 31;
    const int z = blockIdx.z;
    const __half* Ag = z ? A1g : A0g;
    const __half* Bg = z ? B1g : B0g;
    const float* bias = z ? bias1 : bias0;
    __half* Cg = z ? C1g : C0g;

    const int bm0 = blockIdx.y * 128, bn0 = blockIdx.x * 128;
    const int nk = K / 32;
    const int mw = (wid & 1) * 64, nw = (wid >> 1) * 32;

    auto load_stage = [&](int kc, int buf) {
        const int kk = kc * 32;
        const __half* a = Ag + (size_t)bm0 * K + kk;
        const __half* b = Bg + (size_t)bn0 * K + kk;
        const uint32_t base = smb + (uint32_t)buf * STAGE_H * 2;
        #pragma unroll
        for (int i = 0; i < 2; ++i) {
            const int idx = tid + i * 256;
            const int r = idx >> 2, c = (idx & 3) * 8;
            const uint32_t doff = (uint32_t)(r * TSTR + c) * 2;
            cp_async16(base + doff,              a + (size_t)r * K + c);
            cp_async16(base + TILE_H * 2 + doff, b + (size_t)r * K + c);
        }
        cp_commit();
    };

    float acc[4][4][4] = {};
    const int arow = lane & 15, acol = (lane >> 4) * 8;
    const int brow = lane & 7,  bcol = ((lane >> 3) & 1) * 8;

    load_stage(0, 0);
    load_stage(1, 1);
    for (int kc = 0; kc < nk; ++kc) {
        const int buf = kc % 3;
        if (kc + 1 < nk) cp_wait<1>(); else cp_wait<0>();
        __syncthreads();
        if (kc + 2 < nk) load_stage(kc + 2, (kc + 2) % 3);
        const uint32_t base = smb + (uint32_t)buf * STAGE_H * 2;
        #pragma unroll
        for (int ks = 0; ks < 2; ++ks) {
            const int k0 = ks * 16;
            uint32_t ah[4][4];
            #pragma unroll
            for (int mi = 0; mi < 4; ++mi) {
                const uint32_t aoff = (uint32_t)((mw + mi * 16 + arow) * TSTR + k0 + acol) * 2;
                ldm_x4(ah[mi], base + aoff);
            }
            #pragma unroll
            for (int ni = 0; ni < 4; ++ni) {
                const uint32_t boff = (uint32_t)((nw + ni * 8 + brow) * TSTR + k0 + bcol) * 2;
                uint32_t bb[2];
                ldm_x2(bb, base + TILE_H * 2 + boff);
                #pragma unroll
                for (int mi = 0; mi < 4; ++mi)
                    mma_f16(acc[mi][ni], ah[mi], bb);
            }
        }
    }

    const int g = lane >> 2, tq = lane & 3;
    #pragma unroll
    for (int mi = 0; mi < 4; ++mi) {
        const int row0 = bm0 + mw + mi * 16 + g;
        #pragma unroll
        for (int ni = 0; ni < 4; ++ni) {
            const int col = bn0 + nw + ni * 8 + tq * 2;
            const float b0 = __ldg(&bias[col]), b1 = __ldg(&bias[col + 1]);
            *reinterpret_cast<__half2*>(&Cg[(size_t)row0 * N + col]) = __halves2half2(
                __float2half_rn(fmaxf(acc[mi][ni][0] + b0, 0.f)),
                __float2half_rn(fmaxf(acc[mi][ni][1] + b1, 0.f)));
            *reinterpret_cast<__half2*>(&Cg[(size_t)(row0 + 8) * N + col]) = __halves2half2(
                __float2half_rn(fmaxf(acc[mi][ni][2] + b0, 0.f)),
                __float2half_rn(fmaxf(acc[mi][ni][3] + b1, 0.f)));
        }
    }
}

// =============================================================================
// stage-5 GEMM (merged v/q): C = relu(concat(A0,A1) @ W + bias), fp32 out
// =============================================================================
__global__ __launch_bounds__(256)
void gemm_out(const __half* __restrict__ A0v, const __half* __restrict__ A1v,
              const __half* __restrict__ A0q, const __half* __restrict__ A1q,
              int K0,
              const __half* __restrict__ Bv, const __half* __restrict__ Bq,
              const float* __restrict__ biasv, const float* __restrict__ biasq,
              float* __restrict__ C, size_t zoff,
              int M, int N, int K)
{
    extern __shared__ __half sm[];
    const uint32_t smb = smem_u32(sm);
    const int tid = threadIdx.x, wid = tid >> 5, lane = tid & 31;
    const int z = blockIdx.z;
    const __half* A0g = z ? A0q : A0v;
    const __half* A1g = z ? A1q : A1v;
    const __half* Bg  = z ? Bq  : Bv;
    const float* bias = z ? biasq : biasv;
    float* Cg = C + (size_t)z * zoff;

    const int bm0 = blockIdx.y * 128, bn0 = blockIdx.x * 128;
    const int nk = K / 32, K1 = K - K0;
    const int mw = (wid & 1) * 64, nw = (wid >> 1) * 32;

    auto load_stage = [&](int kc, int buf) {
        const int kk = kc * 32;
        const __half* a; int ldA, ka;
        if (kk < K0) { a = A0g; ldA = K0; ka = kk; }
        else         { a = A1g; ldA = K1; ka = kk - K0; }
        a += (size_t)bm0 * ldA + ka;
        const __half* b = Bg + (size_t)bn0 * K + kk;
        const uint32_t base = smb + (uint32_t)buf * STAGE_H * 2;
        #pragma unroll
        for (int i = 0; i < 2; ++i) {
            const int idx = tid + i * 256;
            const int r = idx >> 2, c = (idx & 3) * 8;
            const uint32_t doff = (uint32_t)(r * TSTR + c) * 2;
            cp_async16(base + doff,              a + (size_t)r * ldA + c);
            cp_async16(base + TILE_H * 2 + doff, b + (size_t)r * K + c);
        }
        cp_commit();
    };

    float acc[4][4][4] = {};
    const int arow = lane & 15, acol = (lane >> 4) * 8;
    const int brow = lane & 7,  bcol = ((lane >> 3) & 1) * 8;

    load_stage(0, 0);
    load_stage(1, 1);
    for (int kc = 0; kc < nk; ++kc) {
        const int buf = kc % 3;
        if (kc + 1 < nk) cp_wait<1>(); else cp_wait<0>();
        __syncthreads();
        if (kc + 2 < nk) load_stage(kc + 2, (kc + 2) % 3);
        const uint32_t base = smb + (uint32_t)buf * STAGE_H * 2;
        #pragma unroll
        for (int ks = 0; ks < 2; ++ks) {
            const int k0 = ks * 16;
            uint32_t ah[4][4];
            #pragma unroll
            for (int mi = 0; mi < 4; ++mi) {
                const uint32_t aoff = (uint32_t)((mw + mi * 16 + arow) * TSTR + k0 + acol) * 2;
                ldm_x4(ah[mi], base + aoff);
            }
            #pragma unroll
            for (int ni = 0; ni < 4; ++ni) {
                const uint32_t boff = (uint32_t)((nw + ni * 8 + brow) * TSTR + k0 + bcol) * 2;
                uint32_t bb[2];
                ldm_x2(bb, base + TILE_H * 2 + boff);
                #pragma unroll
                for (int mi = 0; mi < 4; ++mi)
                    mma_f16(acc[mi][ni], ah[mi], bb);
            }
        }
    }

    const int g = lane >> 2, tq = lane & 3;
    #pragma unroll
    for (int mi = 0; mi < 4; ++mi) {
        const int row0 = bm0 + mw + mi * 16 + g;
        #pragma unroll
        for (int ni = 0; ni < 4; ++ni) {
            const int col = bn0 + nw + ni * 8 + tq * 2;
            const float b0 = __ldg(&bias[col]), b1 = __ldg(&bias[col + 1]);
            float2 o0, o1;
            o0.x = fmaxf(acc[mi][ni][0] + b0, 0.f);
            o0.y = fmaxf(acc[mi][ni][1] + b1, 0.f);
            o1.x = fmaxf(acc[mi][ni][2] + b0, 0.f);
            o1.y = fmaxf(acc[mi][ni][3] + b1, 0.f);
            *reinterpret_cast<float2*>(&Cg[(size_t)row0 * N + col]) = o0;
            *reinterpret_cast<float2*>(&Cg[(size_t)(row0 + 8) * N + col]) = o1;
        }
    }
}

// =============================================================================
// Fused flash attention (merged directions by blockIdx.z)
// U = softmax(Q K^T * scale) V;  Q = Ta[:, CD+h*HD], K = Tb[:, h*HD],
// V = Tb[:, 2CD+h*HD]; all fp16. CTA: 128 q-rows, m-chunks of 64, dbl-buffered.
// =============================================================================
constexpr int QSTR = 136;
constexpr int KSTR = 136;
constexpr int Q_HLV = 128 * QSTR;          // 17408 halves
constexpr int KV_TILE = 64 * KSTR;         // 8704 halves
constexpr int KV_STAGE = 2 * KV_TILE;      // K, V
constexpr int ATT_SMEM = (Q_HLV + 2 * KV_STAGE) * 2;   // 104448 B

__global__ __launch_bounds__(256, 1)
void fused_attn(const __half* __restrict__ Ta0, const __half* __restrict__ Tb0,
                __half* __restrict__ U0,
                const __half* __restrict__ Ta1, const __half* __restrict__ Tb1,
                __half* __restrict__ U1, float scale)
{
    extern __shared__ __half sm[];
    const uint32_t smb = smem_u32(sm);
    const int tid = threadIdx.x, wid = tid >> 5, lane = tid & 31;
    const int z = blockIdx.z;
    const __half* Ta = z ? Ta1 : Ta0;
    const __half* Tb = z ? Tb1 : Tb0;
    __half* U = z ? U1 : U0;

    const int bz = blockIdx.y, b = bz >> 3, h = bz & 7;
    const int n0 = blockIdx.x * 128;
    const int wrow = wid * 16;

    const size_t qbase = (size_t)(b * CN + n0) * C3D + CD + h * CHD;
    const size_t kbase = (size_t)b * CN * C3D + h * CHD;
    const size_t vbase = (size_t)b * CN * C3D + 2 * CD + h * CHD;

    auto load_q = [&]() {
        #pragma unroll
        for (int i = 0; i < 8; ++i) {
            const int idx = tid + i * 256;
            const int r = idx >> 4, c = (idx & 15) * 8;
            cp_async16(smb + (uint32_t)(r * QSTR + c) * 2,
                       Ta + qbase + (size_t)r * C3D + c);
        }
        cp_commit();
    };
    auto load_kv = [&](int mc, int buf) {
        const int m0 = mc * 64;
        const uint32_t base = smb + (uint32_t)(Q_HLV + buf * KV_STAGE) * 2;
        const __half* kp = Tb + kbase + (size_t)m0 * C3D;
        const __half* vp = Tb + vbase + (size_t)m0 * C3D;
        #pragma unroll
        for (int i = 0; i < 4; ++i) {
            const int idx = tid + i * 256;
            const int r = idx >> 4, c = (idx & 15) * 8;
            const uint32_t doff = (uint32_t)(r * KSTR + c) * 2;
            cp_async16(base + doff,               kp + (size_t)r * C3D + c);
            cp_async16(base + KV_TILE * 2 + doff, vp + (size_t)r * C3D + c);
        }
        cp_commit();
    };

    load_q();
    load_kv(0, 0);
    cp_wait<1>();
    __syncthreads();

    const int arow = lane & 15, acol = (lane >> 4) * 8;
    uint32_t qf[8][4];
    #pragma unroll
    for (int kf = 0; kf < 8; ++kf)
        ldm_x4(qf[kf], smb + (uint32_t)((wrow + arow) * QSTR + kf * 16 + acol) * 2);

    const int g = lane >> 2, tq = lane & 3;
    const int brow = lane & 7, bcol = ((lane >> 3) & 1) * 8;
    const int vrow = lane & 15;

    float m0s = -1e30f, m1s = -1e30f, l0s = 0.f, l1s = 0.f;
    float o[16][4] = {};

    for (int mc = 0; mc < 8; ++mc) {
        const int buf = mc & 1;
        if (mc + 1 < 8) { load_kv(mc + 1, buf ^ 1); cp_wait<1>(); }
        else            { cp_wait<0>(); }
        __syncthreads();

        const uint32_t base = smb + (uint32_t)(Q_HLV + buf * KV_STAGE) * 2;

        // ---- S = Q K^T (64 cols) ----
        float s[8][4] = {};
        #pragma unroll
        for (int kf = 0; kf < 8; ++kf) {
            #pragma unroll
            for (int nf = 0; nf < 8; ++nf) {
                const uint32_t boff = (uint32_t)((nf * 8 + brow) * KSTR + kf * 16 + bcol) * 2;
                uint32_t kk2[2];
                ldm_x2(kk2, base + boff);
                mma_f16(s[nf], qf[kf], kk2);
            }
        }

        // ---- online softmax ----
        float mx0 = -1e30f, mx1 = -1e30f;
        #pragma unroll
        for (int nf = 0; nf < 8; ++nf) {
            mx0 = fmaxf(mx0, fmaxf(s[nf][0], s[nf][1]));
            mx1 = fmaxf(mx1, fmaxf(s[nf][2], s[nf][3]));
        }
        mx0 = fmaxf(mx0, __shfl_xor_sync(0xffffffffu, mx0, 1));
        mx0 = fmaxf(mx0, __shfl_xor_sync(0xffffffffu, mx0, 2));
        mx1 = fmaxf(mx1, __shfl_xor_sync(0xffffffffu, mx1, 1));
        mx1 = fmaxf(mx1, __shfl_xor_sync(0xffffffffu, mx1, 2));
        mx0 *= scale; mx1 *= scale;
        const float mn0 = fmaxf(m0s, mx0), mn1 = fmaxf(m1s, mx1);
        const float a0 = __expf(m0s - mn0), a1 = __expf(m1s - mn1);
        m0s = mn0; m1s = mn1;

        float rs0 = 0.f, rs1 = 0.f;
        __half2 pf[8][2];
        #pragma unroll
        for (int nf = 0; nf < 8; ++nf) {
            const float p0 = __expf(s[nf][0] * scale - mn0);
            const float p1 = __expf(s[nf][1] * scale - mn0);
            const float p2 = __expf(s[nf][2] * scale - mn1);
            const float p3 = __expf(s[nf][3] * scale - mn1);
            rs0 += p0 + p1; rs1 += p2 + p3;
            pf[nf][0] = __halves2half2(__float2half_rn(p0), __float2half_rn(p1));
            pf[nf][1] = __halves2half2(__float2half_rn(p2), __float2half_rn(p3));
        }
        rs0 += __shfl_xor_sync(0xffffffffu, rs0, 1);
        rs0 += __shfl_xor_sync(0xffffffffu, rs0, 2);
        rs1 += __shfl_xor_sync(0xffffffffu, rs1, 1);
        rs1 += __shfl_xor_sync(0xffffffffu, rs1, 2);
        l0s = l0s * a0 + rs0;
        l1s = l1s * a1 + rs1;

        #pragma unroll
        for (int nf2 = 0; nf2 < 16; ++nf2) {
            o[nf2][0] *= a0; o[nf2][1] *= a0;
            o[nf2][2] *= a1; o[nf2][3] *= a1;
        }

        // ---- O += P V ----
        #pragma unroll
        for (int kf2 = 0; kf2 < 4; ++kf2) {
            uint32_t pa[4];
            pa[0] = *reinterpret_cast<uint32_t*>(&pf[2 * kf2][0]);
            pa[1] = *reinterpret_cast<uint32_t*>(&pf[2 * kf2][1]);
            pa[2] = *reinterpret_cast<uint32_t*>(&pf[2 * kf2 + 1][0]);
            pa[3] = *reinterpret_cast<uint32_t*>(&pf[2 * kf2 + 1][1]);
            #pragma unroll
            for (int nf2 = 0; nf2 < 16; ++nf2) {
                const uint32_t boff = (uint32_t)((kf2 * 16 + vrow) * KSTR + nf2 * 8) * 2;
                uint32_t vv2[2];
                ldm_x2_trans(vv2, base + KV_TILE * 2 + boff);
                mma_f16(o[nf2], pa, vv2);
            }
        }
        __syncthreads();
    }

    const float inv0 = 1.f / l0s, inv1 = 1.f / l1s;
    const int row0 = n0 + wrow + g;
    #pragma unroll
    for (int nf2 = 0; nf2 < 16; ++nf2) {
        const int col = h * CHD + nf2 * 8 + tq * 2;
        const size_t off0 = (size_t)(b * CN + row0) * CD + col;
        const size_t off1 = (size_t)(b * CN + row0 + 8) * CD + col;
        *reinterpret_cast<__half2*>(&U[off0]) =
            __halves2half2(__float2half_rn(o[nf2][0] * inv0), __float2half_rn(o[nf2][1] * inv0));
        *reinterpret_cast<__half2*>(&U[off1]) =
            __halves2half2(__float2half_rn(o[nf2][2] * inv1), __float2half_rn(o[nf2][3] * inv1));
    }
}

// =============================================================================
// precompute kernels
// =============================================================================
__global__ __launch_bounds__(256)
void to_half2(const float* __restrict__ x0, __half* __restrict__ h0,
              const float* __restrict__ x1, __half* __restrict__ h1, size_t n)
{
    const float* x = blockIdx.z ? x1 : x0;
    __half* hh = blockIdx.z ? h1 : h0;
    const size_t stride = (size_t)gridDim.x * blockDim.x * 4;
    for (size_t i = ((size_t)blockIdx.x * blockDim.x + threadIdx.x) * 4; i < n; i += stride) {
        float4 v = *reinterpret_cast<const float4*>(x + i);
        *reinterpret_cast<__half2*>(hh + i) =
            __halves2half2(__float2half_rn(v.x), __float2half_rn(v.y));
        *reinterpret_cast<__half2*>(hh + i + 2) =
            __halves2half2(__float2half_rn(v.z), __float2half_rn(v.w));
    }
}

__global__ __launch_bounds__(256)
void transpose_half(const float* __restrict__ W, __half* __restrict__ t16,
                    int K, int N)
{
    __shared__ float t[32][33];
    const int k0 = blockIdx.y * 32, n0 = blockIdx.x * 32;
    const int tx = threadIdx.x, ty = threadIdx.y;
    for (int i = ty; i < 32; i += 8)
        t[i][tx] = W[(size_t)(k0 + i) * N + n0 + tx];
    __syncthreads();
    for (int i = ty; i < 32; i += 8)
        t16[(size_t)(n0 + i) * K + k0 + tx] = __float2half_rn(t[tx][i]);
}

// =============================================================================
// launch
// =============================================================================
extern "C" void kernel_launch(void* const* d_in, const int* in_sizes, int n_in,
                              void* d_out, int out_size)
{
    const float* v   = (const float*)d_in[0];
    const float* q   = (const float*)d_in[1];
    const float* Wv  = (const float*)d_in[2];
    const float* bv  = (const float*)d_in[3];
    const float* Wq  = (const float*)d_in[4];
    const float* bq  = (const float*)d_in[5];
    const float* Wvo = (const float*)d_in[6];
    const float* bvo = (const float*)d_in[7];
    const float* Wqo = (const float*)d_in[8];
    const float* bqo = (const float*)d_in[9];
    float* out = (float*)d_out;

    __half *vt, *qt, *vh, *qh, *vu, *qu, *Wvt, *Wqt, *Wvot, *Wqot;
    cudaGetSymbolAddress((void**)&vt, g_vt);   cudaGetSymbolAddress((void**)&qt, g_qt);
    cudaGetSymbolAddress((void**)&vh, g_vh);   cudaGetSymbolAddress((void**)&qh, g_qh);
    cudaGetSymbolAddress((void**)&vu, g_vu);   cudaGetSymbolAddress((void**)&qu, g_qu);
    cudaGetSymbolAddress((void**)&Wvt, g_Wvt); cudaGetSymbolAddress((void**)&Wqt, g_Wqt);
    cudaGetSymbolAddress((void**)&Wvot, g_Wvot); cudaGetSymbolAddress((void**)&Wqot, g_Wqot);

    cudaFuncSetAttribute(gemm_in,  cudaFuncAttributeMaxDynamicSharedMemorySize, GEMM_SMEM);
    cudaFuncSetAttribute(gemm_out, cudaFuncAttributeMaxDynamicSharedMemorySize, GEMM_SMEM);
    cudaFuncSetAttribute(fused_attn, cudaFuncAttributeMaxDynamicSharedMemorySize, ATT_SMEM);

    const dim3 t256(256);
    const float scale = 0.08838834764831845f;   // 1/sqrt(128)
    const size_t nVD = (size_t)CM * CD;
    const size_t half = (size_t)CM * CD;

    // launches 0-4: prep (so launch #5 = gemm_in for ncu -s 5 -c 1)
    to_half2<<<dim3(1024, 1, 2), t256>>>(v, vh, q, qh, nVD);
    transpose_half<<<dim3(C3D / 32, CD / 32), dim3(32, 8)>>>(Wv, Wvt, CD, C3D);
    transpose_half<<<dim3(C3D / 32, CD / 32), dim3(32, 8)>>>(Wq, Wqt, CD, C3D);
    transpose_half<<<dim3(CD / 32, 2 * CD / 32), dim3(32, 8)>>>(Wvo, Wvot, 2 * CD, CD);
    transpose_half<<<dim3(CD / 32, 2 * CD / 32), dim3(32, 8)>>>(Wqo, Wqot, 2 * CD, CD);

    // launch 5: input transforms (both modalities)
    gemm_in<<<dim3(C3D / 128, CM / 128, 2), t256, GEMM_SMEM>>>(
        vh, qh, Wvt, Wqt, bv, bq, vt, qt, CM, C3D, CD);

    // launch 6: fused attention, both directions
    fused_attn<<<dim3(CN / 128, CB * CH, 2), t256, ATT_SMEM>>>(
        vt, qt, vu,      // z=0: Q from v-side, K/V from q-side -> v_update
        qt, vt, qu,      // z=1: Q from q-side, K/V from v-side -> q_update
        scale);

    // launch 7: output transforms (virtual concat), both modalities
    gemm_out<<<dim3(CD / 128, CM / 128, 2), t256, GEMM_SMEM>>>(
        vh, vu, qh, qu, CD, Wvot, Wqot, bvo, bqo, out, half, CM, CD, 2 * CD);
}

// round 9
// speedup vs baseline: 8.2613x; 1.2114x over previous
#include <cuda_runtime.h>
#include <cuda_fp16.h>
#include <cstdint>
#include <math.h>

// Problem constants
constexpr int CB  = 32;
constexpr int CN  = 512;
constexpr int CD  = 1024;
constexpr int CH  = 8;
constexpr int CHD = 128;
constexpr int C3D = 3 * CD;
constexpr int CM  = CB * CN;   // 16384

// ---------------- scratch (device globals) ----------------------------------
__device__ __half g_vt[(size_t)CM * C3D];
__device__ __half g_qt[(size_t)CM * C3D];
__device__ __half g_vh[(size_t)CM * CD],  g_qh[(size_t)CM * CD];
__device__ __half g_vu[(size_t)CM * CD],  g_qu[(size_t)CM * CD];
__device__ __half g_Wvt[(size_t)C3D * CD],     g_Wqt[(size_t)C3D * CD];
__device__ __half g_Wvot[(size_t)CD * 2 * CD], g_Wqot[(size_t)CD * 2 * CD];

// ---------------- base-ISA PTX helpers ---------------------------------------
__device__ __forceinline__ uint32_t smem_u32(const void* p) {
    uint32_t a;
    asm("{ .reg .u64 t; cvta.to.shared.u64 t, %1; cvt.u32.u64 %0, t; }" : "=r"(a) : "l"(p));
    return a;
}
__device__ __forceinline__ void cp_async16(uint32_t dst, const void* src) {
    asm volatile("cp.async.cg.shared.global [%0], [%1], 16;" :: "r"(dst), "l"(src) : "memory");
}
__device__ __forceinline__ void cp_commit() { asm volatile("cp.async.commit_group;" ::: "memory"); }
template <int N>
__device__ __forceinline__ void cp_wait() { asm volatile("cp.async.wait_group %0;" :: "n"(N) : "memory"); }

__device__ __forceinline__ void ldm_x4(uint32_t* r, uint32_t addr) {
    asm volatile("ldmatrix.sync.aligned.m8n8.x4.shared.b16 {%0,%1,%2,%3}, [%4];"
        : "=r"(r[0]), "=r"(r[1]), "=r"(r[2]), "=r"(r[3]) : "r"(addr));
}
__device__ __forceinline__ void ldm_x2(uint32_t* r, uint32_t addr) {
    asm volatile("ldmatrix.sync.aligned.m8n8.x2.shared.b16 {%0,%1}, [%2];"
        : "=r"(r[0]), "=r"(r[1]) : "r"(addr));
}
__device__ __forceinline__ void ldm_x2_trans(uint32_t* r, uint32_t addr) {
    asm volatile("ldmatrix.sync.aligned.m8n8.x2.trans.shared.b16 {%0,%1}, [%2];"
        : "=r"(r[0]), "=r"(r[1]) : "r"(addr));
}
__device__ __forceinline__ void mma_f16(float* c, const uint32_t* a, const uint32_t* b) {
    asm volatile("mma.sync.aligned.m16n8k16.row.col.f32.f16.f16.f32 "
        "{%0,%1,%2,%3}, {%4,%5,%6,%7}, {%8,%9}, {%0,%1,%2,%3};"
        : "+f"(c[0]), "+f"(c[1]), "+f"(c[2]), "+f"(c[3])
        : "r"(a[0]), "r"(a[1]), "r"(a[2]), "r"(a[3]), "r"(b[0]), "r"(b[1]));
}

// Weight-GEMM tiling: CTA 128x128, BK=64, 8 warps 2Mx4N, 3-stage, 2 CTAs/SM
constexpr int TSTR    = 72;                  // halves per smem row (64 + pad 8)
constexpr int TILE_H  = 128 * TSTR;          // 9216 halves per 128x64 tile
constexpr int STAGE_H = 2 * TILE_H;          // A, B
constexpr int GEMM_SMEM = 3 * STAGE_H * 2;   // 110592 B

// =============================================================================
// stage-1 GEMM (merged v/q by blockIdx.z): C = fp16(relu(A @ W + bias))
// =============================================================================
__global__ __launch_bounds__(256, 2)
void gemm_in(const __half* __restrict__ A0g, const __half* __restrict__ A1g,
             const __half* __restrict__ B0g, const __half* __restrict__ B1g,
             const float* __restrict__ bias0, const float* __restrict__ bias1,
             __half* __restrict__ C0g, __half* __restrict__ C1g,
             int M, int N, int K)
{
    extern __shared__ __half sm[];
    const uint32_t smb = smem_u32(sm);
    const int tid = threadIdx.x, wid = tid >> 5, lane = tid & 31;
    const int z = blockIdx.z;
    const __half* Ag = z ? A1g : A0g;
    const __half* Bg = z ? B1g : B0g;
    const float* bias = z ? bias1 : bias0;
    __half* Cg = z ? C1g : C0g;

    const int bm0 = blockIdx.y * 128, bn0 = blockIdx.x * 128;
    const int nk = K / 64;
    const int mw = (wid & 1) * 64, nw = (wid >> 1) * 32;

    auto load_stage = [&](int kc, int buf) {
        const int kk = kc * 64;
        const __half* a = Ag + (size_t)bm0 * K + kk;
        const __half* b = Bg + (size_t)bn0 * K + kk;
        const uint32_t base = smb + (uint32_t)buf * STAGE_H * 2;
        #pragma unroll
        for (int i = 0; i < 4; ++i) {
            const int idx = tid + i * 256;           // 0..1023
            const int r = idx >> 3, c = (idx & 7) * 8;
            const uint32_t doff = (uint32_t)(r * TSTR + c) * 2;
            cp_async16(base + doff,              a + (size_t)r * K + c);
            cp_async16(base + TILE_H * 2 + doff, b + (size_t)r * K + c);
        }
        cp_commit();
    };

    float acc[4][4][4] = {};
    const int arow = lane & 15, acol = (lane >> 4) * 8;
    const int brow = lane & 7,  bcol = ((lane >> 3) & 1) * 8;

    load_stage(0, 0);
    load_stage(1, 1);
    for (int kc = 0; kc < nk; ++kc) {
        const int buf = kc % 3;
        if (kc + 1 < nk) cp_wait<1>(); else cp_wait<0>();
        __syncthreads();
        if (kc + 2 < nk) load_stage(kc + 2, (kc + 2) % 3);
        const uint32_t base = smb + (uint32_t)buf * STAGE_H * 2;
        #pragma unroll
        for (int ks = 0; ks < 4; ++ks) {
            const int k0 = ks * 16;
            uint32_t bb[4][2];
            #pragma unroll
            for (int ni = 0; ni < 4; ++ni) {
                const uint32_t boff = (uint32_t)((nw + ni * 8 + brow) * TSTR + k0 + bcol) * 2;
                ldm_x2(bb[ni], base + TILE_H * 2 + boff);
            }
            #pragma unroll
            for (int mi = 0; mi < 4; ++mi) {
                uint32_t ah[4];
                const uint32_t aoff = (uint32_t)((mw + mi * 16 + arow) * TSTR + k0 + acol) * 2;
                ldm_x4(ah, base + aoff);
                #pragma unroll
                for (int ni = 0; ni < 4; ++ni)
                    mma_f16(acc[mi][ni], ah, bb[ni]);
            }
        }
    }

    const int g = lane >> 2, tq = lane & 3;
    #pragma unroll
    for (int mi = 0; mi < 4; ++mi) {
        const int row0 = bm0 + mw + mi * 16 + g;
        #pragma unroll
        for (int ni = 0; ni < 4; ++ni) {
            const int col = bn0 + nw + ni * 8 + tq * 2;
            const float b0 = __ldg(&bias[col]), b1 = __ldg(&bias[col + 1]);
            *reinterpret_cast<__half2*>(&Cg[(size_t)row0 * N + col]) = __halves2half2(
                __float2half_rn(fmaxf(acc[mi][ni][0] + b0, 0.f)),
                __float2half_rn(fmaxf(acc[mi][ni][1] + b1, 0.f)));
            *reinterpret_cast<__half2*>(&Cg[(size_t)(row0 + 8) * N + col]) = __halves2half2(
                __float2half_rn(fmaxf(acc[mi][ni][2] + b0, 0.f)),
                __float2half_rn(fmaxf(acc[mi][ni][3] + b1, 0.f)));
        }
    }
}

// =============================================================================
// stage-5 GEMM (merged v/q): C = relu(concat(A0,A1) @ W + bias), fp32 out
// =============================================================================
__global__ __launch_bounds__(256, 2)
void gemm_out(const __half* __restrict__ A0v, const __half* __restrict__ A1v,
              const __half* __restrict__ A0q, const __half* __restrict__ A1q,
              int K0,
              const __half* __restrict__ Bv, const __half* __restrict__ Bq,
              const float* __restrict__ biasv, const float* __restrict__ biasq,
              float* __restrict__ C, size_t zoff,
              int M, int N, int K)
{
    extern __shared__ __half sm[];
    const uint32_t smb = smem_u32(sm);
    const int tid = threadIdx.x, wid = tid >> 5, lane = tid & 31;
    const int z = blockIdx.z;
    const __half* A0g = z ? A0q : A0v;
    const __half* A1g = z ? A1q : A1v;
    const __half* Bg  = z ? Bq  : Bv;
    const float* bias = z ? biasq : biasv;
    float* Cg = C + (size_t)z * zoff;

    const int bm0 = blockIdx.y * 128, bn0 = blockIdx.x * 128;
    const int nk = K / 64, K1 = K - K0;
    const int mw = (wid & 1) * 64, nw = (wid >> 1) * 32;

    auto load_stage = [&](int kc, int buf) {
        const int kk = kc * 64;
        const __half* a; int ldA, ka;
        if (kk < K0) { a = A0g; ldA = K0; ka = kk; }
        else         { a = A1g; ldA = K1; ka = kk - K0; }
        a += (size_t)bm0 * ldA + ka;
        const __half* b = Bg + (size_t)bn0 * K + kk;
        const uint32_t base = smb + (uint32_t)buf * STAGE_H * 2;
        #pragma unroll
        for (int i = 0; i < 4; ++i) {
            const int idx = tid + i * 256;
            const int r = idx >> 3, c = (idx & 7) * 8;
            const uint32_t doff = (uint32_t)(r * TSTR + c) * 2;
            cp_async16(base + doff,              a + (size_t)r * ldA + c);
            cp_async16(base + TILE_H * 2 + doff, b + (size_t)r * K + c);
        }
        cp_commit();
    };

    float acc[4][4][4] = {};
    const int arow = lane & 15, acol = (lane >> 4) * 8;
    const int brow = lane & 7,  bcol = ((lane >> 3) & 1) * 8;

    load_stage(0, 0);
    load_stage(1, 1);
    for (int kc = 0; kc < nk; ++kc) {
        const int buf = kc % 3;
        if (kc + 1 < nk) cp_wait<1>(); else cp_wait<0>();
        __syncthreads();
        if (kc + 2 < nk) load_stage(kc + 2, (kc + 2) % 3);
        const uint32_t base = smb + (uint32_t)buf * STAGE_H * 2;
        #pragma unroll
        for (int ks = 0; ks < 4; ++ks) {
            const int k0 = ks * 16;
            uint32_t bb[4][2];
            #pragma unroll
            for (int ni = 0; ni < 4; ++ni) {
                const uint32_t boff = (uint32_t)((nw + ni * 8 + brow) * TSTR + k0 + bcol) * 2;
                ldm_x2(bb[ni], base + TILE_H * 2 + boff);
            }
            #pragma unroll
            for (int mi = 0; mi < 4; ++mi) {
                uint32_t ah[4];
                const uint32_t aoff = (uint32_t)((mw + mi * 16 + arow) * TSTR + k0 + acol) * 2;
                ldm_x4(ah, base + aoff);
                #pragma unroll
                for (int ni = 0; ni < 4; ++ni)
                    mma_f16(acc[mi][ni], ah, bb[ni]);
            }
        }
    }

    const int g = lane >> 2, tq = lane & 3;
    #pragma unroll
    for (int mi = 0; mi < 4; ++mi) {
        const int row0 = bm0 + mw + mi * 16 + g;
        #pragma unroll
        for (int ni = 0; ni < 4; ++ni) {
            const int col = bn0 + nw + ni * 8 + tq * 2;
            const float b0 = __ldg(&bias[col]), b1 = __ldg(&bias[col + 1]);
            float2 o0, o1;
            o0.x = fmaxf(acc[mi][ni][0] + b0, 0.f);
            o0.y = fmaxf(acc[mi][ni][1] + b1, 0.f);
            o1.x = fmaxf(acc[mi][ni][2] + b0, 0.f);
            o1.y = fmaxf(acc[mi][ni][3] + b1, 0.f);
            *reinterpret_cast<float2*>(&Cg[(size_t)row0 * N + col]) = o0;
            *reinterpret_cast<float2*>(&Cg[(size_t)(row0 + 8) * N + col]) = o1;
        }
    }
}

// =============================================================================
// Fused flash attention (merged directions by blockIdx.z) — unchanged from R8
// =============================================================================
constexpr int QSTR = 136;
constexpr int KSTR = 136;
constexpr int Q_HLV = 128 * QSTR;
constexpr int KV_TILE = 64 * KSTR;
constexpr int KV_STAGE = 2 * KV_TILE;
constexpr int ATT_SMEM = (Q_HLV + 2 * KV_STAGE) * 2;   // 104448 B

__global__ __launch_bounds__(256, 1)
void fused_attn(const __half* __restrict__ Ta0, const __half* __restrict__ Tb0,
                __half* __restrict__ U0,
                const __half* __restrict__ Ta1, const __half* __restrict__ Tb1,
                __half* __restrict__ U1, float scale)
{
    extern __shared__ __half sm[];
    const uint32_t smb = smem_u32(sm);
    const int tid = threadIdx.x, wid = tid >> 5, lane = tid & 31;
    const int z = blockIdx.z;
    const __half* Ta = z ? Ta1 : Ta0;
    const __half* Tb = z ? Tb1 : Tb0;
    __half* U = z ? U1 : U0;

    const int bz = blockIdx.y, b = bz >> 3, h = bz & 7;
    const int n0 = blockIdx.x * 128;
    const int wrow = wid * 16;

    const size_t qbase = (size_t)(b * CN + n0) * C3D + CD + h * CHD;
    const size_t kbase = (size_t)b * CN * C3D + h * CHD;
    const size_t vbase = (size_t)b * CN * C3D + 2 * CD + h * CHD;

    auto load_q = [&]() {
        #pragma unroll
        for (int i = 0; i < 8; ++i) {
            const int idx = tid + i * 256;
            const int r = idx >> 4, c = (idx & 15) * 8;
            cp_async16(smb + (uint32_t)(r * QSTR + c) * 2,
                       Ta + qbase + (size_t)r * C3D + c);
        }
        cp_commit();
    };
    auto load_kv = [&](int mc, int buf) {
        const int m0 = mc * 64;
        const uint32_t base = smb + (uint32_t)(Q_HLV + buf * KV_STAGE) * 2;
        const __half* kp = Tb + kbase + (size_t)m0 * C3D;
        const __half* vp = Tb + vbase + (size_t)m0 * C3D;
        #pragma unroll
        for (int i = 0; i < 4; ++i) {
            const int idx = tid + i * 256;
            const int r = idx >> 4, c = (idx & 15) * 8;
            const uint32_t doff = (uint32_t)(r * KSTR + c) * 2;
            cp_async16(base + doff,               kp + (size_t)r * C3D + c);
            cp_async16(base + KV_TILE * 2 + doff, vp + (size_t)r * C3D + c);
        }
        cp_commit();
    };

    load_q();
    load_kv(0, 0);
    cp_wait<1>();
    __syncthreads();

    const int arow = lane & 15, acol = (lane >> 4) * 8;
    uint32_t qf[8][4];
    #pragma unroll
    for (int kf = 0; kf < 8; ++kf)
        ldm_x4(qf[kf], smb + (uint32_t)((wrow + arow) * QSTR + kf * 16 + acol) * 2);

    const int g = lane >> 2, tq = lane & 3;
    const int brow = lane & 7, bcol = ((lane >> 3) & 1) * 8;
    const int vrow = lane & 15;

    float m0s = -1e30f, m1s = -1e30f, l0s = 0.f, l1s = 0.f;
    float o[16][4] = {};

    for (int mc = 0; mc < 8; ++mc) {
        const int buf = mc & 1;
        if (mc + 1 < 8) { load_kv(mc + 1, buf ^ 1); cp_wait<1>(); }
        else            { cp_wait<0>(); }
        __syncthreads();

        const uint32_t base = smb + (uint32_t)(Q_HLV + buf * KV_STAGE) * 2;

        float s[8][4] = {};
        #pragma unroll
        for (int kf = 0; kf < 8; ++kf) {
            #pragma unroll
            for (int nf = 0; nf < 8; ++nf) {
                const uint32_t boff = (uint32_t)((nf * 8 + brow) * KSTR + kf * 16 + bcol) * 2;
                uint32_t kk2[2];
                ldm_x2(kk2, base + boff);
                mma_f16(s[nf], qf[kf], kk2);
            }
        }

        float mx0 = -1e30f, mx1 = -1e30f;
        #pragma unroll
        for (int nf = 0; nf < 8; ++nf) {
            mx0 = fmaxf(mx0, fmaxf(s[nf][0], s[nf][1]));
            mx1 = fmaxf(mx1, fmaxf(s[nf][2], s[nf][3]));
        }
        mx0 = fmaxf(mx0, __shfl_xor_sync(0xffffffffu, mx0, 1));
        mx0 = fmaxf(mx0, __shfl_xor_sync(0xffffffffu, mx0, 2));
        mx1 = fmaxf(mx1, __shfl_xor_sync(0xffffffffu, mx1, 1));
        mx1 = fmaxf(mx1, __shfl_xor_sync(0xffffffffu, mx1, 2));
        mx0 *= scale; mx1 *= scale;
        const float mn0 = fmaxf(m0s, mx0), mn1 = fmaxf(m1s, mx1);
        const float a0 = __expf(m0s - mn0), a1 = __expf(m1s - mn1);
        m0s = mn0; m1s = mn1;

        float rs0 = 0.f, rs1 = 0.f;
        __half2 pf[8][2];
        #pragma unroll
        for (int nf = 0; nf < 8; ++nf) {
            const float p0 = __expf(s[nf][0] * scale - mn0);
            const float p1 = __expf(s[nf][1] * scale - mn0);
            const float p2 = __expf(s[nf][2] * scale - mn1);
            const float p3 = __expf(s[nf][3] * scale - mn1);
            rs0 += p0 + p1; rs1 += p2 + p3;
            pf[nf][0] = __halves2half2(__float2half_rn(p0), __float2half_rn(p1));
            pf[nf][1] = __halves2half2(__float2half_rn(p2), __float2half_rn(p3));
        }
        rs0 += __shfl_xor_sync(0xffffffffu, rs0, 1);
        rs0 += __shfl_xor_sync(0xffffffffu, rs0, 2);
        rs1 += __shfl_xor_sync(0xffffffffu, rs1, 1);
        rs1 += __shfl_xor_sync(0xffffffffu, rs1, 2);
        l0s = l0s * a0 + rs0;
        l1s = l1s * a1 + rs1;

        #pragma unroll
        for (int nf2 = 0; nf2 < 16; ++nf2) {
            o[nf2][0] *= a0; o[nf2][1] *= a0;
            o[nf2][2] *= a1; o[nf2][3] *= a1;
        }

        #pragma unroll
        for (int kf2 = 0; kf2 < 4; ++kf2) {
            uint32_t pa[4];
            pa[0] = *reinterpret_cast<uint32_t*>(&pf[2 * kf2][0]);
            pa[1] = *reinterpret_cast<uint32_t*>(&pf[2 * kf2][1]);
            pa[2] = *reinterpret_cast<uint32_t*>(&pf[2 * kf2 + 1][0]);
            pa[3] = *reinterpret_cast<uint32_t*>(&pf[2 * kf2 + 1][1]);
            #pragma unroll
            for (int nf2 = 0; nf2 < 16; ++nf2) {
                const uint32_t boff = (uint32_t)((kf2 * 16 + vrow) * KSTR + nf2 * 8) * 2;
                uint32_t vv2[2];
                ldm_x2_trans(vv2, base + KV_TILE * 2 + boff);
                mma_f16(o[nf2], pa, vv2);
            }
        }
        __syncthreads();
    }

    const float inv0 = 1.f / l0s, inv1 = 1.f / l1s;
    const int row0 = n0 + wrow + g;
    #pragma unroll
    for (int nf2 = 0; nf2 < 16; ++nf2) {
        const int col = h * CHD + nf2 * 8 + tq * 2;
        const size_t off0 = (size_t)(b * CN + row0) * CD + col;
        const size_t off1 = (size_t)(b * CN + row0 + 8) * CD + col;
        *reinterpret_cast<__half2*>(&U[off0]) =
            __halves2half2(__float2half_rn(o[nf2][0] * inv0), __float2half_rn(o[nf2][1] * inv0));
        *reinterpret_cast<__half2*>(&U[off1]) =
            __halves2half2(__float2half_rn(o[nf2][2] * inv1), __float2half_rn(o[nf2][3] * inv1));
    }
}

// =============================================================================
// precompute kernels
// =============================================================================
__global__ __launch_bounds__(256)
void to_half2(const float* __restrict__ x0, __half* __restrict__ h0,
              const float* __restrict__ x1, __half* __restrict__ h1, size_t n)
{
    const float* x = blockIdx.z ? x1 : x0;
    __half* hh = blockIdx.z ? h1 : h0;
    const size_t stride = (size_t)gridDim.x * blockDim.x * 4;
    for (size_t i = ((size_t)blockIdx.x * blockDim.x + threadIdx.x) * 4; i < n; i += stride) {
        float4 v = *reinterpret_cast<const float4*>(x + i);
        *reinterpret_cast<__half2*>(hh + i) =
            __halves2half2(__float2half_rn(v.x), __float2half_rn(v.y));
        *reinterpret_cast<__half2*>(hh + i + 2) =
            __halves2half2(__float2half_rn(v.z), __float2half_rn(v.w));
    }
}

// All four weight transposes in one launch; flattened 1D grid.
// Segments: Wv [1024x3072] 3072 tiles, Wq 3072, Wvo [2048x1024] 2048, Wqo 2048.
__global__ __launch_bounds__(256)
void transpose_all(const float* __restrict__ Wv, const float* __restrict__ Wq,
                   const float* __restrict__ Wvo, const float* __restrict__ Wqo,
                   __half* __restrict__ Tv, __half* __restrict__ Tq,
                   __half* __restrict__ Tvo, __half* __restrict__ Tqo)
{
    const int bid = blockIdx.x;
    const float* W; __half* T; int K, N, local;
    if (bid < 3072)      { W = Wv;  T = Tv;  K = 1024; N = 3072; local = bid; }
    else if (bid < 6144) { W = Wq;  T = Tq;  K = 1024; N = 3072; local = bid - 3072; }
    else if (bid < 8192) { W = Wvo; T = Tvo; K = 2048; N = 1024; local = bid - 6144; }
    else                 { W = Wqo; T = Tqo; K = 2048; N = 1024; local = bid - 8192; }
    const int ntiles = N / 32;
    const int k0 = (local / ntiles) * 32, n0 = (local % ntiles) * 32;

    __shared__ float t[32][33];
    const int tx = threadIdx.x & 31, ty = threadIdx.x >> 5;
    for (int i = ty; i < 32; i += 8)
        t[i][tx] = W[(size_t)(k0 + i) * N + n0 + tx];
    __syncthreads();
    for (int i = ty; i < 32; i += 8)
        T[(size_t)(n0 + i) * K + k0 + tx] = __float2half_rn(t[tx][i]);
}

// =============================================================================
// launch
// =============================================================================
extern "C" void kernel_launch(void* const* d_in, const int* in_sizes, int n_in,
                              void* d_out, int out_size)
{
    const float* v   = (const float*)d_in[0];
    const float* q   = (const float*)d_in[1];
    const float* Wv  = (const float*)d_in[2];
    const float* bv  = (const float*)d_in[3];
    const float* Wq  = (const float*)d_in[4];
    const float* bq  = (const float*)d_in[5];
    const float* Wvo = (const float*)d_in[6];
    const float* bvo = (const float*)d_in[7];
    const float* Wqo = (const float*)d_in[8];
    const float* bqo = (const float*)d_in[9];
    float* out = (float*)d_out;

    __half *vt, *qt, *vh, *qh, *vu, *qu, *Wvt, *Wqt, *Wvot, *Wqot;
    cudaGetSymbolAddress((void**)&vt, g_vt);   cudaGetSymbolAddress((void**)&qt, g_qt);
    cudaGetSymbolAddress((void**)&vh, g_vh);   cudaGetSymbolAddress((void**)&qh, g_qh);
    cudaGetSymbolAddress((void**)&vu, g_vu);   cudaGetSymbolAddress((void**)&qu, g_qu);
    cudaGetSymbolAddress((void**)&Wvt, g_Wvt); cudaGetSymbolAddress((void**)&Wqt, g_Wqt);
    cudaGetSymbolAddress((void**)&Wvot, g_Wvot); cudaGetSymbolAddress((void**)&Wqot, g_Wqot);

    cudaFuncSetAttribute(gemm_in,  cudaFuncAttributeMaxDynamicSharedMemorySize, GEMM_SMEM);
    cudaFuncSetAttribute(gemm_out, cudaFuncAttributeMaxDynamicSharedMemorySize, GEMM_SMEM);
    cudaFuncSetAttribute(fused_attn, cudaFuncAttributeMaxDynamicSharedMemorySize, ATT_SMEM);

    const dim3 t256(256);
    const float scale = 0.08838834764831845f;   // 1/sqrt(128)
    const size_t nVD = (size_t)CM * CD;
    const size_t half = (size_t)CM * CD;

    // prep
    to_half2<<<dim3(1024, 1, 2), t256>>>(v, vh, q, qh, nVD);
    transpose_all<<<10240, t256>>>(Wv, Wq, Wvo, Wqo, Wvt, Wqt, Wvot, Wqot);

    // input transforms (both modalities)
    gemm_in<<<dim3(C3D / 128, CM / 128, 2), t256, GEMM_SMEM>>>(
        vh, qh, Wvt, Wqt, bv, bq, vt, qt, CM, C3D, CD);

    // fused attention, both directions
    fused_attn<<<dim3(CN / 128, CB * CH, 2), t256, ATT_SMEM>>>(
        vt, qt, vu, qt, vt, qu, scale);

    // output transforms (virtual concat), both modalities
    gemm_out<<<dim3(CD / 128, CM / 128, 2), t256, GEMM_SMEM>>>(
        vh, vu, qh, qu, CD, Wvot, Wqot, bvo, bqo, out, half, CM, CD, 2 * CD);
}

// round 10
// speedup vs baseline: 8.3763x; 1.0139x over previous
#include <cuda_runtime.h>
#include <cuda_fp16.h>
#include <cstdint>
#include <math.h>

// Problem constants
constexpr int CB  = 32;
constexpr int CN  = 512;
constexpr int CD  = 1024;
constexpr int CH  = 8;
constexpr int CHD = 128;
constexpr int C3D = 3 * CD;
constexpr int CM  = CB * CN;   // 16384

// ---------------- scratch (device globals) ----------------------------------
__device__ __half g_vt[(size_t)CM * C3D];
__device__ __half g_qt[(size_t)CM * C3D];
__device__ __half g_vh[(size_t)CM * CD],  g_qh[(size_t)CM * CD];
__device__ __half g_vu[(size_t)CM * CD],  g_qu[(size_t)CM * CD];
__device__ __half g_Wvt[(size_t)C3D * CD],     g_Wqt[(size_t)C3D * CD];
__device__ __half g_Wvot[(size_t)CD * 2 * CD], g_Wqot[(size_t)CD * 2 * CD];

// ---------------- base-ISA PTX helpers ---------------------------------------
__device__ __forceinline__ uint32_t smem_u32(const void* p) {
    uint32_t a;
    asm("{ .reg .u64 t; cvta.to.shared.u64 t, %1; cvt.u32.u64 %0, t; }" : "=r"(a) : "l"(p));
    return a;
}
__device__ __forceinline__ void cp_async16(uint32_t dst, const void* src) {
    asm volatile("cp.async.cg.shared.global [%0], [%1], 16;" :: "r"(dst), "l"(src) : "memory");
}
__device__ __forceinline__ void cp_commit() { asm volatile("cp.async.commit_group;" ::: "memory"); }
template <int N>
__device__ __forceinline__ void cp_wait() { asm volatile("cp.async.wait_group %0;" :: "n"(N) : "memory"); }

__device__ __forceinline__ void ldm_x4(uint32_t* r, uint32_t addr) {
    asm volatile("ldmatrix.sync.aligned.m8n8.x4.shared.b16 {%0,%1,%2,%3}, [%4];"
        : "=r"(r[0]), "=r"(r[1]), "=r"(r[2]), "=r"(r[3]) : "r"(addr));
}
__device__ __forceinline__ void ldm_x4_trans(uint32_t* r, uint32_t addr) {
    asm volatile("ldmatrix.sync.aligned.m8n8.x4.trans.shared.b16 {%0,%1,%2,%3}, [%4];"
        : "=r"(r[0]), "=r"(r[1]), "=r"(r[2]), "=r"(r[3]) : "r"(addr));
}
__device__ __forceinline__ void mma_f16(float* c, const uint32_t* a, const uint32_t* b) {
    asm volatile("mma.sync.aligned.m16n8k16.row.col.f32.f16.f16.f32 "
        "{%0,%1,%2,%3}, {%4,%5,%6,%7}, {%8,%9}, {%0,%1,%2,%3};"
        : "+f"(c[0]), "+f"(c[1]), "+f"(c[2]), "+f"(c[3])
        : "r"(a[0]), "r"(a[1]), "r"(a[2]), "r"(a[3]), "r"(b[0]), "r"(b[1]));
}

// Weight-GEMM tiling: CTA 128x128, BK=64, 8 warps 2Mx4N, 3-stage, 2 CTAs/SM
constexpr int TSTR    = 72;
constexpr int TILE_H  = 128 * TSTR;
constexpr int STAGE_H = 2 * TILE_H;
constexpr int GEMM_SMEM = 3 * STAGE_H * 2;   // 110592 B

// =============================================================================
// stage-1 GEMM (merged v/q): C = fp16(relu(A @ W + bias))
// =============================================================================
__global__ __launch_bounds__(256, 2)
void gemm_in(const __half* __restrict__ A0g, const __half* __restrict__ A1g,
             const __half* __restrict__ B0g, const __half* __restrict__ B1g,
             const float* __restrict__ bias0, const float* __restrict__ bias1,
             __half* __restrict__ C0g, __half* __restrict__ C1g,
             int M, int N, int K)
{
    extern __shared__ __half sm[];
    const uint32_t smb = smem_u32(sm);
    const int tid = threadIdx.x, wid = tid >> 5, lane = tid & 31;
    const int z = blockIdx.z;
    const __half* Ag = z ? A1g : A0g;
    const __half* Bg = z ? B1g : B0g;
    const float* bias = z ? bias1 : bias0;
    __half* Cg = z ? C1g : C0g;

    const int bm0 = blockIdx.y * 128, bn0 = blockIdx.x * 128;
    const int nk = K / 64;
    const int mw = (wid & 1) * 64, nw = (wid >> 1) * 32;

    auto load_stage = [&](int kc, int buf) {
        const int kk = kc * 64;
        const __half* a = Ag + (size_t)bm0 * K + kk;
        const __half* b = Bg + (size_t)bn0 * K + kk;
        const uint32_t base = smb + (uint32_t)buf * STAGE_H * 2;
        #pragma unroll
        for (int i = 0; i < 4; ++i) {
            const int idx = tid + i * 256;
            const int r = idx >> 3, c = (idx & 7) * 8;
            const uint32_t doff = (uint32_t)(r * TSTR + c) * 2;
            cp_async16(base + doff,              a + (size_t)r * K + c);
            cp_async16(base + TILE_H * 2 + doff, b + (size_t)r * K + c);
        }
        cp_commit();
    };

    float acc[4][4][4] = {};
    const int arow = lane & 15, acol = (lane >> 4) * 8;
    // x4 B addressing: two n8 blocks per load
    const int bq_row = (lane & 7) + ((lane >> 4) & 1) * 8;   // n within 16
    const int bq_col = ((lane >> 3) & 1) * 8;                // k half-block

    load_stage(0, 0);
    load_stage(1, 1);
    for (int kc = 0; kc < nk; ++kc) {
        const int buf = kc % 3;
        if (kc + 1 < nk) cp_wait<1>(); else cp_wait<0>();
        __syncthreads();
        if (kc + 2 < nk) load_stage(kc + 2, (kc + 2) % 3);
        const uint32_t base = smb + (uint32_t)buf * STAGE_H * 2;
        #pragma unroll
        for (int ks = 0; ks < 4; ++ks) {
            const int k0 = ks * 16;
            uint32_t bb[2][4];
            #pragma unroll
            for (int p = 0; p < 2; ++p) {
                const uint32_t boff =
                    (uint32_t)((nw + p * 16 + bq_row) * TSTR + k0 + bq_col) * 2;
                ldm_x4(bb[p], base + TILE_H * 2 + boff);
            }
            #pragma unroll
            for (int mi = 0; mi < 4; ++mi) {
                uint32_t ah[4];
                const uint32_t aoff = (uint32_t)((mw + mi * 16 + arow) * TSTR + k0 + acol) * 2;
                ldm_x4(ah, base + aoff);
                #pragma unroll
                for (int p = 0; p < 2; ++p) {
                    mma_f16(acc[mi][2 * p],     ah, &bb[p][0]);
                    mma_f16(acc[mi][2 * p + 1], ah, &bb[p][2]);
                }
            }
        }
    }

    const int g = lane >> 2, tq = lane & 3;
    #pragma unroll
    for (int mi = 0; mi < 4; ++mi) {
        const int row0 = bm0 + mw + mi * 16 + g;
        #pragma unroll
        for (int ni = 0; ni < 4; ++ni) {
            const int col = bn0 + nw + ni * 8 + tq * 2;
            const float b0 = __ldg(&bias[col]), b1 = __ldg(&bias[col + 1]);
            *reinterpret_cast<__half2*>(&Cg[(size_t)row0 * N + col]) = __halves2half2(
                __float2half_rn(fmaxf(acc[mi][ni][0] + b0, 0.f)),
                __float2half_rn(fmaxf(acc[mi][ni][1] + b1, 0.f)));
            *reinterpret_cast<__half2*>(&Cg[(size_t)(row0 + 8) * N + col]) = __halves2half2(
                __float2half_rn(fmaxf(acc[mi][ni][2] + b0, 0.f)),
                __float2half_rn(fmaxf(acc[mi][ni][3] + b1, 0.f)));
        }
    }
}

// =============================================================================
// stage-5 GEMM (merged v/q): C = relu(concat(A0,A1) @ W + bias), fp32 out
// =============================================================================
__global__ __launch_bounds__(256, 2)
void gemm_out(const __half* __restrict__ A0v, const __half* __restrict__ A1v,
              const __half* __restrict__ A0q, const __half* __restrict__ A1q,
              int K0,
              const __half* __restrict__ Bv, const __half* __restrict__ Bq,
              const float* __restrict__ biasv, const float* __restrict__ biasq,
              float* __restrict__ C, size_t zoff,
              int M, int N, int K)
{
    extern __shared__ __half sm[];
    const uint32_t smb = smem_u32(sm);
    const int tid = threadIdx.x, wid = tid >> 5, lane = tid & 31;
    const int z = blockIdx.z;
    const __half* A0g = z ? A0q : A0v;
    const __half* A1g = z ? A1q : A1v;
    const __half* Bg  = z ? Bq  : Bv;
    const float* bias = z ? biasq : biasv;
    float* Cg = C + (size_t)z * zoff;

    const int bm0 = blockIdx.y * 128, bn0 = blockIdx.x * 128;
    const int nk = K / 64, K1 = K - K0;
    const int mw = (wid & 1) * 64, nw = (wid >> 1) * 32;

    auto load_stage = [&](int kc, int buf) {
        const int kk = kc * 64;
        const __half* a; int ldA, ka;
        if (kk < K0) { a = A0g; ldA = K0; ka = kk; }
        else         { a = A1g; ldA = K1; ka = kk - K0; }
        a += (size_t)bm0 * ldA + ka;
        const __half* b = Bg + (size_t)bn0 * K + kk;
        const uint32_t base = smb + (uint32_t)buf * STAGE_H * 2;
        #pragma unroll
        for (int i = 0; i < 4; ++i) {
            const int idx = tid + i * 256;
            const int r = idx >> 3, c = (idx & 7) * 8;
            const uint32_t doff = (uint32_t)(r * TSTR + c) * 2;
            cp_async16(base + doff,              a + (size_t)r * ldA + c);
            cp_async16(base + TILE_H * 2 + doff, b + (size_t)r * K + c);
        }
        cp_commit();
    };

    float acc[4][4][4] = {};
    const int arow = lane & 15, acol = (lane >> 4) * 8;
    const int bq_row = (lane & 7) + ((lane >> 4) & 1) * 8;
    const int bq_col = ((lane >> 3) & 1) * 8;

    load_stage(0, 0);
    load_stage(1, 1);
    for (int kc = 0; kc < nk; ++kc) {
        const int buf = kc % 3;
        if (kc + 1 < nk) cp_wait<1>(); else cp_wait<0>();
        __syncthreads();
        if (kc + 2 < nk) load_stage(kc + 2, (kc + 2) % 3);
        const uint32_t base = smb + (uint32_t)buf * STAGE_H * 2;
        #pragma unroll
        for (int ks = 0; ks < 4; ++ks) {
            const int k0 = ks * 16;
            uint32_t bb[2][4];
            #pragma unroll
            for (int p = 0; p < 2; ++p) {
                const uint32_t boff =
                    (uint32_t)((nw + p * 16 + bq_row) * TSTR + k0 + bq_col) * 2;
                ldm_x4(bb[p], base + TILE_H * 2 + boff);
            }
            #pragma unroll
            for (int mi = 0; mi < 4; ++mi) {
                uint32_t ah[4];
                const uint32_t aoff = (uint32_t)((mw + mi * 16 + arow) * TSTR + k0 + acol) * 2;
                ldm_x4(ah, base + aoff);
                #pragma unroll
                for (int p = 0; p < 2; ++p) {
                    mma_f16(acc[mi][2 * p],     ah, &bb[p][0]);
                    mma_f16(acc[mi][2 * p + 1], ah, &bb[p][2]);
                }
            }
        }
    }

    const int g = lane >> 2, tq = lane & 3;
    #pragma unroll
    for (int mi = 0; mi < 4; ++mi) {
        const int row0 = bm0 + mw + mi * 16 + g;
        #pragma unroll
        for (int ni = 0; ni < 4; ++ni) {
            const int col = bn0 + nw + ni * 8 + tq * 2;
            const float b0 = __ldg(&bias[col]), b1 = __ldg(&bias[col + 1]);
            float2 o0, o1;
            o0.x = fmaxf(acc[mi][ni][0] + b0, 0.f);
            o0.y = fmaxf(acc[mi][ni][1] + b1, 0.f);
            o1.x = fmaxf(acc[mi][ni][2] + b0, 0.f);
            o1.y = fmaxf(acc[mi][ni][3] + b1, 0.f);
            *reinterpret_cast<float2*>(&Cg[(size_t)row0 * N + col]) = o0;
            *reinterpret_cast<float2*>(&Cg[(size_t)(row0 + 8) * N + col]) = o1;
        }
    }
}

// =============================================================================
// Fused flash attention (merged directions) with x4 K/V fragment loads
// =============================================================================
constexpr int QSTR = 136;
constexpr int KSTR = 136;
constexpr int Q_HLV = 128 * QSTR;
constexpr int KV_TILE = 64 * KSTR;
constexpr int KV_STAGE = 2 * KV_TILE;
constexpr int ATT_SMEM = (Q_HLV + 2 * KV_STAGE) * 2;   // 104448 B

__global__ __launch_bounds__(256, 1)
void fused_attn(const __half* __restrict__ Ta0, const __half* __restrict__ Tb0,
                __half* __restrict__ U0,
                const __half* __restrict__ Ta1, const __half* __restrict__ Tb1,
                __half* __restrict__ U1, float scale)
{
    extern __shared__ __half sm[];
    const uint32_t smb = smem_u32(sm);
    const int tid = threadIdx.x, wid = tid >> 5, lane = tid & 31;
    const int z = blockIdx.z;
    const __half* Ta = z ? Ta1 : Ta0;
    const __half* Tb = z ? Tb1 : Tb0;
    __half* U = z ? U1 : U0;

    const int bz = blockIdx.y, b = bz >> 3, h = bz & 7;
    const int n0 = blockIdx.x * 128;
    const int wrow = wid * 16;

    const size_t qbase = (size_t)(b * CN + n0) * C3D + CD + h * CHD;
    const size_t kbase = (size_t)b * CN * C3D + h * CHD;
    const size_t vbase = (size_t)b * CN * C3D + 2 * CD + h * CHD;

    auto load_q = [&]() {
        #pragma unroll
        for (int i = 0; i < 8; ++i) {
            const int idx = tid + i * 256;
            const int r = idx >> 4, c = (idx & 15) * 8;
            cp_async16(smb + (uint32_t)(r * QSTR + c) * 2,
                       Ta + qbase + (size_t)r * C3D + c);
        }
        cp_commit();
    };
    auto load_kv = [&](int mc, int buf) {
        const int m0 = mc * 64;
        const uint32_t base = smb + (uint32_t)(Q_HLV + buf * KV_STAGE) * 2;
        const __half* kp = Tb + kbase + (size_t)m0 * C3D;
        const __half* vp = Tb + vbase + (size_t)m0 * C3D;
        #pragma unroll
        for (int i = 0; i < 4; ++i) {
            const int idx = tid + i * 256;
            const int r = idx >> 4, c = (idx & 15) * 8;
            const uint32_t doff = (uint32_t)(r * KSTR + c) * 2;
            cp_async16(base + doff,               kp + (size_t)r * C3D + c);
            cp_async16(base + KV_TILE * 2 + doff, vp + (size_t)r * C3D + c);
        }
        cp_commit();
    };

    load_q();
    load_kv(0, 0);
    cp_wait<1>();
    __syncthreads();

    const int arow = lane & 15, acol = (lane >> 4) * 8;
    uint32_t qf[8][4];
    #pragma unroll
    for (int kf = 0; kf < 8; ++kf)
        ldm_x4(qf[kf], smb + (uint32_t)((wrow + arow) * QSTR + kf * 16 + acol) * 2);

    const int g = lane >> 2, tq = lane & 3;
    const int bq_row = (lane & 7) + ((lane >> 4) & 1) * 8;   // n within 16 (x4 B)
    const int bq_col = ((lane >> 3) & 1) * 8;                // k half-block
    const int vq_row = lane & 15;                            // k row (x4 trans V)
    const int vq_col = ((lane >> 4) & 1) * 8;                // n half-block

    float m0s = -1e30f, m1s = -1e30f, l0s = 0.f, l1s = 0.f;
    float o[16][4] = {};

    for (int mc = 0; mc < 8; ++mc) {
        const int buf = mc & 1;
        if (mc + 1 < 8) { load_kv(mc + 1, buf ^ 1); cp_wait<1>(); }
        else            { cp_wait<0>(); }
        __syncthreads();

        const uint32_t base = smb + (uint32_t)(Q_HLV + buf * KV_STAGE) * 2;

        // ---- S = Q K^T (64 cols); K frags via x4 (two n8 per load) ----
        float s[8][4] = {};
        #pragma unroll
        for (int kf = 0; kf < 8; ++kf) {
            #pragma unroll
            for (int p = 0; p < 4; ++p) {
                const uint32_t boff =
                    (uint32_t)((p * 16 + bq_row) * KSTR + kf * 16 + bq_col) * 2;
                uint32_t kk4[4];
                ldm_x4(kk4, base + boff);
                mma_f16(s[2 * p],     qf[kf], &kk4[0]);
                mma_f16(s[2 * p + 1], qf[kf], &kk4[2]);
            }
        }

        // ---- online softmax ----
        float mx0 = -1e30f, mx1 = -1e30f;
        #pragma unroll
        for (int nf = 0; nf < 8; ++nf) {
            mx0 = fmaxf(mx0, fmaxf(s[nf][0], s[nf][1]));
            mx1 = fmaxf(mx1, fmaxf(s[nf][2], s[nf][3]));
        }
        mx0 = fmaxf(mx0, __shfl_xor_sync(0xffffffffu, mx0, 1));
        mx0 = fmaxf(mx0, __shfl_xor_sync(0xffffffffu, mx0, 2));
        mx1 = fmaxf(mx1, __shfl_xor_sync(0xffffffffu, mx1, 1));
        mx1 = fmaxf(mx1, __shfl_xor_sync(0xffffffffu, mx1, 2));
        mx0 *= scale; mx1 *= scale;
        const float mn0 = fmaxf(m0s, mx0), mn1 = fmaxf(m1s, mx1);
        const float a0 = __expf(m0s - mn0), a1 = __expf(m1s - mn1);
        m0s = mn0; m1s = mn1;

        float rs0 = 0.f, rs1 = 0.f;
        __half2 pf[8][2];
        #pragma unroll
        for (int nf = 0; nf < 8; ++nf) {
            const float p0 = __expf(s[nf][0] * scale - mn0);
            const float p1 = __expf(s[nf][1] * scale - mn0);
            const float p2 = __expf(s[nf][2] * scale - mn1);
            const float p3 = __expf(s[nf][3] * scale - mn1);
            rs0 += p0 + p1; rs1 += p2 + p3;
            pf[nf][0] = __halves2half2(__float2half_rn(p0), __float2half_rn(p1));
            pf[nf][1] = __halves2half2(__float2half_rn(p2), __float2half_rn(p3));
        }
        rs0 += __shfl_xor_sync(0xffffffffu, rs0, 1);
        rs0 += __shfl_xor_sync(0xffffffffu, rs0, 2);
        rs1 += __shfl_xor_sync(0xffffffffu, rs1, 1);
        rs1 += __shfl_xor_sync(0xffffffffu, rs1, 2);
        l0s = l0s * a0 + rs0;
        l1s = l1s * a1 + rs1;

        #pragma unroll
        for (int nf2 = 0; nf2 < 16; ++nf2) {
            o[nf2][0] *= a0; o[nf2][1] *= a0;
            o[nf2][2] *= a1; o[nf2][3] *= a1;
        }

        // ---- O += P V; V frags via x4.trans (two n8 per load) ----
        #pragma unroll
        for (int kf2 = 0; kf2 < 4; ++kf2) {
            uint32_t pa[4];
            pa[0] = *reinterpret_cast<uint32_t*>(&pf[2 * kf2][0]);
            pa[1] = *reinterpret_cast<uint32_t*>(&pf[2 * kf2][1]);
            pa[2] = *reinterpret_cast<uint32_t*>(&pf[2 * kf2 + 1][0]);
            pa[3] = *reinterpret_cast<uint32_t*>(&pf[2 * kf2 + 1][1]);
            #pragma unroll
            for (int p = 0; p < 8; ++p) {
                const uint32_t boff =
                    (uint32_t)((kf2 * 16 + vq_row) * KSTR + p * 16 + vq_col) * 2;
                uint32_t vv4[4];
                ldm_x4_trans(vv4, base + KV_TILE * 2 + boff);
                mma_f16(o[2 * p],     pa, &vv4[0]);
                mma_f16(o[2 * p + 1], pa, &vv4[2]);
            }
        }
        __syncthreads();
    }

    const float inv0 = 1.f / l0s, inv1 = 1.f / l1s;
    const int row0 = n0 + wrow + g;
    #pragma unroll
    for (int nf2 = 0; nf2 < 16; ++nf2) {
        const int col = h * CHD + nf2 * 8 + tq * 2;
        const size_t off0 = (size_t)(b * CN + row0) * CD + col;
        const size_t off1 = (size_t)(b * CN + row0 + 8) * CD + col;
        *reinterpret_cast<__half2*>(&U[off0]) =
            __halves2half2(__float2half_rn(o[nf2][0] * inv0), __float2half_rn(o[nf2][1] * inv0));
        *reinterpret_cast<__half2*>(&U[off1]) =
            __halves2half2(__float2half_rn(o[nf2][2] * inv1), __float2half_rn(o[nf2][3] * inv1));
    }
}

// =============================================================================
// precompute kernels
// =============================================================================
__global__ __launch_bounds__(256)
void to_half2(const float* __restrict__ x0, __half* __restrict__ h0,
              const float* __restrict__ x1, __half* __restrict__ h1, size_t n)
{
    const float* x = blockIdx.z ? x1 : x0;
    __half* hh = blockIdx.z ? h1 : h0;
    const size_t stride = (size_t)gridDim.x * blockDim.x * 4;
    for (size_t i = ((size_t)blockIdx.x * blockDim.x + threadIdx.x) * 4; i < n; i += stride) {
        float4 v = *reinterpret_cast<const float4*>(x + i);
        *reinterpret_cast<__half2*>(hh + i) =
            __halves2half2(__float2half_rn(v.x), __float2half_rn(v.y));
        *reinterpret_cast<__half2*>(hh + i + 2) =
            __halves2half2(__float2half_rn(v.z), __float2half_rn(v.w));
    }
}

__global__ __launch_bounds__(256)
void transpose_all(const float* __restrict__ Wv, const float* __restrict__ Wq,
                   const float* __restrict__ Wvo, const float* __restrict__ Wqo,
                   __half* __restrict__ Tv, __half* __restrict__ Tq,
                   __half* __restrict__ Tvo, __half* __restrict__ Tqo)
{
    const int bid = blockIdx.x;
    const float* W; __half* T; int K, N, local;
    if (bid < 3072)      { W = Wv;  T = Tv;  K = 1024; N = 3072; local = bid; }
    else if (bid < 6144) { W = Wq;  T = Tq;  K = 1024; N = 3072; local = bid - 3072; }
    else if (bid < 8192) { W = Wvo; T = Tvo; K = 2048; N = 1024; local = bid - 6144; }
    else                 { W = Wqo; T = Tqo; K = 2048; N = 1024; local = bid - 8192; }
    const int ntiles = N / 32;
    const int k0 = (local / ntiles) * 32, n0 = (local % ntiles) * 32;

    __shared__ float t[32][33];
    const int tx = threadIdx.x & 31, ty = threadIdx.x >> 5;
    for (int i = ty; i < 32; i += 8)
        t[i][tx] = W[(size_t)(k0 + i) * N + n0 + tx];
    __syncthreads();
    for (int i = ty; i < 32; i += 8)
        T[(size_t)(n0 + i) * K + k0 + tx] = __float2half_rn(t[tx][i]);
}

// =============================================================================
// launch
// =============================================================================
extern "C" void kernel_launch(void* const* d_in, const int* in_sizes, int n_in,
                              void* d_out, int out_size)
{
    const float* v   = (const float*)d_in[0];
    const float* q   = (const float*)d_in[1];
    const float* Wv  = (const float*)d_in[2];
    const float* bv  = (const float*)d_in[3];
    const float* Wq  = (const float*)d_in[4];
    const float* bq  = (const float*)d_in[5];
    const float* Wvo = (const float*)d_in[6];
    const float* bvo = (const float*)d_in[7];
    const float* Wqo = (const float*)d_in[8];
    const float* bqo = (const float*)d_in[9];
    float* out = (float*)d_out;

    __half *vt, *qt, *vh, *qh, *vu, *qu, *Wvt, *Wqt, *Wvot, *Wqot;
    cudaGetSymbolAddress((void**)&vt, g_vt);   cudaGetSymbolAddress((void**)&qt, g_qt);
    cudaGetSymbolAddress((void**)&vh, g_vh);   cudaGetSymbolAddress((void**)&qh, g_qh);
    cudaGetSymbolAddress((void**)&vu, g_vu);   cudaGetSymbolAddress((void**)&qu, g_qu);
    cudaGetSymbolAddress((void**)&Wvt, g_Wvt); cudaGetSymbolAddress((void**)&Wqt, g_Wqt);
    cudaGetSymbolAddress((void**)&Wvot, g_Wvot); cudaGetSymbolAddress((void**)&Wqot, g_Wqot);

    cudaFuncSetAttribute(gemm_in,  cudaFuncAttributeMaxDynamicSharedMemorySize, GEMM_SMEM);
    cudaFuncSetAttribute(gemm_out, cudaFuncAttributeMaxDynamicSharedMemorySize, GEMM_SMEM);
    cudaFuncSetAttribute(fused_attn, cudaFuncAttributeMaxDynamicSharedMemorySize, ATT_SMEM);

    const dim3 t256(256);
    const float scale = 0.08838834764831845f;   // 1/sqrt(128)
    const size_t nVD = (size_t)CM * CD;
    const size_t half = (size_t)CM * CD;

    // prep
    to_half2<<<dim3(1024, 1, 2), t256>>>(v, vh, q, qh, nVD);
    transpose_all<<<10240, t256>>>(Wv, Wq, Wvo, Wqo, Wvt, Wqt, Wvot, Wqot);

    // input transforms (both modalities)
    gemm_in<<<dim3(C3D / 128, CM / 128, 2), t256, GEMM_SMEM>>>(
        vh, qh, Wvt, Wqt, bv, bq, vt, qt, CM, C3D, CD);

    // fused attention, both directions
    fused_attn<<<dim3(CN / 128, CB * CH, 2), t256, ATT_SMEM>>>(
        vt, qt, vu, qt, vt, qu, scale);

    // output transforms (virtual concat), both modalities
    gemm_out<<<dim3(CD / 128, CM / 128, 2), t256, GEMM_SMEM>>>(
        vh, vu, qh, qu, CD, Wvot, Wqot, bvo, bqo, out, half, CM, CD, 2 * CD);
}

// round 11
// speedup vs baseline: 8.5472x; 1.0204x over previous
#include <cuda_runtime.h>
#include <cuda_fp16.h>
#include <cstdint>
#include <math.h>

// Problem constants
constexpr int CB  = 32;
constexpr int CN  = 512;
constexpr int CD  = 1024;
constexpr int CH  = 8;
constexpr int CHD = 128;
constexpr int C3D = 3 * CD;
constexpr int CM  = CB * CN;   // 16384

// ---------------- scratch (device globals) ----------------------------------
__device__ __half g_vt[(size_t)CM * C3D];
__device__ __half g_qt[(size_t)CM * C3D];
__device__ __half g_vh[(size_t)CM * CD],  g_qh[(size_t)CM * CD];
__device__ __half g_vu[(size_t)CM * CD],  g_qu[(size_t)CM * CD];
__device__ __half g_Wvt[(size_t)C3D * CD],     g_Wqt[(size_t)C3D * CD];
__device__ __half g_Wvot[(size_t)CD * 2 * CD], g_Wqot[(size_t)CD * 2 * CD];

// ---------------- base-ISA PTX helpers ---------------------------------------
__device__ __forceinline__ uint32_t smem_u32(const void* p) {
    uint32_t a;
    asm("{ .reg .u64 t; cvta.to.shared.u64 t, %1; cvt.u32.u64 %0, t; }" : "=r"(a) : "l"(p));
    return a;
}
__device__ __forceinline__ void cp_async16(uint32_t dst, const void* src) {
    asm volatile("cp.async.cg.shared.global [%0], [%1], 16;" :: "r"(dst), "l"(src) : "memory");
}
__device__ __forceinline__ void cp_commit() { asm volatile("cp.async.commit_group;" ::: "memory"); }
template <int N>
__device__ __forceinline__ void cp_wait() { asm volatile("cp.async.wait_group %0;" :: "n"(N) : "memory"); }

__device__ __forceinline__ void ldm_x4(uint32_t* r, uint32_t addr) {
    asm volatile("ldmatrix.sync.aligned.m8n8.x4.shared.b16 {%0,%1,%2,%3}, [%4];"
        : "=r"(r[0]), "=r"(r[1]), "=r"(r[2]), "=r"(r[3]) : "r"(addr));
}
__device__ __forceinline__ void ldm_x4_trans(uint32_t* r, uint32_t addr) {
    asm volatile("ldmatrix.sync.aligned.m8n8.x4.trans.shared.b16 {%0,%1,%2,%3}, [%4];"
        : "=r"(r[0]), "=r"(r[1]), "=r"(r[2]), "=r"(r[3]) : "r"(addr));
}
__device__ __forceinline__ void mma_f16(float* c, const uint32_t* a, const uint32_t* b) {
    asm volatile("mma.sync.aligned.m16n8k16.row.col.f32.f16.f16.f32 "
        "{%0,%1,%2,%3}, {%4,%5,%6,%7}, {%8,%9}, {%0,%1,%2,%3};"
        : "+f"(c[0]), "+f"(c[1]), "+f"(c[2]), "+f"(c[3])
        : "r"(a[0]), "r"(a[1]), "r"(a[2]), "r"(a[3]), "r"(b[0]), "r"(b[1]));
}

// Weight-GEMM tiling: CTA 128x128, BK=64, 8 warps 2Mx4N, 3-stage, 2 CTAs/SM
constexpr int TSTR    = 72;
constexpr int TILE_H  = 128 * TSTR;
constexpr int STAGE_H = 2 * TILE_H;
constexpr int GEMM_SMEM = 3 * STAGE_H * 2;   // 110592 B

// =============================================================================
// stage-1 GEMM (merged v/q): C = fp16(relu(A @ W + bias))
// =============================================================================
__global__ __launch_bounds__(256, 2)
void gemm_in(const __half* __restrict__ A0g, const __half* __restrict__ A1g,
             const __half* __restrict__ B0g, const __half* __restrict__ B1g,
             const float* __restrict__ bias0, const float* __restrict__ bias1,
             __half* __restrict__ C0g, __half* __restrict__ C1g,
             int M, int N, int K)
{
    extern __shared__ __half sm[];
    const uint32_t smb = smem_u32(sm);
    const int tid = threadIdx.x, wid = tid >> 5, lane = tid & 31;
    const int z = blockIdx.z;
    const __half* Ag = z ? A1g : A0g;
    const __half* Bg = z ? B1g : B0g;
    const float* bias = z ? bias1 : bias0;
    __half* Cg = z ? C1g : C0g;

    const int bm0 = blockIdx.y * 128, bn0 = blockIdx.x * 128;
    const int nk = K / 64;
    const int mw = (wid & 1) * 64, nw = (wid >> 1) * 32;

    auto load_stage = [&](int kc, int buf) {
        const int kk = kc * 64;
        const __half* a = Ag + (size_t)bm0 * K + kk;
        const __half* b = Bg + (size_t)bn0 * K + kk;
        const uint32_t base = smb + (uint32_t)buf * STAGE_H * 2;
        #pragma unroll
        for (int i = 0; i < 4; ++i) {
            const int idx = tid + i * 256;
            const int r = idx >> 3, c = (idx & 7) * 8;
            const uint32_t doff = (uint32_t)(r * TSTR + c) * 2;
            cp_async16(base + doff,              a + (size_t)r * K + c);
            cp_async16(base + TILE_H * 2 + doff, b + (size_t)r * K + c);
        }
        cp_commit();
    };

    float acc[4][4][4] = {};
    const int arow = lane & 15, acol = (lane >> 4) * 8;
    const int bq_row = (lane & 7) + ((lane >> 4) & 1) * 8;
    const int bq_col = ((lane >> 3) & 1) * 8;

    load_stage(0, 0);
    load_stage(1, 1);
    for (int kc = 0; kc < nk; ++kc) {
        const int buf = kc % 3;
        if (kc + 1 < nk) cp_wait<1>(); else cp_wait<0>();
        __syncthreads();
        if (kc + 2 < nk) load_stage(kc + 2, (kc + 2) % 3);
        const uint32_t base = smb + (uint32_t)buf * STAGE_H * 2;
        #pragma unroll
        for (int ks = 0; ks < 4; ++ks) {
            const int k0 = ks * 16;
            uint32_t bb[2][4];
            #pragma unroll
            for (int p = 0; p < 2; ++p) {
                const uint32_t boff =
                    (uint32_t)((nw + p * 16 + bq_row) * TSTR + k0 + bq_col) * 2;
                ldm_x4(bb[p], base + TILE_H * 2 + boff);
            }
            #pragma unroll
            for (int mi = 0; mi < 4; ++mi) {
                uint32_t ah[4];
                const uint32_t aoff = (uint32_t)((mw + mi * 16 + arow) * TSTR + k0 + acol) * 2;
                ldm_x4(ah, base + aoff);
                #pragma unroll
                for (int p = 0; p < 2; ++p) {
                    mma_f16(acc[mi][2 * p],     ah, &bb[p][0]);
                    mma_f16(acc[mi][2 * p + 1], ah, &bb[p][2]);
                }
            }
        }
    }

    const int g = lane >> 2, tq = lane & 3;
    #pragma unroll
    for (int mi = 0; mi < 4; ++mi) {
        const int row0 = bm0 + mw + mi * 16 + g;
        #pragma unroll
        for (int ni = 0; ni < 4; ++ni) {
            const int col = bn0 + nw + ni * 8 + tq * 2;
            const float b0 = __ldg(&bias[col]), b1 = __ldg(&bias[col + 1]);
            *reinterpret_cast<__half2*>(&Cg[(size_t)row0 * N + col]) = __halves2half2(
                __float2half_rn(fmaxf(acc[mi][ni][0] + b0, 0.f)),
                __float2half_rn(fmaxf(acc[mi][ni][1] + b1, 0.f)));
            *reinterpret_cast<__half2*>(&Cg[(size_t)(row0 + 8) * N + col]) = __halves2half2(
                __float2half_rn(fmaxf(acc[mi][ni][2] + b0, 0.f)),
                __float2half_rn(fmaxf(acc[mi][ni][3] + b1, 0.f)));
        }
    }
}

// =============================================================================
// stage-5 GEMM (merged v/q): C = relu(concat(A0,A1) @ W + bias), fp32 out
// =============================================================================
__global__ __launch_bounds__(256, 2)
void gemm_out(const __half* __restrict__ A0v, const __half* __restrict__ A1v,
              const __half* __restrict__ A0q, const __half* __restrict__ A1q,
              int K0,
              const __half* __restrict__ Bv, const __half* __restrict__ Bq,
              const float* __restrict__ biasv, const float* __restrict__ biasq,
              float* __restrict__ C, size_t zoff,
              int M, int N, int K)
{
    extern __shared__ __half sm[];
    const uint32_t smb = smem_u32(sm);
    const int tid = threadIdx.x, wid = tid >> 5, lane = tid & 31;
    const int z = blockIdx.z;
    const __half* A0g = z ? A0q : A0v;
    const __half* A1g = z ? A1q : A1v;
    const __half* Bg  = z ? Bq  : Bv;
    const float* bias = z ? biasq : biasv;
    float* Cg = C + (size_t)z * zoff;

    const int bm0 = blockIdx.y * 128, bn0 = blockIdx.x * 128;
    const int nk = K / 64, K1 = K - K0;
    const int mw = (wid & 1) * 64, nw = (wid >> 1) * 32;

    auto load_stage = [&](int kc, int buf) {
        const int kk = kc * 64;
        const __half* a; int ldA, ka;
        if (kk < K0) { a = A0g; ldA = K0; ka = kk; }
        else         { a = A1g; ldA = K1; ka = kk - K0; }
        a += (size_t)bm0 * ldA + ka;
        const __half* b = Bg + (size_t)bn0 * K + kk;
        const uint32_t base = smb + (uint32_t)buf * STAGE_H * 2;
        #pragma unroll
        for (int i = 0; i < 4; ++i) {
            const int idx = tid + i * 256;
            const int r = idx >> 3, c = (idx & 7) * 8;
            const uint32_t doff = (uint32_t)(r * TSTR + c) * 2;
            cp_async16(base + doff,              a + (size_t)r * ldA + c);
            cp_async16(base + TILE_H * 2 + doff, b + (size_t)r * K + c);
        }
        cp_commit();
    };

    float acc[4][4][4] = {};
    const int arow = lane & 15, acol = (lane >> 4) * 8;
    const int bq_row = (lane & 7) + ((lane >> 4) & 1) * 8;
    const int bq_col = ((lane >> 3) & 1) * 8;

    load_stage(0, 0);
    load_stage(1, 1);
    for (int kc = 0; kc < nk; ++kc) {
        const int buf = kc % 3;
        if (kc + 1 < nk) cp_wait<1>(); else cp_wait<0>();
        __syncthreads();
        if (kc + 2 < nk) load_stage(kc + 2, (kc + 2) % 3);
        const uint32_t base = smb + (uint32_t)buf * STAGE_H * 2;
        #pragma unroll
        for (int ks = 0; ks < 4; ++ks) {
            const int k0 = ks * 16;
            uint32_t bb[2][4];
            #pragma unroll
            for (int p = 0; p < 2; ++p) {
                const uint32_t boff =
                    (uint32_t)((nw + p * 16 + bq_row) * TSTR + k0 + bq_col) * 2;
                ldm_x4(bb[p], base + TILE_H * 2 + boff);
            }
            #pragma unroll
            for (int mi = 0; mi < 4; ++mi) {
                uint32_t ah[4];
                const uint32_t aoff = (uint32_t)((mw + mi * 16 + arow) * TSTR + k0 + acol) * 2;
                ldm_x4(ah, base + aoff);
                #pragma unroll
                for (int p = 0; p < 2; ++p) {
                    mma_f16(acc[mi][2 * p],     ah, &bb[p][0]);
                    mma_f16(acc[mi][2 * p + 1], ah, &bb[p][2]);
                }
            }
        }
    }

    const int g = lane >> 2, tq = lane & 3;
    #pragma unroll
    for (int mi = 0; mi < 4; ++mi) {
        const int row0 = bm0 + mw + mi * 16 + g;
        #pragma unroll
        for (int ni = 0; ni < 4; ++ni) {
            const int col = bn0 + nw + ni * 8 + tq * 2;
            const float b0 = __ldg(&bias[col]), b1 = __ldg(&bias[col + 1]);
            float2 o0, o1;
            o0.x = fmaxf(acc[mi][ni][0] + b0, 0.f);
            o0.y = fmaxf(acc[mi][ni][1] + b1, 0.f);
            o1.x = fmaxf(acc[mi][ni][2] + b0, 0.f);
            o1.y = fmaxf(acc[mi][ni][3] + b1, 0.f);
            *reinterpret_cast<float2*>(&Cg[(size_t)row0 * N + col]) = o0;
            *reinterpret_cast<float2*>(&Cg[(size_t)(row0 + 8) * N + col]) = o1;
        }
    }
}

// =============================================================================
// Fused flash attention — 2 CTAs/SM via register diet (Q frags reloaded from
// smem per chunk instead of held in registers).
// =============================================================================
constexpr int QSTR = 136;
constexpr int KSTR = 136;
constexpr int Q_HLV = 128 * QSTR;
constexpr int KV_TILE = 64 * KSTR;
constexpr int KV_STAGE = 2 * KV_TILE;
constexpr int ATT_SMEM = (Q_HLV + 2 * KV_STAGE) * 2;   // 104448 B

__global__ __launch_bounds__(256, 2)
void fused_attn(const __half* __restrict__ Ta0, const __half* __restrict__ Tb0,
                __half* __restrict__ U0,
                const __half* __restrict__ Ta1, const __half* __restrict__ Tb1,
                __half* __restrict__ U1, float scale)
{
    extern __shared__ __half sm[];
    const uint32_t smb = smem_u32(sm);
    const int tid = threadIdx.x, wid = tid >> 5, lane = tid & 31;
    const int z = blockIdx.z;
    const __half* Ta = z ? Ta1 : Ta0;
    const __half* Tb = z ? Tb1 : Tb0;
    __half* U = z ? U1 : U0;

    const int bz = blockIdx.y, b = bz >> 3, h = bz & 7;
    const int n0 = blockIdx.x * 128;
    const int wrow = wid * 16;

    const size_t qbase = (size_t)(b * CN + n0) * C3D + CD + h * CHD;
    const size_t kbase = (size_t)b * CN * C3D + h * CHD;
    const size_t vbase = (size_t)b * CN * C3D + 2 * CD + h * CHD;

    auto load_q = [&]() {
        #pragma unroll
        for (int i = 0; i < 8; ++i) {
            const int idx = tid + i * 256;
            const int r = idx >> 4, c = (idx & 15) * 8;
            cp_async16(smb + (uint32_t)(r * QSTR + c) * 2,
                       Ta + qbase + (size_t)r * C3D + c);
        }
        cp_commit();
    };
    auto load_kv = [&](int mc, int buf) {
        const int m0 = mc * 64;
        const uint32_t base = smb + (uint32_t)(Q_HLV + buf * KV_STAGE) * 2;
        const __half* kp = Tb + kbase + (size_t)m0 * C3D;
        const __half* vp = Tb + vbase + (size_t)m0 * C3D;
        #pragma unroll
        for (int i = 0; i < 4; ++i) {
            const int idx = tid + i * 256;
            const int r = idx >> 4, c = (idx & 15) * 8;
            const uint32_t doff = (uint32_t)(r * KSTR + c) * 2;
            cp_async16(base + doff,               kp + (size_t)r * C3D + c);
            cp_async16(base + KV_TILE * 2 + doff, vp + (size_t)r * C3D + c);
        }
        cp_commit();
    };

    load_q();
    load_kv(0, 0);
    cp_wait<0>();
    __syncthreads();

    const int arow = lane & 15, acol = (lane >> 4) * 8;
    const uint32_t q_addr0 = smb + (uint32_t)((wrow + arow) * QSTR + acol) * 2;

    const int g = lane >> 2, tq = lane & 3;
    const int bq_row = (lane & 7) + ((lane >> 4) & 1) * 8;
    const int bq_col = ((lane >> 3) & 1) * 8;
    const int vq_row = lane & 15;
    const int vq_col = ((lane >> 4) & 1) * 8;

    float m0s = -1e30f, m1s = -1e30f, l0s = 0.f, l1s = 0.f;
    float o[16][4] = {};

    for (int mc = 0; mc < 8; ++mc) {
        const int buf = mc & 1;
        if (mc + 1 < 8) { load_kv(mc + 1, buf ^ 1); cp_wait<1>(); }
        else            { cp_wait<0>(); }
        __syncthreads();

        const uint32_t base = smb + (uint32_t)(Q_HLV + buf * KV_STAGE) * 2;

        // ---- S = Q K^T; Q frags reloaded from smem per k-frag ----
        float s[8][4] = {};
        #pragma unroll
        for (int kf = 0; kf < 8; ++kf) {
            uint32_t qf[4];
            ldm_x4(qf, q_addr0 + (uint32_t)(kf * 16) * 2);
            #pragma unroll
            for (int p = 0; p < 4; ++p) {
                const uint32_t boff =
                    (uint32_t)((p * 16 + bq_row) * KSTR + kf * 16 + bq_col) * 2;
                uint32_t kk4[4];
                ldm_x4(kk4, base + boff);
                mma_f16(s[2 * p],     qf, &kk4[0]);
                mma_f16(s[2 * p + 1], qf, &kk4[2]);
            }
        }

        // ---- online softmax ----
        float mx0 = -1e30f, mx1 = -1e30f;
        #pragma unroll
        for (int nf = 0; nf < 8; ++nf) {
            mx0 = fmaxf(mx0, fmaxf(s[nf][0], s[nf][1]));
            mx1 = fmaxf(mx1, fmaxf(s[nf][2], s[nf][3]));
        }
        mx0 = fmaxf(mx0, __shfl_xor_sync(0xffffffffu, mx0, 1));
        mx0 = fmaxf(mx0, __shfl_xor_sync(0xffffffffu, mx0, 2));
        mx1 = fmaxf(mx1, __shfl_xor_sync(0xffffffffu, mx1, 1));
        mx1 = fmaxf(mx1, __shfl_xor_sync(0xffffffffu, mx1, 2));
        mx0 *= scale; mx1 *= scale;
        const float mn0 = fmaxf(m0s, mx0), mn1 = fmaxf(m1s, mx1);
        const float a0 = __expf(m0s - mn0), a1 = __expf(m1s - mn1);
        m0s = mn0; m1s = mn1;

        float rs0 = 0.f, rs1 = 0.f;
        __half2 pf[8][2];
        #pragma unroll
        for (int nf = 0; nf < 8; ++nf) {
            const float p0 = __expf(s[nf][0] * scale - mn0);
            const float p1 = __expf(s[nf][1] * scale - mn0);
            const float p2 = __expf(s[nf][2] * scale - mn1);
            const float p3 = __expf(s[nf][3] * scale - mn1);
            rs0 += p0 + p1; rs1 += p2 + p3;
            pf[nf][0] = __halves2half2(__float2half_rn(p0), __float2half_rn(p1));
            pf[nf][1] = __halves2half2(__float2half_rn(p2), __float2half_rn(p3));
        }
        rs0 += __shfl_xor_sync(0xffffffffu, rs0, 1);
        rs0 += __shfl_xor_sync(0xffffffffu, rs0, 2);
        rs1 += __shfl_xor_sync(0xffffffffu, rs1, 1);
        rs1 += __shfl_xor_sync(0xffffffffu, rs1, 2);
        l0s = l0s * a0 + rs0;
        l1s = l1s * a1 + rs1;

        #pragma unroll
        for (int nf2 = 0; nf2 < 16; ++nf2) {
            o[nf2][0] *= a0; o[nf2][1] *= a0;
            o[nf2][2] *= a1; o[nf2][3] *= a1;
        }

        // ---- O += P V ----
        #pragma unroll
        for (int kf2 = 0; kf2 < 4; ++kf2) {
            uint32_t pa[4];
            pa[0] = *reinterpret_cast<uint32_t*>(&pf[2 * kf2][0]);
            pa[1] = *reinterpret_cast<uint32_t*>(&pf[2 * kf2][1]);
            pa[2] = *reinterpret_cast<uint32_t*>(&pf[2 * kf2 + 1][0]);
            pa[3] = *reinterpret_cast<uint32_t*>(&pf[2 * kf2 + 1][1]);
            #pragma unroll
            for (int p = 0; p < 8; ++p) {
                const uint32_t boff =
                    (uint32_t)((kf2 * 16 + vq_row) * KSTR + p * 16 + vq_col) * 2;
                uint32_t vv4[4];
                ldm_x4_trans(vv4, base + KV_TILE * 2 + boff);
                mma_f16(o[2 * p],     pa, &vv4[0]);
                mma_f16(o[2 * p + 1], pa, &vv4[2]);
            }
        }
        __syncthreads();
    }

    const float inv0 = 1.f / l0s, inv1 = 1.f / l1s;
    const int row0 = n0 + wrow + g;
    #pragma unroll
    for (int nf2 = 0; nf2 < 16; ++nf2) {
        const int col = h * CHD + nf2 * 8 + tq * 2;
        const size_t off0 = (size_t)(b * CN + row0) * CD + col;
        const size_t off1 = (size_t)(b * CN + row0 + 8) * CD + col;
        *reinterpret_cast<__half2*>(&U[off0]) =
            __halves2half2(__float2half_rn(o[nf2][0] * inv0), __float2half_rn(o[nf2][1] * inv0));
        *reinterpret_cast<__half2*>(&U[off1]) =
            __halves2half2(__float2half_rn(o[nf2][2] * inv1), __float2half_rn(o[nf2][3] * inv1));
    }
}

// =============================================================================
// precompute kernels
// =============================================================================
__global__ __launch_bounds__(256)
void to_half2(const float* __restrict__ x0, __half* __restrict__ h0,
              const float* __restrict__ x1, __half* __restrict__ h1, size_t n)
{
    const float* x = blockIdx.z ? x1 : x0;
    __half* hh = blockIdx.z ? h1 : h0;
    const size_t stride = (size_t)gridDim.x * blockDim.x * 4;
    for (size_t i = ((size_t)blockIdx.x * blockDim.x + threadIdx.x) * 4; i < n; i += stride) {
        float4 v = *reinterpret_cast<const float4*>(x + i);
        *reinterpret_cast<__half2*>(hh + i) =
            __halves2half2(__float2half_rn(v.x), __float2half_rn(v.y));
        *reinterpret_cast<__half2*>(hh + i + 2) =
            __halves2half2(__float2half_rn(v.z), __float2half_rn(v.w));
    }
}

__global__ __launch_bounds__(256)
void transpose_all(const float* __restrict__ Wv, const float* __restrict__ Wq,
                   const float* __restrict__ Wvo, const float* __restrict__ Wqo,
                   __half* __restrict__ Tv, __half* __restrict__ Tq,
                   __half* __restrict__ Tvo, __half* __restrict__ Tqo)
{
    const int bid = blockIdx.x;
    const float* W; __half* T; int K, N, local;
    if (bid < 3072)      { W = Wv;  T = Tv;  K = 1024; N = 3072; local = bid; }
    else if (bid < 6144) { W = Wq;  T = Tq;  K = 1024; N = 3072; local = bid - 3072; }
    else if (bid < 8192) { W = Wvo; T = Tvo; K = 2048; N = 1024; local = bid - 6144; }
    else                 { W = Wqo; T = Tqo; K = 2048; N = 1024; local = bid - 8192; }
    const int ntiles = N / 32;
    const int k0 = (local / ntiles) * 32, n0 = (local % ntiles) * 32;

    __shared__ float t[32][33];
    const int tx = threadIdx.x & 31, ty = threadIdx.x >> 5;
    for (int i = ty; i < 32; i += 8)
        t[i][tx] = W[(size_t)(k0 + i) * N + n0 + tx];
    __syncthreads();
    for (int i = ty; i < 32; i += 8)
        T[(size_t)(n0 + i) * K + k0 + tx] = __float2half_rn(t[tx][i]);
}

// =============================================================================
// launch
// =============================================================================
extern "C" void kernel_launch(void* const* d_in, const int* in_sizes, int n_in,
                              void* d_out, int out_size)
{
    const float* v   = (const float*)d_in[0];
    const float* q   = (const float*)d_in[1];
    const float* Wv  = (const float*)d_in[2];
    const float* bv  = (const float*)d_in[3];
    const float* Wq  = (const float*)d_in[4];
    const float* bq  = (const float*)d_in[5];
    const float* Wvo = (const float*)d_in[6];
    const float* bvo = (const float*)d_in[7];
    const float* Wqo = (const float*)d_in[8];
    const float* bqo = (const float*)d_in[9];
    float* out = (float*)d_out;

    __half *vt, *qt, *vh, *qh, *vu, *qu, *Wvt, *Wqt, *Wvot, *Wqot;
    cudaGetSymbolAddress((void**)&vt, g_vt);   cudaGetSymbolAddress((void**)&qt, g_qt);
    cudaGetSymbolAddress((void**)&vh, g_vh);   cudaGetSymbolAddress((void**)&qh, g_qh);
    cudaGetSymbolAddress((void**)&vu, g_vu);   cudaGetSymbolAddress((void**)&qu, g_qu);
    cudaGetSymbolAddress((void**)&Wvt, g_Wvt); cudaGetSymbolAddress((void**)&Wqt, g_Wqt);
    cudaGetSymbolAddress((void**)&Wvot, g_Wvot); cudaGetSymbolAddress((void**)&Wqot, g_Wqot);

    cudaFuncSetAttribute(gemm_in,  cudaFuncAttributeMaxDynamicSharedMemorySize, GEMM_SMEM);
    cudaFuncSetAttribute(gemm_out, cudaFuncAttributeMaxDynamicSharedMemorySize, GEMM_SMEM);
    cudaFuncSetAttribute(fused_attn, cudaFuncAttributeMaxDynamicSharedMemorySize, ATT_SMEM);

    const dim3 t256(256);
    const float scale = 0.08838834764831845f;   // 1/sqrt(128)
    const size_t nVD = (size_t)CM * CD;
    const size_t half = (size_t)CM * CD;

    // prep
    to_half2<<<dim3(1024, 1, 2), t256>>>(v, vh, q, qh, nVD);
    transpose_all<<<10240, t256>>>(Wv, Wq, Wvo, Wqo, Wvt, Wqt, Wvot, Wqot);

    // input transforms (both modalities)
    gemm_in<<<dim3(C3D / 128, CM / 128, 2), t256, GEMM_SMEM>>>(
        vh, qh, Wvt, Wqt, bv, bq, vt, qt, CM, C3D, CD);

    // fused attention, both directions
    fused_attn<<<dim3(CN / 128, CB * CH, 2), t256, ATT_SMEM>>>(
        vt, qt, vu, qt, vt, qu, scale);

    // output transforms (virtual concat), both modalities
    gemm_out<<<dim3(CD / 128, CM / 128, 2), t256, GEMM_SMEM>>>(
        vh, vu, qh, qu, CD, Wvot, Wqot, bvo, bqo, out, half, CM, CD, 2 * CD);
}